// round 10
// baseline (speedup 1.0000x reference)
#include <cuda_runtime.h>
#include <cuda_bf16.h>
#include <cstdint>
#include <cstddef>
#include <math.h>

// Problem constants
constexpr int B_  = 2;
constexpr int T_  = 2048;
constexpr int HID = 2048;
constexpr int NH  = 16;
constexpr int NKV = 4;
constexpr int HD  = 128;

// ---------------- scratch (static device arrays; no allocation) ----------------
__device__ float        g_Octx[(size_t)B_ * T_ * NH * HD];
__device__ __nv_bfloat16 g_Qh[(size_t)B_ * NH  * T_ * HD];
__device__ __nv_bfloat16 g_Ql[(size_t)B_ * NH  * T_ * HD];
__device__ __nv_bfloat16 g_Kh[(size_t)B_ * NKV * T_ * HD];
__device__ __nv_bfloat16 g_Kl[(size_t)B_ * NKV * T_ * HD];
__device__ __nv_bfloat16 g_Vh[(size_t)B_ * NKV * T_ * HD];
__device__ __nv_bfloat16 g_Vl[(size_t)B_ * NKV * T_ * HD];

// ---------------- PTX helpers ----------------
__device__ __forceinline__ uint32_t smem_u32(const void* p) {
    return (uint32_t)__cvta_generic_to_shared(p);
}
__device__ __forceinline__ void ldsm4(uint32_t r[4], const void* p) {
    uint32_t a = smem_u32(p);
    asm volatile("ldmatrix.sync.aligned.m8n8.x4.shared.b16 {%0,%1,%2,%3}, [%4];"
                 : "=r"(r[0]), "=r"(r[1]), "=r"(r[2]), "=r"(r[3]) : "r"(a));
}
__device__ __forceinline__ void ldsm4t(uint32_t r[4], const void* p) {
    uint32_t a = smem_u32(p);
    asm volatile("ldmatrix.sync.aligned.m8n8.x4.trans.shared.b16 {%0,%1,%2,%3}, [%4];"
                 : "=r"(r[0]), "=r"(r[1]), "=r"(r[2]), "=r"(r[3]) : "r"(a));
}
__device__ __forceinline__ void mma_bf16(float c[4], const uint32_t a[4], uint32_t b0, uint32_t b1) {
    asm volatile("mma.sync.aligned.m16n8k16.row.col.f32.bf16.bf16.f32 "
                 "{%0,%1,%2,%3}, {%4,%5,%6,%7}, {%8,%9}, {%0,%1,%2,%3};"
                 : "+f"(c[0]), "+f"(c[1]), "+f"(c[2]), "+f"(c[3])
                 : "r"(a[0]), "r"(a[1]), "r"(a[2]), "r"(a[3]), "r"(b0), "r"(b1));
}
__device__ __forceinline__ void cpasync16(uint32_t saddr, const void* g) {
    asm volatile("cp.async.cg.shared.global [%0], [%1], 16;" :: "r"(saddr), "l"(g));
}
__device__ __forceinline__ void cpcommit() { asm volatile("cp.async.commit_group;"); }
template <int N> __device__ __forceinline__ void cpwait() {
    asm volatile("cp.async.wait_group %0;" :: "n"(N));
}
__device__ __forceinline__ void split2(float a, float b, uint32_t& hv, uint32_t& lv) {
    __nv_bfloat162 h = __floats2bfloat162_rn(a, b);
    float2 f = __bfloat1622float2(h);
    __nv_bfloat162 l = __floats2bfloat162_rn(a - f.x, b - f.y);
    hv = *reinterpret_cast<uint32_t*>(&h);
    lv = *reinterpret_cast<uint32_t*>(&l);
}
__device__ __forceinline__ void split_store4(float4 v, __nv_bfloat16* hi, __nv_bfloat16* lo) {
    uint32_t h0, l0, h1, l1;
    split2(v.x, v.y, h0, l0);
    split2(v.z, v.w, h1, l1);
    *reinterpret_cast<uint2*>(hi) = make_uint2(h0, h1);
    *reinterpret_cast<uint2*>(lo) = make_uint2(l0, l1);
}

// =====================================================================
// shared GEMM tile constants: CTA 128x256x32, 512 thr (16 warps 4x4),
// warp tile 32x64, two smem stages, one barrier per k-tile.
// =====================================================================
constexpr int SA_ST = 40;    // sA row stride (32+8 halves)
constexpr int SB_ST = 264;   // sB row stride (256+8 halves)
constexpr int SA_SZ = 128 * SA_ST;
constexpr int SB_SZ = 32 * SB_ST;
constexpr int ST_SZ = 2 * SA_SZ + 2 * SB_SZ;               // halves per stage
constexpr int GEMM_SMEM_BYTES = 2 * ST_SZ * 2;             // 108544 B

// mainloop body shared by both GEMM kernels (macro-free: duplicated inline)
// acc layout: acc[mf][nf][4]; rows wm+mf*16+(lane>>2)(+8), col wn+nf*8+(lane&3)*2

// =====================================================================
// Fused QKV projection + RoPE + scale + bf16 hi/lo split + relayout.
// One launch, 384 tiles: t<256 -> Q (32x8), t<320 -> K (32x2), else V (32x2).
// Epilogue routes C through smem (two 64-row passes) for (d,d+64) rope
// pairing, then writes split bf16 directly to [B,H,T,D] buffers.
// =====================================================================
__global__ __launch_bounds__(512, 1) void gemm_qkv_rope(
    const float* __restrict__ A,
    const float* __restrict__ wq, const float* __restrict__ wk, const float* __restrict__ wv,
    const float* __restrict__ cosb, const float* __restrict__ sinb,
    __nv_bfloat16* __restrict__ Qh, __nv_bfloat16* __restrict__ Ql,
    __nv_bfloat16* __restrict__ Kh, __nv_bfloat16* __restrict__ Kl,
    __nv_bfloat16* __restrict__ Vh, __nv_bfloat16* __restrict__ Vl,
    float qsc)
{
    extern __shared__ __nv_bfloat16 gs[];

    const int tile = blockIdx.x;
    int which, bm, bn;
    if (tile < 256)      { which = 0; bm = tile >> 3;         bn = tile & 7; }
    else if (tile < 320) { which = 1; bm = (tile - 256) >> 1; bn = (tile - 256) & 1; }
    else                 { which = 2; bm = (tile - 320) >> 1; bn = (tile - 320) & 1; }
    const float* Bm = (which == 0) ? wq : (which == 1) ? wk : wv;
    const int N = (which == 0) ? (NH * HD) : (NKV * HD);
    const int K = HID;

    const int tid  = threadIdx.x;
    const int lane = tid & 31;
    const int wid  = tid >> 5;                 // 0..15
    const int wm   = (wid >> 2) * 32;
    const int wn   = (wid & 3) * 64;

    const float* Ab = A + (size_t)bm * 128 * K;
    const float* Bb = Bm + (size_t)bn * 256;

    float acc[2][8][4] = {};
    float4 ra[2], rb[4];

    auto gload = [&](int k0) {
#pragma unroll
        for (int i = 0; i < 2; i++) {
            int idx = i * 512 + tid;
            int r = idx >> 3, c4 = idx & 7;
            ra[i] = *(const float4*)(Ab + (size_t)r * K + k0 + c4 * 4);
        }
#pragma unroll
        for (int i = 0; i < 4; i++) {
            int idx = i * 512 + tid;
            int r = idx >> 6, c4 = idx & 63;
            rb[i] = *(const float4*)(Bb + (size_t)(k0 + r) * N + c4 * 4);
        }
    };
    auto sstore = [&](int s) {
        __nv_bfloat16* sA0 = gs + s * ST_SZ;
        __nv_bfloat16* sA1 = sA0 + SA_SZ;
        __nv_bfloat16* sB0 = sA0 + 2 * SA_SZ;
        __nv_bfloat16* sB1 = sB0 + SB_SZ;
#pragma unroll
        for (int i = 0; i < 2; i++) {
            int idx = i * 512 + tid;
            int r = idx >> 3, c = (idx & 7) * 4;
            split_store4(ra[i], sA0 + r * SA_ST + c, sA1 + r * SA_ST + c);
        }
#pragma unroll
        for (int i = 0; i < 4; i++) {
            int idx = i * 512 + tid;
            int r = idx >> 6, c = (idx & 63) * 4;
            split_store4(rb[i], sB0 + r * SB_ST + c, sB1 + r * SB_ST + c);
        }
    };

    gload(0);
    sstore(0);
    __syncthreads();

    const int nk = K / 32;
    for (int kt = 0; kt < nk; kt++) {
        const int s = kt & 1;
        if (kt + 1 < nk) gload((kt + 1) * 32);

        const __nv_bfloat16* sA0 = gs + s * ST_SZ;
        const __nv_bfloat16* sA1 = sA0 + SA_SZ;
        const __nv_bfloat16* sB0 = sA0 + 2 * SA_SZ;
        const __nv_bfloat16* sB1 = sB0 + SB_SZ;

#pragma unroll
        for (int ks = 0; ks < 2; ks++) {
            const int colA = ks * 16 + ((lane >> 4) << 3);
            uint32_t af0[2][4], af1[2][4];
#pragma unroll
            for (int mf = 0; mf < 2; mf++) {
                int row = wm + mf * 16 + (lane & 15);
                ldsm4(af0[mf], sA0 + row * SA_ST + colA);
                ldsm4(af1[mf], sA1 + row * SA_ST + colA);
            }
            const int rowB = ks * 16 + (lane & 15);
#pragma unroll
            for (int nf2 = 0; nf2 < 4; nf2++) {
                const int colB = wn + nf2 * 16 + ((lane >> 4) << 3);
                uint32_t bh[4], bl[4];
                ldsm4t(bh, sB0 + rowB * SB_ST + colB);
                ldsm4t(bl, sB1 + rowB * SB_ST + colB);
#pragma unroll
                for (int mf = 0; mf < 2; mf++)
#pragma unroll
                    for (int sub = 0; sub < 2; sub++)
                        mma_bf16(acc[mf][nf2 * 2 + sub], af0[mf], bh[sub * 2], bh[sub * 2 + 1]);
#pragma unroll
                for (int mf = 0; mf < 2; mf++)
#pragma unroll
                    for (int sub = 0; sub < 2; sub++)
                        mma_bf16(acc[mf][nf2 * 2 + sub], af0[mf], bl[sub * 2], bl[sub * 2 + 1]);
#pragma unroll
                for (int mf = 0; mf < 2; mf++)
#pragma unroll
                    for (int sub = 0; sub < 2; sub++)
                        mma_bf16(acc[mf][nf2 * 2 + sub], af1[mf], bh[sub * 2], bh[sub * 2 + 1]);
            }
        }
        if (kt + 1 < nk) sstore(s ^ 1);
        __syncthreads();
    }

    // ---- fused rope + split epilogue (smem exchange, two 64-row passes) ----
    {
        float* sf = reinterpret_cast<float*>(gs);        // 64 x 264 f32 = 67.6 KB
        const int H = (which == 0) ? NH : NKV;
        const float scale = (which == 0) ? qsc : 1.0f;
        const int do_rope = (which != 2);
        __nv_bfloat16* dh = (which == 0) ? Qh : (which == 1) ? Kh : Vh;
        __nv_bfloat16* dl = (which == 0) ? Ql : (which == 1) ? Kl : Vl;

#pragma unroll
        for (int mf = 0; mf < 2; mf++) {
            int rl0 = (wm >> 5) * 16 + (lane >> 2);
#pragma unroll
            for (int nf = 0; nf < 8; nf++) {
                int col = wn + nf * 8 + (lane & 3) * 2;
                *(float2*)(sf + rl0 * 264 + col)       = make_float2(acc[mf][nf][0], acc[mf][nf][1]);
                *(float2*)(sf + (rl0 + 8) * 264 + col) = make_float2(acc[mf][nf][2], acc[mf][nf][3]);
            }
            __syncthreads();
#pragma unroll
            for (int k = 0; k < 16; k++) {
                int e2 = k * 512 + tid;                  // 8192 float2 = 64x256 elems
                int rl = e2 >> 7;
                int c2 = (e2 & 127) * 2;
                int r  = bm * 128 + (rl >> 4) * 32 + mf * 16 + (rl & 15);
                int t  = r & (T_ - 1);
                int b  = r >> 11;
                int gc = bn * 256 + c2;
                int h  = gc >> 7;
                int d  = gc & 127;
                float2 v = *(float2*)(sf + rl * 264 + c2);
                float o0, o1;
                if (do_rope) {
                    int dd = d & 63;
                    float2 cs = *(const float2*)(cosb + t * 64 + dd);
                    float2 sn = *(const float2*)(sinb + t * 64 + dd);
                    float2 w  = *(float2*)(sf + rl * 264 + (c2 ^ 64));
                    if (d < 64) { o0 = v.x * cs.x - w.x * sn.x; o1 = v.y * cs.y - w.y * sn.y; }
                    else        { o0 = v.x * cs.x + w.x * sn.x; o1 = v.y * cs.y + w.y * sn.y; }
                } else { o0 = v.x; o1 = v.y; }
                o0 *= scale; o1 *= scale;
                uint32_t hv, lv;
                split2(o0, o1, hv, lv);
                size_t di = (((size_t)(b * H + h)) * T_ + t) * HD + d;
                *(uint32_t*)(dh + di) = hv;
                *(uint32_t*)(dl + di) = lv;
            }
            __syncthreads();
        }
    }
}

// =====================================================================
// Output-projection GEMM (fp32 in/out), same tile machinery.
// =====================================================================
__global__ __launch_bounds__(512, 1) void gemm_bf16x3(
    const float* __restrict__ A, const float* __restrict__ Bm, float* __restrict__ C,
    int M, int N, int K)
{
    extern __shared__ __nv_bfloat16 gs[];

    const int tid  = threadIdx.x;
    const int lane = tid & 31;
    const int wid  = tid >> 5;
    const int bm   = blockIdx.y, bn = blockIdx.x;
    const int wm   = (wid >> 2) * 32;
    const int wn   = (wid & 3) * 64;

    const float* Ab = A + (size_t)bm * 128 * K;
    const float* Bb = Bm + (size_t)bn * 256;

    float acc[2][8][4] = {};
    float4 ra[2], rb[4];

    auto gload = [&](int k0) {
#pragma unroll
        for (int i = 0; i < 2; i++) {
            int idx = i * 512 + tid;
            int r = idx >> 3, c4 = idx & 7;
            ra[i] = *(const float4*)(Ab + (size_t)r * K + k0 + c4 * 4);
        }
#pragma unroll
        for (int i = 0; i < 4; i++) {
            int idx = i * 512 + tid;
            int r = idx >> 6, c4 = idx & 63;
            rb[i] = *(const float4*)(Bb + (size_t)(k0 + r) * N + c4 * 4);
        }
    };
    auto sstore = [&](int s) {
        __nv_bfloat16* sA0 = gs + s * ST_SZ;
        __nv_bfloat16* sA1 = sA0 + SA_SZ;
        __nv_bfloat16* sB0 = sA0 + 2 * SA_SZ;
        __nv_bfloat16* sB1 = sB0 + SB_SZ;
#pragma unroll
        for (int i = 0; i < 2; i++) {
            int idx = i * 512 + tid;
            int r = idx >> 3, c = (idx & 7) * 4;
            split_store4(ra[i], sA0 + r * SA_ST + c, sA1 + r * SA_ST + c);
        }
#pragma unroll
        for (int i = 0; i < 4; i++) {
            int idx = i * 512 + tid;
            int r = idx >> 6, c = (idx & 63) * 4;
            split_store4(rb[i], sB0 + r * SB_ST + c, sB1 + r * SB_ST + c);
        }
    };

    gload(0);
    sstore(0);
    __syncthreads();

    const int nk = K / 32;
    for (int kt = 0; kt < nk; kt++) {
        const int s = kt & 1;
        if (kt + 1 < nk) gload((kt + 1) * 32);

        const __nv_bfloat16* sA0 = gs + s * ST_SZ;
        const __nv_bfloat16* sA1 = sA0 + SA_SZ;
        const __nv_bfloat16* sB0 = sA0 + 2 * SA_SZ;
        const __nv_bfloat16* sB1 = sB0 + SB_SZ;

#pragma unroll
        for (int ks = 0; ks < 2; ks++) {
            const int colA = ks * 16 + ((lane >> 4) << 3);
            uint32_t af0[2][4], af1[2][4];
#pragma unroll
            for (int mf = 0; mf < 2; mf++) {
                int row = wm + mf * 16 + (lane & 15);
                ldsm4(af0[mf], sA0 + row * SA_ST + colA);
                ldsm4(af1[mf], sA1 + row * SA_ST + colA);
            }
            const int rowB = ks * 16 + (lane & 15);
#pragma unroll
            for (int nf2 = 0; nf2 < 4; nf2++) {
                const int colB = wn + nf2 * 16 + ((lane >> 4) << 3);
                uint32_t bh[4], bl[4];
                ldsm4t(bh, sB0 + rowB * SB_ST + colB);
                ldsm4t(bl, sB1 + rowB * SB_ST + colB);
#pragma unroll
                for (int mf = 0; mf < 2; mf++)
#pragma unroll
                    for (int sub = 0; sub < 2; sub++)
                        mma_bf16(acc[mf][nf2 * 2 + sub], af0[mf], bh[sub * 2], bh[sub * 2 + 1]);
#pragma unroll
                for (int mf = 0; mf < 2; mf++)
#pragma unroll
                    for (int sub = 0; sub < 2; sub++)
                        mma_bf16(acc[mf][nf2 * 2 + sub], af0[mf], bl[sub * 2], bl[sub * 2 + 1]);
#pragma unroll
                for (int mf = 0; mf < 2; mf++)
#pragma unroll
                    for (int sub = 0; sub < 2; sub++)
                        mma_bf16(acc[mf][nf2 * 2 + sub], af1[mf], bh[sub * 2], bh[sub * 2 + 1]);
            }
        }
        if (kt + 1 < nk) sstore(s ^ 1);
        __syncthreads();
    }

#pragma unroll
    for (int mf = 0; mf < 2; mf++) {
        int r0 = bm * 128 + wm + mf * 16 + (lane >> 2);
#pragma unroll
        for (int nf = 0; nf < 8; nf++) {
            int c = bn * 256 + wn + nf * 8 + (lane & 3) * 2;
            *(float2*)(C + (size_t)r0 * N + c)       = make_float2(acc[mf][nf][0], acc[mf][nf][1]);
            *(float2*)(C + (size_t)(r0 + 8) * N + c) = make_float2(acc[mf][nf][2], acc[mf][nf][3]);
        }
    }
}

// =====================================================================
// Flash attention (causal, GQA). Br=64 (4 warps x 16 rows), Bc=64,
// single KV buffer, 2 CTAs per SM. (unchanged from R9)
// =====================================================================
constexpr int AS       = 136;
constexpr int Q_H_OFF  = 0;
constexpr int Q_L_OFF  = 64 * AS;
constexpr int KV_OFF   = 2 * 64 * AS;
constexpr int ATTN_SMEM_BYTES = (2 * 64 * AS + 4 * 64 * AS) * 2;   // 104448

__global__ __launch_bounds__(128, 2) void attn_kernel(
    const __nv_bfloat16* __restrict__ Qh, const __nv_bfloat16* __restrict__ Ql,
    const __nv_bfloat16* __restrict__ Kh, const __nv_bfloat16* __restrict__ Kl,
    const __nv_bfloat16* __restrict__ Vh, const __nv_bfloat16* __restrict__ Vl,
    float* __restrict__ O)
{
    extern __shared__ __nv_bfloat16 sm[];
    const int tid  = threadIdx.x;
    const int lane = tid & 31;
    const int wid  = tid >> 5;
    const int bh   = blockIdx.y;
    const int b    = bh >> 4, h = bh & 15;
    const int qi   = (int)gridDim.x - 1 - (int)blockIdx.x;
    const int qbase = qi * 64;
    const int kvi  = b * NKV + (h >> 2);

    const __nv_bfloat16* qh_g = Qh + ((size_t)bh * T_ + qbase) * HD;
    const __nv_bfloat16* ql_g = Ql + ((size_t)bh * T_ + qbase) * HD;
    const __nv_bfloat16* ks_g[4] = {
        Kh + (size_t)kvi * T_ * HD, Kl + (size_t)kvi * T_ * HD,
        Vh + (size_t)kvi * T_ * HD, Vl + (size_t)kvi * T_ * HD
    };

#pragma unroll
    for (int i = 0; i < 16; i++) {
        int c = i * 128 + tid;
        int split = c >> 10, cc = c & 1023;
        int row = cc >> 4, ch = cc & 15;
        const __nv_bfloat16* src = (split ? ql_g : qh_g) + row * HD + ch * 8;
        cpasync16(smem_u32(sm + (split ? Q_L_OFF : Q_H_OFF) + row * AS + ch * 8), src);
    }
    cpcommit();

    auto loadKV = [&](int j) {
        size_t gb = (size_t)j * 64 * HD;
#pragma unroll
        for (int i = 0; i < 32; i++) {
            int c = i * 128 + tid;
            int which = c >> 10, cc = c & 1023;
            int row = cc >> 4, ch = cc & 15;
            cpasync16(smem_u32(sm + KV_OFF + which * (64 * AS) + row * AS + ch * 8),
                      ks_g[which] + gb + row * HD + ch * 8);
        }
        cpcommit();
    };

    float m0 = -1e30f, m1 = -1e30f, l0 = 0.f, l1 = 0.f;
    float o[16][4];
#pragma unroll
    for (int i = 0; i < 16; i++)
#pragma unroll
        for (int j = 0; j < 4; j++) o[i][j] = 0.f;

    const int nj = qi + 1;
    const int rowbase = qbase + wid * 16;

    for (int j = 0; j < nj; j++) {
        loadKV(j);
        cpwait<0>();
        __syncthreads();

        float sacc[8][4];
#pragma unroll
        for (int i = 0; i < 8; i++)
#pragma unroll
            for (int jj = 0; jj < 4; jj++) sacc[i][jj] = 0.f;

#pragma unroll
        for (int ks = 0; ks < 8; ks++) {
            uint32_t qa[2][4];
            {
                int row = wid * 16 + (lane & 15);
                int col = ks * 16 + ((lane >> 4) << 3);
                ldsm4(qa[0], sm + Q_H_OFF + row * AS + col);
                ldsm4(qa[1], sm + Q_L_OFF + row * AS + col);
            }
#pragma unroll
            for (int nf2 = 0; nf2 < 4; nf2++) {
                uint32_t kh4[4], kl4[4];
                int krow = nf2 * 16 + (lane & 15);
                int kcol = ks * 16 + ((lane >> 4) << 3);
                ldsm4(kh4, sm + KV_OFF + krow * AS + kcol);
                ldsm4(kl4, sm + KV_OFF + 64 * AS + krow * AS + kcol);
                mma_bf16(sacc[2 * nf2],     qa[0], kh4[0], kh4[2]);
                mma_bf16(sacc[2 * nf2 + 1], qa[0], kh4[1], kh4[3]);
                mma_bf16(sacc[2 * nf2],     qa[0], kl4[0], kl4[2]);
                mma_bf16(sacc[2 * nf2 + 1], qa[0], kl4[1], kl4[3]);
                mma_bf16(sacc[2 * nf2],     qa[1], kh4[0], kh4[2]);
                mma_bf16(sacc[2 * nf2 + 1], qa[1], kh4[1], kh4[3]);
            }
        }

        const int kvb = j * 64;
        if (kvb + 63 > rowbase) {
            int r0 = rowbase + (lane >> 2), r1 = r0 + 8;
#pragma unroll
            for (int nf = 0; nf < 8; nf++) {
                int c0 = kvb + nf * 8 + (lane & 3) * 2;
                if (c0 > r0)     sacc[nf][0] = -1e30f;
                if (c0 + 1 > r0) sacc[nf][1] = -1e30f;
                if (c0 > r1)     sacc[nf][2] = -1e30f;
                if (c0 + 1 > r1) sacc[nf][3] = -1e30f;
            }
        }

        float rm0 = -1e30f, rm1 = -1e30f;
#pragma unroll
        for (int nf = 0; nf < 8; nf++) {
            rm0 = fmaxf(rm0, fmaxf(sacc[nf][0], sacc[nf][1]));
            rm1 = fmaxf(rm1, fmaxf(sacc[nf][2], sacc[nf][3]));
        }
        rm0 = fmaxf(rm0, __shfl_xor_sync(0xffffffffu, rm0, 1));
        rm0 = fmaxf(rm0, __shfl_xor_sync(0xffffffffu, rm0, 2));
        rm1 = fmaxf(rm1, __shfl_xor_sync(0xffffffffu, rm1, 1));
        rm1 = fmaxf(rm1, __shfl_xor_sync(0xffffffffu, rm1, 2));
        float mn0 = fmaxf(m0, rm0), mn1 = fmaxf(m1, rm1);
        float corr0 = exp2f(m0 - mn0), corr1 = exp2f(m1 - mn1);
        m0 = mn0; m1 = mn1;

        float rs0 = 0.f, rs1 = 0.f;
#pragma unroll
        for (int nf = 0; nf < 8; nf++) {
            float p0 = exp2f(sacc[nf][0] - mn0);
            float p1 = exp2f(sacc[nf][1] - mn0);
            float p2 = exp2f(sacc[nf][2] - mn1);
            float p3 = exp2f(sacc[nf][3] - mn1);
            sacc[nf][0] = p0; sacc[nf][1] = p1; sacc[nf][2] = p2; sacc[nf][3] = p3;
            rs0 += p0 + p1; rs1 += p2 + p3;
        }
        l0 = l0 * corr0 + rs0;
        l1 = l1 * corr1 + rs1;
        if (__any_sync(0xffffffffu, (corr0 != 1.f) || (corr1 != 1.f))) {
#pragma unroll
            for (int df = 0; df < 16; df++) {
                o[df][0] *= corr0; o[df][1] *= corr0;
                o[df][2] *= corr1; o[df][3] *= corr1;
            }
        }

        uint32_t ph[4][4], pl[4][4];
#pragma unroll
        for (int kk = 0; kk < 4; kk++) {
            const float* A0 = sacc[2 * kk];
            const float* A1 = sacc[2 * kk + 1];
            split2(A0[0], A0[1], ph[kk][0], pl[kk][0]);
            split2(A0[2], A0[3], ph[kk][1], pl[kk][1]);
            split2(A1[0], A1[1], ph[kk][2], pl[kk][2]);
            split2(A1[2], A1[3], ph[kk][3], pl[kk][3]);
        }

        const int vb = KV_OFF + 2 * 64 * AS;
#pragma unroll
        for (int kk = 0; kk < 4; kk++) {
#pragma unroll
            for (int nf2 = 0; nf2 < 8; nf2++) {
                uint32_t vh4[4], vl4[4];
                int vrow = kk * 16 + (lane & 15);
                int vcol = nf2 * 16 + ((lane >> 4) << 3);
                ldsm4t(vh4, sm + vb + vrow * AS + vcol);
                ldsm4t(vl4, sm + vb + 64 * AS + vrow * AS + vcol);
                mma_bf16(o[2 * nf2],     ph[kk], vh4[0], vh4[1]);
                mma_bf16(o[2 * nf2 + 1], ph[kk], vh4[2], vh4[3]);
                mma_bf16(o[2 * nf2],     ph[kk], vl4[0], vl4[1]);
                mma_bf16(o[2 * nf2 + 1], ph[kk], vl4[2], vl4[3]);
                mma_bf16(o[2 * nf2],     pl[kk], vh4[0], vh4[1]);
                mma_bf16(o[2 * nf2 + 1], pl[kk], vh4[2], vh4[3]);
            }
        }
        __syncthreads();
    }

    l0 += __shfl_xor_sync(0xffffffffu, l0, 1);
    l0 += __shfl_xor_sync(0xffffffffu, l0, 2);
    l1 += __shfl_xor_sync(0xffffffffu, l1, 1);
    l1 += __shfl_xor_sync(0xffffffffu, l1, 2);
    float inv0 = 1.f / l0, inv1 = 1.f / l1;

    int r0 = rowbase + (lane >> 2);
    size_t base0 = ((size_t)b * T_ + r0) * HID + h * HD + (lane & 3) * 2;
    size_t base1 = base0 + (size_t)8 * HID;
#pragma unroll
    for (int df = 0; df < 16; df++) {
        *(float2*)(O + base0 + df * 8) = make_float2(o[df][0] * inv0, o[df][1] * inv0);
        *(float2*)(O + base1 + df * 8) = make_float2(o[df][2] * inv1, o[df][3] * inv1);
    }
}

// =====================================================================
// host launcher
// =====================================================================
extern "C" void kernel_launch(void* const* d_in, const int* in_sizes, int n_in,
                              void* d_out, int out_size)
{
    const float* x    = (const float*)d_in[0];
    const float* cosb = (const float*)d_in[1];
    const float* sinb = (const float*)d_in[2];
    const float* wq   = (const float*)d_in[3];
    const float* wk   = (const float*)d_in[4];
    const float* wv   = (const float*)d_in[5];
    const float* wo   = (const float*)d_in[6];

    float* Octx;
    __nv_bfloat16 *Qh, *Ql, *Kh, *Kl, *Vh, *Vl;
    cudaGetSymbolAddress((void**)&Octx, g_Octx);
    cudaGetSymbolAddress((void**)&Qh, g_Qh);
    cudaGetSymbolAddress((void**)&Ql, g_Ql);
    cudaGetSymbolAddress((void**)&Kh, g_Kh);
    cudaGetSymbolAddress((void**)&Kl, g_Kl);
    cudaGetSymbolAddress((void**)&Vh, g_Vh);
    cudaGetSymbolAddress((void**)&Vl, g_Vl);

    cudaFuncSetAttribute(attn_kernel, cudaFuncAttributeMaxDynamicSharedMemorySize,
                         ATTN_SMEM_BYTES);
    cudaFuncSetAttribute(gemm_bf16x3, cudaFuncAttributeMaxDynamicSharedMemorySize,
                         GEMM_SMEM_BYTES);
    cudaFuncSetAttribute(gemm_qkv_rope, cudaFuncAttributeMaxDynamicSharedMemorySize,
                         GEMM_SMEM_BYTES);

    const int M = B_ * T_;  // 4096
    float qsc = (1.0f / sqrtf((float)HD)) * 1.4426950408889634f;

    // 0: fused QKV projection + rope + split (384 tiles, one launch)
    gemm_qkv_rope<<<384, 512, GEMM_SMEM_BYTES>>>(
        x, wq, wk, wv, cosb, sinb, Qh, Ql, Kh, Kl, Vh, Vl, qsc);
    // 1: attention
    attn_kernel<<<dim3(T_ / 64, B_ * NH), 128, ATTN_SMEM_BYTES>>>(
        Qh, Ql, Kh, Kl, Vh, Vl, Octx);
    // 2: output projection
    gemm_bf16x3<<<dim3(HID / 256, M / 128), 512, GEMM_SMEM_BYTES>>>(
        Octx, wo, (float*)d_out, M, HID, HID);
}

// round 11
// speedup vs baseline: 1.3825x; 1.3825x over previous
#include <cuda_runtime.h>
#include <cuda_fp16.h>
#include <cstdint>
#include <cstddef>
#include <math.h>

// Problem constants
constexpr int B_  = 2;
constexpr int T_  = 2048;
constexpr int HID = 2048;
constexpr int NH  = 16;
constexpr int NKV = 4;
constexpr int HD  = 128;

// ---------------- scratch (static device arrays; no allocation) ----------------
__device__ float   g_Octx[(size_t)B_ * T_ * NH * HD];
__device__ __half  g_Qh[(size_t)B_ * NH  * T_ * HD];
__device__ __half  g_Ql[(size_t)B_ * NH  * T_ * HD];
__device__ __half  g_Kh[(size_t)B_ * NKV * T_ * HD];
__device__ __half  g_Vh[(size_t)B_ * NKV * T_ * HD];

// ---------------- PTX helpers ----------------
__device__ __forceinline__ uint32_t smem_u32(const void* p) {
    return (uint32_t)__cvta_generic_to_shared(p);
}
__device__ __forceinline__ void ldsm4(uint32_t r[4], const void* p) {
    uint32_t a = smem_u32(p);
    asm volatile("ldmatrix.sync.aligned.m8n8.x4.shared.b16 {%0,%1,%2,%3}, [%4];"
                 : "=r"(r[0]), "=r"(r[1]), "=r"(r[2]), "=r"(r[3]) : "r"(a));
}
__device__ __forceinline__ void ldsm4t(uint32_t r[4], const void* p) {
    uint32_t a = smem_u32(p);
    asm volatile("ldmatrix.sync.aligned.m8n8.x4.trans.shared.b16 {%0,%1,%2,%3}, [%4];"
                 : "=r"(r[0]), "=r"(r[1]), "=r"(r[2]), "=r"(r[3]) : "r"(a));
}
__device__ __forceinline__ void mma_f16(float c[4], const uint32_t a[4], uint32_t b0, uint32_t b1) {
    asm volatile("mma.sync.aligned.m16n8k16.row.col.f32.f16.f16.f32 "
                 "{%0,%1,%2,%3}, {%4,%5,%6,%7}, {%8,%9}, {%0,%1,%2,%3};"
                 : "+f"(c[0]), "+f"(c[1]), "+f"(c[2]), "+f"(c[3])
                 : "r"(a[0]), "r"(a[1]), "r"(a[2]), "r"(a[3]), "r"(b0), "r"(b1));
}
__device__ __forceinline__ void cpasync16(uint32_t saddr, const void* g) {
    asm volatile("cp.async.cg.shared.global [%0], [%1], 16;" :: "r"(saddr), "l"(g));
}
__device__ __forceinline__ void cpcommit() { asm volatile("cp.async.commit_group;"); }
template <int N> __device__ __forceinline__ void cpwait() {
    asm volatile("cp.async.wait_group %0;" :: "n"(N));
}
// fp16 hi/lo split of a float pair
__device__ __forceinline__ void split2h(float a, float b, uint32_t& hv, uint32_t& lv) {
    __half2 h = __floats2half2_rn(a, b);
    float2 f = __half22float2(h);
    __half2 l = __floats2half2_rn(a - f.x, b - f.y);
    hv = *reinterpret_cast<uint32_t*>(&h);
    lv = *reinterpret_cast<uint32_t*>(&l);
}
__device__ __forceinline__ uint32_t cvt2h(float a, float b) {
    __half2 h = __floats2half2_rn(a, b);
    return *reinterpret_cast<uint32_t*>(&h);
}
__device__ __forceinline__ void split_store4h(float4 v, __half* hi, __half* lo) {
    uint32_t h0, l0, h1, l1;
    split2h(v.x, v.y, h0, l0);
    split2h(v.z, v.w, h1, l1);
    *reinterpret_cast<uint2*>(hi) = make_uint2(h0, h1);
    *reinterpret_cast<uint2*>(lo) = make_uint2(l0, l1);
}
__device__ __forceinline__ void cvt_store4h(float4 v, __half* dst) {
    *reinterpret_cast<uint2*>(dst) = make_uint2(cvt2h(v.x, v.y), cvt2h(v.z, v.w));
}

// =====================================================================
// GEMM tile constants: CTA 128x256x32, 512 thr (16 warps 4x4),
// warp tile 32x64, two smem stages, one barrier per k-tile.
// A split into fp16 hi/lo (2 planes); B single fp16 (1 plane).
// =====================================================================
constexpr int SA_ST = 40;    // sA row stride (32+8 halves)
constexpr int SB_ST = 264;   // sB row stride (256+8 halves)
constexpr int SA_SZ = 128 * SA_ST;          // 5120
constexpr int SB_SZ = 32 * SB_ST;           // 8448
constexpr int ST_SZ = 2 * SA_SZ + SB_SZ;    // halves per stage = 18688
constexpr int GEMM_SMEM_BYTES = 2 * ST_SZ * 2;   // 74752 B

// =====================================================================
// Fused QKV projection + RoPE + scale + fp16 split/convert + relayout.
// One launch, 384 tiles: t<256 -> Q (32x8), t<320 -> K (32x2), else V (32x2).
// Q written as hi/lo split; K,V written single fp16.
// =====================================================================
__global__ __launch_bounds__(512, 1) void gemm_qkv_rope(
    const float* __restrict__ A,
    const float* __restrict__ wq, const float* __restrict__ wk, const float* __restrict__ wv,
    const float* __restrict__ cosb, const float* __restrict__ sinb,
    __half* __restrict__ Qh, __half* __restrict__ Ql,
    __half* __restrict__ Kh, __half* __restrict__ Vh,
    float qsc)
{
    extern __shared__ __half gs[];

    const int tile = blockIdx.x;
    int which, bm, bn;
    if (tile < 256)      { which = 0; bm = tile >> 3;         bn = tile & 7; }
    else if (tile < 320) { which = 1; bm = (tile - 256) >> 1; bn = (tile - 256) & 1; }
    else                 { which = 2; bm = (tile - 320) >> 1; bn = (tile - 320) & 1; }
    const float* Bm = (which == 0) ? wq : (which == 1) ? wk : wv;
    const int N = (which == 0) ? (NH * HD) : (NKV * HD);
    const int K = HID;

    const int tid  = threadIdx.x;
    const int lane = tid & 31;
    const int wid  = tid >> 5;
    const int wm   = (wid >> 2) * 32;
    const int wn   = (wid & 3) * 64;

    const float* Ab = A + (size_t)bm * 128 * K;
    const float* Bb = Bm + (size_t)bn * 256;

    float acc[2][8][4] = {};
    float4 ra[2], rb[4];

    auto gload = [&](int k0) {
#pragma unroll
        for (int i = 0; i < 2; i++) {
            int idx = i * 512 + tid;
            int r = idx >> 3, c4 = idx & 7;
            ra[i] = *(const float4*)(Ab + (size_t)r * K + k0 + c4 * 4);
        }
#pragma unroll
        for (int i = 0; i < 4; i++) {
            int idx = i * 512 + tid;
            int r = idx >> 6, c4 = idx & 63;
            rb[i] = *(const float4*)(Bb + (size_t)(k0 + r) * N + c4 * 4);
        }
    };
    auto sstore = [&](int s) {
        __half* sA0 = gs + s * ST_SZ;
        __half* sA1 = sA0 + SA_SZ;
        __half* sB0 = sA0 + 2 * SA_SZ;
#pragma unroll
        for (int i = 0; i < 2; i++) {
            int idx = i * 512 + tid;
            int r = idx >> 3, c = (idx & 7) * 4;
            split_store4h(ra[i], sA0 + r * SA_ST + c, sA1 + r * SA_ST + c);
        }
#pragma unroll
        for (int i = 0; i < 4; i++) {
            int idx = i * 512 + tid;
            int r = idx >> 6, c = (idx & 63) * 4;
            cvt_store4h(rb[i], sB0 + r * SB_ST + c);
        }
    };

    gload(0);
    sstore(0);
    __syncthreads();

    const int nk = K / 32;
    for (int kt = 0; kt < nk; kt++) {
        const int s = kt & 1;
        if (kt + 1 < nk) gload((kt + 1) * 32);

        const __half* sA0 = gs + s * ST_SZ;
        const __half* sA1 = sA0 + SA_SZ;
        const __half* sB0 = sA0 + 2 * SA_SZ;

#pragma unroll
        for (int ks = 0; ks < 2; ks++) {
            const int colA = ks * 16 + ((lane >> 4) << 3);
            uint32_t af0[2][4], af1[2][4];
#pragma unroll
            for (int mf = 0; mf < 2; mf++) {
                int row = wm + mf * 16 + (lane & 15);
                ldsm4(af0[mf], sA0 + row * SA_ST + colA);
                ldsm4(af1[mf], sA1 + row * SA_ST + colA);
            }
            const int rowB = ks * 16 + (lane & 15);
#pragma unroll
            for (int nf2 = 0; nf2 < 4; nf2++) {
                const int colB = wn + nf2 * 16 + ((lane >> 4) << 3);
                uint32_t bh[4];
                ldsm4t(bh, sB0 + rowB * SB_ST + colB);
#pragma unroll
                for (int mf = 0; mf < 2; mf++)
#pragma unroll
                    for (int sub = 0; sub < 2; sub++)
                        mma_f16(acc[mf][nf2 * 2 + sub], af0[mf], bh[sub * 2], bh[sub * 2 + 1]);
#pragma unroll
                for (int mf = 0; mf < 2; mf++)
#pragma unroll
                    for (int sub = 0; sub < 2; sub++)
                        mma_f16(acc[mf][nf2 * 2 + sub], af1[mf], bh[sub * 2], bh[sub * 2 + 1]);
            }
        }
        if (kt + 1 < nk) sstore(s ^ 1);
        __syncthreads();
    }

    // ---- fused rope + convert epilogue (smem exchange, two 64-row passes) ----
    {
        float* sf = reinterpret_cast<float*>(gs);        // 64 x 264 f32 = 67.6 KB
        const int H = (which == 0) ? NH : NKV;
        const float scale = (which == 0) ? qsc : 1.0f;
        const int do_rope = (which != 2);

#pragma unroll
        for (int mf = 0; mf < 2; mf++) {
            int rl0 = (wm >> 5) * 16 + (lane >> 2);
#pragma unroll
            for (int nf = 0; nf < 8; nf++) {
                int col = wn + nf * 8 + (lane & 3) * 2;
                *(float2*)(sf + rl0 * 264 + col)       = make_float2(acc[mf][nf][0], acc[mf][nf][1]);
                *(float2*)(sf + (rl0 + 8) * 264 + col) = make_float2(acc[mf][nf][2], acc[mf][nf][3]);
            }
            __syncthreads();
#pragma unroll
            for (int k = 0; k < 16; k++) {
                int e2 = k * 512 + tid;
                int rl = e2 >> 7;
                int c2 = (e2 & 127) * 2;
                int r  = bm * 128 + (rl >> 4) * 32 + mf * 16 + (rl & 15);
                int t  = r & (T_ - 1);
                int b  = r >> 11;
                int gc = bn * 256 + c2;
                int h  = gc >> 7;
                int d  = gc & 127;
                float2 v = *(float2*)(sf + rl * 264 + c2);
                float o0, o1;
                if (do_rope) {
                    int dd = d & 63;
                    float2 cs = *(const float2*)(cosb + t * 64 + dd);
                    float2 sn = *(const float2*)(sinb + t * 64 + dd);
                    float2 w  = *(float2*)(sf + rl * 264 + (c2 ^ 64));
                    if (d < 64) { o0 = v.x * cs.x - w.x * sn.x; o1 = v.y * cs.y - w.y * sn.y; }
                    else        { o0 = v.x * cs.x + w.x * sn.x; o1 = v.y * cs.y + w.y * sn.y; }
                } else { o0 = v.x; o1 = v.y; }
                o0 *= scale; o1 *= scale;
                size_t di = (((size_t)(b * H + h)) * T_ + t) * HD + d;
                if (which == 0) {
                    uint32_t hv, lv;
                    split2h(o0, o1, hv, lv);
                    *(uint32_t*)(Qh + di) = hv;
                    *(uint32_t*)(Ql + di) = lv;
                } else if (which == 1) {
                    *(uint32_t*)(Kh + di) = cvt2h(o0, o1);
                } else {
                    *(uint32_t*)(Vh + di) = cvt2h(o0, o1);
                }
            }
            __syncthreads();
        }
    }
}

// =====================================================================
// Output-projection GEMM (fp32 in/out): A split fp16, B single fp16.
// =====================================================================
__global__ __launch_bounds__(512, 1) void gemm_f16(
    const float* __restrict__ A, const float* __restrict__ Bm, float* __restrict__ C,
    int M, int N, int K)
{
    extern __shared__ __half gs[];

    const int tid  = threadIdx.x;
    const int lane = tid & 31;
    const int wid  = tid >> 5;
    const int bm   = blockIdx.y, bn = blockIdx.x;
    const int wm   = (wid >> 2) * 32;
    const int wn   = (wid & 3) * 64;

    const float* Ab = A + (size_t)bm * 128 * K;
    const float* Bb = Bm + (size_t)bn * 256;

    float acc[2][8][4] = {};
    float4 ra[2], rb[4];

    auto gload = [&](int k0) {
#pragma unroll
        for (int i = 0; i < 2; i++) {
            int idx = i * 512 + tid;
            int r = idx >> 3, c4 = idx & 7;
            ra[i] = *(const float4*)(Ab + (size_t)r * K + k0 + c4 * 4);
        }
#pragma unroll
        for (int i = 0; i < 4; i++) {
            int idx = i * 512 + tid;
            int r = idx >> 6, c4 = idx & 63;
            rb[i] = *(const float4*)(Bb + (size_t)(k0 + r) * N + c4 * 4);
        }
    };
    auto sstore = [&](int s) {
        __half* sA0 = gs + s * ST_SZ;
        __half* sA1 = sA0 + SA_SZ;
        __half* sB0 = sA0 + 2 * SA_SZ;
#pragma unroll
        for (int i = 0; i < 2; i++) {
            int idx = i * 512 + tid;
            int r = idx >> 3, c = (idx & 7) * 4;
            split_store4h(ra[i], sA0 + r * SA_ST + c, sA1 + r * SA_ST + c);
        }
#pragma unroll
        for (int i = 0; i < 4; i++) {
            int idx = i * 512 + tid;
            int r = idx >> 6, c = (idx & 63) * 4;
            cvt_store4h(rb[i], sB0 + r * SB_ST + c);
        }
    };

    gload(0);
    sstore(0);
    __syncthreads();

    const int nk = K / 32;
    for (int kt = 0; kt < nk; kt++) {
        const int s = kt & 1;
        if (kt + 1 < nk) gload((kt + 1) * 32);

        const __half* sA0 = gs + s * ST_SZ;
        const __half* sA1 = sA0 + SA_SZ;
        const __half* sB0 = sA0 + 2 * SA_SZ;

#pragma unroll
        for (int ks = 0; ks < 2; ks++) {
            const int colA = ks * 16 + ((lane >> 4) << 3);
            uint32_t af0[2][4], af1[2][4];
#pragma unroll
            for (int mf = 0; mf < 2; mf++) {
                int row = wm + mf * 16 + (lane & 15);
                ldsm4(af0[mf], sA0 + row * SA_ST + colA);
                ldsm4(af1[mf], sA1 + row * SA_ST + colA);
            }
            const int rowB = ks * 16 + (lane & 15);
#pragma unroll
            for (int nf2 = 0; nf2 < 4; nf2++) {
                const int colB = wn + nf2 * 16 + ((lane >> 4) << 3);
                uint32_t bh[4];
                ldsm4t(bh, sB0 + rowB * SB_ST + colB);
#pragma unroll
                for (int mf = 0; mf < 2; mf++)
#pragma unroll
                    for (int sub = 0; sub < 2; sub++)
                        mma_f16(acc[mf][nf2 * 2 + sub], af0[mf], bh[sub * 2], bh[sub * 2 + 1]);
#pragma unroll
                for (int mf = 0; mf < 2; mf++)
#pragma unroll
                    for (int sub = 0; sub < 2; sub++)
                        mma_f16(acc[mf][nf2 * 2 + sub], af1[mf], bh[sub * 2], bh[sub * 2 + 1]);
            }
        }
        if (kt + 1 < nk) sstore(s ^ 1);
        __syncthreads();
    }

#pragma unroll
    for (int mf = 0; mf < 2; mf++) {
        int r0 = bm * 128 + wm + mf * 16 + (lane >> 2);
#pragma unroll
        for (int nf = 0; nf < 8; nf++) {
            int c = bn * 256 + wn + nf * 8 + (lane & 3) * 2;
            *(float2*)(C + (size_t)r0 * N + c)       = make_float2(acc[mf][nf][0], acc[mf][nf][1]);
            *(float2*)(C + (size_t)(r0 + 8) * N + c) = make_float2(acc[mf][nf][2], acc[mf][nf][3]);
        }
    }
}

// =====================================================================
// Flash attention (causal, GQA). Br=64 (4 warps x 16 rows), Bc=64.
// Q split fp16 hi/lo; K, V single fp16. 2 CTAs per SM.
// =====================================================================
constexpr int AS       = 136;
constexpr int Q_H_OFF  = 0;
constexpr int Q_L_OFF  = 64 * AS;
constexpr int K_OFF    = 2 * 64 * AS;
constexpr int V_OFF    = 3 * 64 * AS;
constexpr int ATTN_SMEM_BYTES = 4 * 64 * AS * 2;   // 69632

__global__ __launch_bounds__(128, 2) void attn_kernel(
    const __half* __restrict__ Qh, const __half* __restrict__ Ql,
    const __half* __restrict__ Kh, const __half* __restrict__ Vh,
    float* __restrict__ O)
{
    extern __shared__ __half sm[];
    const int tid  = threadIdx.x;
    const int lane = tid & 31;
    const int wid  = tid >> 5;
    const int bh   = blockIdx.y;
    const int b    = bh >> 4, h = bh & 15;
    const int qi   = (int)gridDim.x - 1 - (int)blockIdx.x;
    const int qbase = qi * 64;
    const int kvi  = b * NKV + (h >> 2);

    const __half* qh_g = Qh + ((size_t)bh * T_ + qbase) * HD;
    const __half* ql_g = Ql + ((size_t)bh * T_ + qbase) * HD;
    const __half* k_g  = Kh + (size_t)kvi * T_ * HD;
    const __half* v_g  = Vh + (size_t)kvi * T_ * HD;

    // Q tile: 2 planes x 64 rows x 128 halves = 2048 x 16B / 2 = 1024 chunks
#pragma unroll
    for (int i = 0; i < 8; i++) {
        int c = i * 128 + tid;
        int split = c >> 9, cc = c & 511;
        int row = cc >> 3, ch = cc & 7;
        const __half* src = (split ? ql_g : qh_g) + row * HD + ch * 16;
        cpasync16(smem_u32(sm + (split ? Q_L_OFF : Q_H_OFF) + row * AS + ch * 16), src);
        cpasync16(smem_u32(sm + (split ? Q_L_OFF : Q_H_OFF) + row * AS + ch * 16 + 8),
                  src + 8);
    }
    cpcommit();

    auto loadKV = [&](int j) {
        size_t gb = (size_t)j * 64 * HD;
#pragma unroll
        for (int i = 0; i < 8; i++) {
            int c = i * 128 + tid;                  // 1024 chunks: 512 K + 512 V
            int which = c >> 9, cc = c & 511;
            int row = cc >> 3, ch = cc & 7;
            const __half* src = (which ? v_g : k_g) + gb + row * HD + ch * 16;
            int off = (which ? V_OFF : K_OFF) + row * AS + ch * 16;
            cpasync16(smem_u32(sm + off), src);
            cpasync16(smem_u32(sm + off + 8), src + 8);
        }
        cpcommit();
    };

    float m0 = -1e30f, m1 = -1e30f, l0 = 0.f, l1 = 0.f;
    float o[16][4];
#pragma unroll
    for (int i = 0; i < 16; i++)
#pragma unroll
        for (int j = 0; j < 4; j++) o[i][j] = 0.f;

    const int nj = qi + 1;
    const int rowbase = qbase + wid * 16;

    for (int j = 0; j < nj; j++) {
        loadKV(j);
        cpwait<0>();
        __syncthreads();

        // ---- S = Q K^T (exp2 domain): (Qh+Ql) x Kh, 4 mma per nf2 ----
        float sacc[8][4];
#pragma unroll
        for (int i = 0; i < 8; i++)
#pragma unroll
            for (int jj = 0; jj < 4; jj++) sacc[i][jj] = 0.f;

#pragma unroll
        for (int ks = 0; ks < 8; ks++) {
            uint32_t qa[2][4];
            {
                int row = wid * 16 + (lane & 15);
                int col = ks * 16 + ((lane >> 4) << 3);
                ldsm4(qa[0], sm + Q_H_OFF + row * AS + col);
                ldsm4(qa[1], sm + Q_L_OFF + row * AS + col);
            }
#pragma unroll
            for (int nf2 = 0; nf2 < 4; nf2++) {
                uint32_t kh4[4];
                int krow = nf2 * 16 + (lane & 15);
                int kcol = ks * 16 + ((lane >> 4) << 3);
                ldsm4(kh4, sm + K_OFF + krow * AS + kcol);
                mma_f16(sacc[2 * nf2],     qa[0], kh4[0], kh4[2]);
                mma_f16(sacc[2 * nf2 + 1], qa[0], kh4[1], kh4[3]);
                mma_f16(sacc[2 * nf2],     qa[1], kh4[0], kh4[2]);
                mma_f16(sacc[2 * nf2 + 1], qa[1], kh4[1], kh4[3]);
            }
        }

        // ---- causal mask (diagonal tile only) ----
        const int kvb = j * 64;
        if (kvb + 63 > rowbase) {
            int r0 = rowbase + (lane >> 2), r1 = r0 + 8;
#pragma unroll
            for (int nf = 0; nf < 8; nf++) {
                int c0 = kvb + nf * 8 + (lane & 3) * 2;
                if (c0 > r0)     sacc[nf][0] = -1e30f;
                if (c0 + 1 > r0) sacc[nf][1] = -1e30f;
                if (c0 > r1)     sacc[nf][2] = -1e30f;
                if (c0 + 1 > r1) sacc[nf][3] = -1e30f;
            }
        }

        // ---- online softmax (base 2) ----
        float rm0 = -1e30f, rm1 = -1e30f;
#pragma unroll
        for (int nf = 0; nf < 8; nf++) {
            rm0 = fmaxf(rm0, fmaxf(sacc[nf][0], sacc[nf][1]));
            rm1 = fmaxf(rm1, fmaxf(sacc[nf][2], sacc[nf][3]));
        }
        rm0 = fmaxf(rm0, __shfl_xor_sync(0xffffffffu, rm0, 1));
        rm0 = fmaxf(rm0, __shfl_xor_sync(0xffffffffu, rm0, 2));
        rm1 = fmaxf(rm1, __shfl_xor_sync(0xffffffffu, rm1, 1));
        rm1 = fmaxf(rm1, __shfl_xor_sync(0xffffffffu, rm1, 2));
        float mn0 = fmaxf(m0, rm0), mn1 = fmaxf(m1, rm1);
        float corr0 = exp2f(m0 - mn0), corr1 = exp2f(m1 - mn1);
        m0 = mn0; m1 = mn1;

        float rs0 = 0.f, rs1 = 0.f;
#pragma unroll
        for (int nf = 0; nf < 8; nf++) {
            float p0 = exp2f(sacc[nf][0] - mn0);
            float p1 = exp2f(sacc[nf][1] - mn0);
            float p2 = exp2f(sacc[nf][2] - mn1);
            float p3 = exp2f(sacc[nf][3] - mn1);
            sacc[nf][0] = p0; sacc[nf][1] = p1; sacc[nf][2] = p2; sacc[nf][3] = p3;
            rs0 += p0 + p1; rs1 += p2 + p3;
        }
        l0 = l0 * corr0 + rs0;
        l1 = l1 * corr1 + rs1;
        if (__any_sync(0xffffffffu, (corr0 != 1.f) || (corr1 != 1.f))) {
#pragma unroll
            for (int df = 0; df < 16; df++) {
                o[df][0] *= corr0; o[df][1] *= corr0;
                o[df][2] *= corr1; o[df][3] *= corr1;
            }
        }

        // ---- pack P into fp16 hi/lo A-fragments ----
        uint32_t ph[4][4], pl[4][4];
#pragma unroll
        for (int kk = 0; kk < 4; kk++) {
            const float* A0 = sacc[2 * kk];
            const float* A1 = sacc[2 * kk + 1];
            split2h(A0[0], A0[1], ph[kk][0], pl[kk][0]);
            split2h(A0[2], A0[3], ph[kk][1], pl[kk][1]);
            split2h(A1[0], A1[1], ph[kk][2], pl[kk][2]);
            split2h(A1[2], A1[3], ph[kk][3], pl[kk][3]);
        }

        // ---- O += P V : (Ph+Pl) x Vh, 4 mma per nf2 ----
#pragma unroll
        for (int kk = 0; kk < 4; kk++) {
#pragma unroll
            for (int nf2 = 0; nf2 < 8; nf2++) {
                uint32_t vh4[4];
                int vrow = kk * 16 + (lane & 15);
                int vcol = nf2 * 16 + ((lane >> 4) << 3);
                ldsm4t(vh4, sm + V_OFF + vrow * AS + vcol);
                mma_f16(o[2 * nf2],     ph[kk], vh4[0], vh4[1]);
                mma_f16(o[2 * nf2 + 1], ph[kk], vh4[2], vh4[3]);
                mma_f16(o[2 * nf2],     pl[kk], vh4[0], vh4[1]);
                mma_f16(o[2 * nf2 + 1], pl[kk], vh4[2], vh4[3]);
            }
        }
        __syncthreads();
    }

    // ---- finalize ----
    l0 += __shfl_xor_sync(0xffffffffu, l0, 1);
    l0 += __shfl_xor_sync(0xffffffffu, l0, 2);
    l1 += __shfl_xor_sync(0xffffffffu, l1, 1);
    l1 += __shfl_xor_sync(0xffffffffu, l1, 2);
    float inv0 = 1.f / l0, inv1 = 1.f / l1;

    int r0 = rowbase + (lane >> 2);
    size_t base0 = ((size_t)b * T_ + r0) * HID + h * HD + (lane & 3) * 2;
    size_t base1 = base0 + (size_t)8 * HID;
#pragma unroll
    for (int df = 0; df < 16; df++) {
        *(float2*)(O + base0 + df * 8) = make_float2(o[df][0] * inv0, o[df][1] * inv0);
        *(float2*)(O + base1 + df * 8) = make_float2(o[df][2] * inv1, o[df][3] * inv1);
    }
}

// =====================================================================
// host launcher
// =====================================================================
extern "C" void kernel_launch(void* const* d_in, const int* in_sizes, int n_in,
                              void* d_out, int out_size)
{
    const float* x    = (const float*)d_in[0];
    const float* cosb = (const float*)d_in[1];
    const float* sinb = (const float*)d_in[2];
    const float* wq   = (const float*)d_in[3];
    const float* wk   = (const float*)d_in[4];
    const float* wv   = (const float*)d_in[5];
    const float* wo   = (const float*)d_in[6];

    float* Octx;
    __half *Qh, *Ql, *Kh, *Vh;
    cudaGetSymbolAddress((void**)&Octx, g_Octx);
    cudaGetSymbolAddress((void**)&Qh, g_Qh);
    cudaGetSymbolAddress((void**)&Ql, g_Ql);
    cudaGetSymbolAddress((void**)&Kh, g_Kh);
    cudaGetSymbolAddress((void**)&Vh, g_Vh);

    cudaFuncSetAttribute(attn_kernel, cudaFuncAttributeMaxDynamicSharedMemorySize,
                         ATTN_SMEM_BYTES);
    cudaFuncSetAttribute(gemm_f16, cudaFuncAttributeMaxDynamicSharedMemorySize,
                         GEMM_SMEM_BYTES);
    cudaFuncSetAttribute(gemm_qkv_rope, cudaFuncAttributeMaxDynamicSharedMemorySize,
                         GEMM_SMEM_BYTES);

    const int M = B_ * T_;  // 4096
    float qsc = (1.0f / sqrtf((float)HD)) * 1.4426950408889634f;

    // 0: fused QKV projection + rope + split (384 tiles, one launch)
    gemm_qkv_rope<<<384, 512, GEMM_SMEM_BYTES>>>(
        x, wq, wk, wv, cosb, sinb, Qh, Ql, Kh, Vh, qsc);
    // 1: attention
    attn_kernel<<<dim3(T_ / 64, B_ * NH), 128, ATTN_SMEM_BYTES>>>(
        Qh, Ql, Kh, Vh, Octx);
    // 2: output projection
    gemm_f16<<<dim3(HID / 256, M / 128), 512, GEMM_SMEM_BYTES>>>(
        Octx, wo, (float*)d_out, M, HID, HID);
}

// round 12
// speedup vs baseline: 1.3947x; 1.0088x over previous
#include <cuda_runtime.h>
#include <cuda_fp16.h>
#include <cstdint>
#include <cstddef>
#include <math.h>

// Problem constants
constexpr int B_  = 2;
constexpr int T_  = 2048;
constexpr int HID = 2048;
constexpr int NH  = 16;
constexpr int NKV = 4;
constexpr int HD  = 128;

// ---------------- scratch (static device arrays; no allocation) ----------------
__device__ float   g_Octx[(size_t)B_ * T_ * NH * HD];
__device__ __half  g_Qh[(size_t)B_ * NH  * T_ * HD];
__device__ __half  g_Ql[(size_t)B_ * NH  * T_ * HD];
__device__ __half  g_Kh[(size_t)B_ * NKV * T_ * HD];
__device__ __half  g_Vh[(size_t)B_ * NKV * T_ * HD];

// ---------------- PTX helpers ----------------
__device__ __forceinline__ uint32_t smem_u32(const void* p) {
    return (uint32_t)__cvta_generic_to_shared(p);
}
__device__ __forceinline__ void ldsm4(uint32_t r[4], const void* p) {
    uint32_t a = smem_u32(p);
    asm volatile("ldmatrix.sync.aligned.m8n8.x4.shared.b16 {%0,%1,%2,%3}, [%4];"
                 : "=r"(r[0]), "=r"(r[1]), "=r"(r[2]), "=r"(r[3]) : "r"(a));
}
__device__ __forceinline__ void ldsm4t(uint32_t r[4], const void* p) {
    uint32_t a = smem_u32(p);
    asm volatile("ldmatrix.sync.aligned.m8n8.x4.trans.shared.b16 {%0,%1,%2,%3}, [%4];"
                 : "=r"(r[0]), "=r"(r[1]), "=r"(r[2]), "=r"(r[3]) : "r"(a));
}
__device__ __forceinline__ void mma_f16(float c[4], const uint32_t a[4], uint32_t b0, uint32_t b1) {
    asm volatile("mma.sync.aligned.m16n8k16.row.col.f32.f16.f16.f32 "
                 "{%0,%1,%2,%3}, {%4,%5,%6,%7}, {%8,%9}, {%0,%1,%2,%3};"
                 : "+f"(c[0]), "+f"(c[1]), "+f"(c[2]), "+f"(c[3])
                 : "r"(a[0]), "r"(a[1]), "r"(a[2]), "r"(a[3]), "r"(b0), "r"(b1));
}
__device__ __forceinline__ void cpasync16(uint32_t saddr, const void* g) {
    asm volatile("cp.async.cg.shared.global [%0], [%1], 16;" :: "r"(saddr), "l"(g));
}
__device__ __forceinline__ void cpcommit() { asm volatile("cp.async.commit_group;"); }
template <int N> __device__ __forceinline__ void cpwait() {
    asm volatile("cp.async.wait_group %0;" :: "n"(N));
}
// fp16 hi/lo split of a float pair
__device__ __forceinline__ void split2h(float a, float b, uint32_t& hv, uint32_t& lv) {
    __half2 h = __floats2half2_rn(a, b);
    float2 f = __half22float2(h);
    __half2 l = __floats2half2_rn(a - f.x, b - f.y);
    hv = *reinterpret_cast<uint32_t*>(&h);
    lv = *reinterpret_cast<uint32_t*>(&l);
}
__device__ __forceinline__ uint32_t cvt2h(float a, float b) {
    __half2 h = __floats2half2_rn(a, b);
    return *reinterpret_cast<uint32_t*>(&h);
}
__device__ __forceinline__ void split_store4h(float4 v, __half* hi, __half* lo) {
    uint32_t h0, l0, h1, l1;
    split2h(v.x, v.y, h0, l0);
    split2h(v.z, v.w, h1, l1);
    *reinterpret_cast<uint2*>(hi) = make_uint2(h0, h1);
    *reinterpret_cast<uint2*>(lo) = make_uint2(l0, l1);
}
__device__ __forceinline__ void cvt_store4h(float4 v, __half* dst) {
    *reinterpret_cast<uint2*>(dst) = make_uint2(cvt2h(v.x, v.y), cvt2h(v.z, v.w));
}

// =====================================================================
// GEMM tile constants: CTA 128x256x32, 512 thr (16 warps 4x4),
// warp tile 32x64, two smem stages, one barrier per k-tile.
// A split into fp16 hi/lo (2 planes); B single fp16 (1 plane).
// =====================================================================
constexpr int SA_ST = 40;    // sA row stride (32+8 halves)
constexpr int SB_ST = 264;   // sB row stride (256+8 halves)
constexpr int SA_SZ = 128 * SA_ST;          // 5120
constexpr int SB_SZ = 32 * SB_ST;           // 8448
constexpr int ST_SZ = 2 * SA_SZ + SB_SZ;    // halves per stage = 18688
constexpr int GEMM_SMEM_BYTES = 2 * ST_SZ * 2;   // 74752 B

// =====================================================================
// Fused QKV projection + RoPE + scale + fp16 split/convert + relayout.
// One launch, 384 tiles: t<256 -> Q (32x8), t<320 -> K (32x2), else V (32x2).
// Q written as hi/lo split; K,V written single fp16.
// =====================================================================
__global__ __launch_bounds__(512, 1) void gemm_qkv_rope(
    const float* __restrict__ A,
    const float* __restrict__ wq, const float* __restrict__ wk, const float* __restrict__ wv,
    const float* __restrict__ cosb, const float* __restrict__ sinb,
    __half* __restrict__ Qh, __half* __restrict__ Ql,
    __half* __restrict__ Kh, __half* __restrict__ Vh,
    float qsc)
{
    extern __shared__ __half gs[];

    const int tile = blockIdx.x;
    int which, bm, bn;
    if (tile < 256)      { which = 0; bm = tile >> 3;         bn = tile & 7; }
    else if (tile < 320) { which = 1; bm = (tile - 256) >> 1; bn = (tile - 256) & 1; }
    else                 { which = 2; bm = (tile - 320) >> 1; bn = (tile - 320) & 1; }
    const float* Bm = (which == 0) ? wq : (which == 1) ? wk : wv;
    const int N = (which == 0) ? (NH * HD) : (NKV * HD);
    const int K = HID;

    const int tid  = threadIdx.x;
    const int lane = tid & 31;
    const int wid  = tid >> 5;
    const int wm   = (wid >> 2) * 32;
    const int wn   = (wid & 3) * 64;

    const float* Ab = A + (size_t)bm * 128 * K;
    const float* Bb = Bm + (size_t)bn * 256;

    float acc[2][8][4] = {};
    float4 ra[2], rb[4];

    auto gload = [&](int k0) {
#pragma unroll
        for (int i = 0; i < 2; i++) {
            int idx = i * 512 + tid;
            int r = idx >> 3, c4 = idx & 7;
            ra[i] = *(const float4*)(Ab + (size_t)r * K + k0 + c4 * 4);
        }
#pragma unroll
        for (int i = 0; i < 4; i++) {
            int idx = i * 512 + tid;
            int r = idx >> 6, c4 = idx & 63;
            rb[i] = *(const float4*)(Bb + (size_t)(k0 + r) * N + c4 * 4);
        }
    };
    auto sstore = [&](int s) {
        __half* sA0 = gs + s * ST_SZ;
        __half* sA1 = sA0 + SA_SZ;
        __half* sB0 = sA0 + 2 * SA_SZ;
#pragma unroll
        for (int i = 0; i < 2; i++) {
            int idx = i * 512 + tid;
            int r = idx >> 3, c = (idx & 7) * 4;
            split_store4h(ra[i], sA0 + r * SA_ST + c, sA1 + r * SA_ST + c);
        }
#pragma unroll
        for (int i = 0; i < 4; i++) {
            int idx = i * 512 + tid;
            int r = idx >> 6, c = (idx & 63) * 4;
            cvt_store4h(rb[i], sB0 + r * SB_ST + c);
        }
    };

    gload(0);
    sstore(0);
    __syncthreads();

    const int nk = K / 32;
    for (int kt = 0; kt < nk; kt++) {
        const int s = kt & 1;
        if (kt + 1 < nk) gload((kt + 1) * 32);

        const __half* sA0 = gs + s * ST_SZ;
        const __half* sA1 = sA0 + SA_SZ;
        const __half* sB0 = sA0 + 2 * SA_SZ;

#pragma unroll
        for (int ks = 0; ks < 2; ks++) {
            const int colA = ks * 16 + ((lane >> 4) << 3);
            uint32_t af0[2][4], af1[2][4];
#pragma unroll
            for (int mf = 0; mf < 2; mf++) {
                int row = wm + mf * 16 + (lane & 15);
                ldsm4(af0[mf], sA0 + row * SA_ST + colA);
                ldsm4(af1[mf], sA1 + row * SA_ST + colA);
            }
            const int rowB = ks * 16 + (lane & 15);
#pragma unroll
            for (int nf2 = 0; nf2 < 4; nf2++) {
                const int colB = wn + nf2 * 16 + ((lane >> 4) << 3);
                uint32_t bh[4];
                ldsm4t(bh, sB0 + rowB * SB_ST + colB);
#pragma unroll
                for (int mf = 0; mf < 2; mf++)
#pragma unroll
                    for (int sub = 0; sub < 2; sub++)
                        mma_f16(acc[mf][nf2 * 2 + sub], af0[mf], bh[sub * 2], bh[sub * 2 + 1]);
#pragma unroll
                for (int mf = 0; mf < 2; mf++)
#pragma unroll
                    for (int sub = 0; sub < 2; sub++)
                        mma_f16(acc[mf][nf2 * 2 + sub], af1[mf], bh[sub * 2], bh[sub * 2 + 1]);
            }
        }
        if (kt + 1 < nk) sstore(s ^ 1);
        __syncthreads();
    }

    // ---- fused rope + convert epilogue (smem exchange, two 64-row passes) ----
    {
        float* sf = reinterpret_cast<float*>(gs);        // 64 x 264 f32 = 67.6 KB
        const int H = (which == 0) ? NH : NKV;
        const float scale = (which == 0) ? qsc : 1.0f;
        const int do_rope = (which != 2);

#pragma unroll
        for (int mf = 0; mf < 2; mf++) {
            int rl0 = (wm >> 5) * 16 + (lane >> 2);
#pragma unroll
            for (int nf = 0; nf < 8; nf++) {
                int col = wn + nf * 8 + (lane & 3) * 2;
                *(float2*)(sf + rl0 * 264 + col)       = make_float2(acc[mf][nf][0], acc[mf][nf][1]);
                *(float2*)(sf + (rl0 + 8) * 264 + col) = make_float2(acc[mf][nf][2], acc[mf][nf][3]);
            }
            __syncthreads();
#pragma unroll
            for (int k = 0; k < 16; k++) {
                int e2 = k * 512 + tid;
                int rl = e2 >> 7;
                int c2 = (e2 & 127) * 2;
                int r  = bm * 128 + (rl >> 4) * 32 + mf * 16 + (rl & 15);
                int t  = r & (T_ - 1);
                int b  = r >> 11;
                int gc = bn * 256 + c2;
                int h  = gc >> 7;
                int d  = gc & 127;
                float2 v = *(float2*)(sf + rl * 264 + c2);
                float o0, o1;
                if (do_rope) {
                    int dd = d & 63;
                    float2 cs = *(const float2*)(cosb + t * 64 + dd);
                    float2 sn = *(const float2*)(sinb + t * 64 + dd);
                    float2 w  = *(float2*)(sf + rl * 264 + (c2 ^ 64));
                    if (d < 64) { o0 = v.x * cs.x - w.x * sn.x; o1 = v.y * cs.y - w.y * sn.y; }
                    else        { o0 = v.x * cs.x + w.x * sn.x; o1 = v.y * cs.y + w.y * sn.y; }
                } else { o0 = v.x; o1 = v.y; }
                o0 *= scale; o1 *= scale;
                size_t di = (((size_t)(b * H + h)) * T_ + t) * HD + d;
                if (which == 0) {
                    uint32_t hv, lv;
                    split2h(o0, o1, hv, lv);
                    *(uint32_t*)(Qh + di) = hv;
                    *(uint32_t*)(Ql + di) = lv;
                } else if (which == 1) {
                    *(uint32_t*)(Kh + di) = cvt2h(o0, o1);
                } else {
                    *(uint32_t*)(Vh + di) = cvt2h(o0, o1);
                }
            }
            __syncthreads();
        }
    }
}

// =====================================================================
// Output-projection GEMM (fp32 in/out): A split fp16, B single fp16.
// =====================================================================
__global__ __launch_bounds__(512, 1) void gemm_f16(
    const float* __restrict__ A, const float* __restrict__ Bm, float* __restrict__ C,
    int M, int N, int K)
{
    extern __shared__ __half gs[];

    const int tid  = threadIdx.x;
    const int lane = tid & 31;
    const int wid  = tid >> 5;
    const int bm   = blockIdx.y, bn = blockIdx.x;
    const int wm   = (wid >> 2) * 32;
    const int wn   = (wid & 3) * 64;

    const float* Ab = A + (size_t)bm * 128 * K;
    const float* Bb = Bm + (size_t)bn * 256;

    float acc[2][8][4] = {};
    float4 ra[2], rb[4];

    auto gload = [&](int k0) {
#pragma unroll
        for (int i = 0; i < 2; i++) {
            int idx = i * 512 + tid;
            int r = idx >> 3, c4 = idx & 7;
            ra[i] = *(const float4*)(Ab + (size_t)r * K + k0 + c4 * 4);
        }
#pragma unroll
        for (int i = 0; i < 4; i++) {
            int idx = i * 512 + tid;
            int r = idx >> 6, c4 = idx & 63;
            rb[i] = *(const float4*)(Bb + (size_t)(k0 + r) * N + c4 * 4);
        }
    };
    auto sstore = [&](int s) {
        __half* sA0 = gs + s * ST_SZ;
        __half* sA1 = sA0 + SA_SZ;
        __half* sB0 = sA0 + 2 * SA_SZ;
#pragma unroll
        for (int i = 0; i < 2; i++) {
            int idx = i * 512 + tid;
            int r = idx >> 3, c = (idx & 7) * 4;
            split_store4h(ra[i], sA0 + r * SA_ST + c, sA1 + r * SA_ST + c);
        }
#pragma unroll
        for (int i = 0; i < 4; i++) {
            int idx = i * 512 + tid;
            int r = idx >> 6, c = (idx & 63) * 4;
            cvt_store4h(rb[i], sB0 + r * SB_ST + c);
        }
    };

    gload(0);
    sstore(0);
    __syncthreads();

    const int nk = K / 32;
    for (int kt = 0; kt < nk; kt++) {
        const int s = kt & 1;
        if (kt + 1 < nk) gload((kt + 1) * 32);

        const __half* sA0 = gs + s * ST_SZ;
        const __half* sA1 = sA0 + SA_SZ;
        const __half* sB0 = sA0 + 2 * SA_SZ;

#pragma unroll
        for (int ks = 0; ks < 2; ks++) {
            const int colA = ks * 16 + ((lane >> 4) << 3);
            uint32_t af0[2][4], af1[2][4];
#pragma unroll
            for (int mf = 0; mf < 2; mf++) {
                int row = wm + mf * 16 + (lane & 15);
                ldsm4(af0[mf], sA0 + row * SA_ST + colA);
                ldsm4(af1[mf], sA1 + row * SA_ST + colA);
            }
            const int rowB = ks * 16 + (lane & 15);
#pragma unroll
            for (int nf2 = 0; nf2 < 4; nf2++) {
                const int colB = wn + nf2 * 16 + ((lane >> 4) << 3);
                uint32_t bh[4];
                ldsm4t(bh, sB0 + rowB * SB_ST + colB);
#pragma unroll
                for (int mf = 0; mf < 2; mf++)
#pragma unroll
                    for (int sub = 0; sub < 2; sub++)
                        mma_f16(acc[mf][nf2 * 2 + sub], af0[mf], bh[sub * 2], bh[sub * 2 + 1]);
#pragma unroll
                for (int mf = 0; mf < 2; mf++)
#pragma unroll
                    for (int sub = 0; sub < 2; sub++)
                        mma_f16(acc[mf][nf2 * 2 + sub], af1[mf], bh[sub * 2], bh[sub * 2 + 1]);
            }
        }
        if (kt + 1 < nk) sstore(s ^ 1);
        __syncthreads();
    }

#pragma unroll
    for (int mf = 0; mf < 2; mf++) {
        int r0 = bm * 128 + wm + mf * 16 + (lane >> 2);
#pragma unroll
        for (int nf = 0; nf < 8; nf++) {
            int c = bn * 256 + wn + nf * 8 + (lane & 3) * 2;
            *(float2*)(C + (size_t)r0 * N + c)       = make_float2(acc[mf][nf][0], acc[mf][nf][1]);
            *(float2*)(C + (size_t)(r0 + 8) * N + c) = make_float2(acc[mf][nf][2], acc[mf][nf][3]);
        }
    }
}

// =====================================================================
// Flash attention (causal, GQA). Br=64 (4 warps x 16 rows), Bc=64.
// Q split fp16 hi/lo; K, V single fp16. DOUBLE-BUFFERED KV, one barrier
// per tile: wait(j) -> sync -> prefetch(j+1 into s^1) -> compute(s).
// 2 CTAs per SM (smem 104448 x 2 = 208896 <= 228KB).
// =====================================================================
constexpr int AS       = 136;
constexpr int Q_H_OFF  = 0;
constexpr int Q_L_OFF  = 64 * AS;
constexpr int KV_STAGE = 2 * 64 * AS;              // K+V per stage (halves)
constexpr int KV_BASE  = 2 * 64 * AS;              // after Q planes
constexpr int ATTN_SMEM_BYTES = (2 * 64 * AS + 2 * KV_STAGE) * 2;   // 104448

__global__ __launch_bounds__(128, 2) void attn_kernel(
    const __half* __restrict__ Qh, const __half* __restrict__ Ql,
    const __half* __restrict__ Kh, const __half* __restrict__ Vh,
    float* __restrict__ O)
{
    extern __shared__ __half sm[];
    const int tid  = threadIdx.x;
    const int lane = tid & 31;
    const int wid  = tid >> 5;
    const int bh   = blockIdx.y;
    const int b    = bh >> 4, h = bh & 15;
    const int qi   = (int)gridDim.x - 1 - (int)blockIdx.x;
    const int qbase = qi * 64;
    const int kvi  = b * NKV + (h >> 2);

    const __half* qh_g = Qh + ((size_t)bh * T_ + qbase) * HD;
    const __half* ql_g = Ql + ((size_t)bh * T_ + qbase) * HD;
    const __half* k_g  = Kh + (size_t)kvi * T_ * HD;
    const __half* v_g  = Vh + (size_t)kvi * T_ * HD;

    // Q tile: 2 planes x 64 rows x 128 halves
#pragma unroll
    for (int i = 0; i < 8; i++) {
        int c = i * 128 + tid;
        int split = c >> 9, cc = c & 511;
        int row = cc >> 3, ch = cc & 7;
        const __half* src = (split ? ql_g : qh_g) + row * HD + ch * 16;
        cpasync16(smem_u32(sm + (split ? Q_L_OFF : Q_H_OFF) + row * AS + ch * 16), src);
        cpasync16(smem_u32(sm + (split ? Q_L_OFF : Q_H_OFF) + row * AS + ch * 16 + 8),
                  src + 8);
    }

    auto loadKV = [&](int j, int st) {
        size_t gb = (size_t)j * 64 * HD;
        const int koff = KV_BASE + st * KV_STAGE;
        const int voff = koff + 64 * AS;
#pragma unroll
        for (int i = 0; i < 8; i++) {
            int c = i * 128 + tid;
            int which = c >> 9, cc = c & 511;
            int row = cc >> 3, ch = cc & 7;
            const __half* src = (which ? v_g : k_g) + gb + row * HD + ch * 16;
            int off = (which ? voff : koff) + row * AS + ch * 16;
            cpasync16(smem_u32(sm + off), src);
            cpasync16(smem_u32(sm + off + 8), src + 8);
        }
    };
    loadKV(0, 0);
    cpcommit();   // group 0: Q + KV0

    float m0 = -1e30f, m1 = -1e30f, l0 = 0.f, l1 = 0.f;
    float o[16][4];
#pragma unroll
    for (int i = 0; i < 16; i++)
#pragma unroll
        for (int j = 0; j < 4; j++) o[i][j] = 0.f;

    const int nj = qi + 1;
    const int rowbase = qbase + wid * 16;

    for (int j = 0; j < nj; j++) {
        const int s = j & 1;
        cpwait<0>();          // tile j resident (own warp)
        __syncthreads();      // all warps: loads visible, prev stage reads done
        if (j + 1 < nj) { loadKV(j + 1, s ^ 1); cpcommit(); }

        const int kb = KV_BASE + s * KV_STAGE;
        const int vb = kb + 64 * AS;

        // ---- S = Q K^T (exp2 domain): (Qh+Ql) x Kh ----
        float sacc[8][4];
#pragma unroll
        for (int i = 0; i < 8; i++)
#pragma unroll
            for (int jj = 0; jj < 4; jj++) sacc[i][jj] = 0.f;

#pragma unroll
        for (int ks = 0; ks < 8; ks++) {
            uint32_t qa[2][4];
            {
                int row = wid * 16 + (lane & 15);
                int col = ks * 16 + ((lane >> 4) << 3);
                ldsm4(qa[0], sm + Q_H_OFF + row * AS + col);
                ldsm4(qa[1], sm + Q_L_OFF + row * AS + col);
            }
#pragma unroll
            for (int nf2 = 0; nf2 < 4; nf2++) {
                uint32_t kh4[4];
                int krow = nf2 * 16 + (lane & 15);
                int kcol = ks * 16 + ((lane >> 4) << 3);
                ldsm4(kh4, sm + kb + krow * AS + kcol);
                mma_f16(sacc[2 * nf2],     qa[0], kh4[0], kh4[2]);
                mma_f16(sacc[2 * nf2 + 1], qa[0], kh4[1], kh4[3]);
                mma_f16(sacc[2 * nf2],     qa[1], kh4[0], kh4[2]);
                mma_f16(sacc[2 * nf2 + 1], qa[1], kh4[1], kh4[3]);
            }
        }

        // ---- causal mask (diagonal tile only) ----
        const int kvb = j * 64;
        if (kvb + 63 > rowbase) {
            int r0 = rowbase + (lane >> 2), r1 = r0 + 8;
#pragma unroll
            for (int nf = 0; nf < 8; nf++) {
                int c0 = kvb + nf * 8 + (lane & 3) * 2;
                if (c0 > r0)     sacc[nf][0] = -1e30f;
                if (c0 + 1 > r0) sacc[nf][1] = -1e30f;
                if (c0 > r1)     sacc[nf][2] = -1e30f;
                if (c0 + 1 > r1) sacc[nf][3] = -1e30f;
            }
        }

        // ---- online softmax (base 2) ----
        float rm0 = -1e30f, rm1 = -1e30f;
#pragma unroll
        for (int nf = 0; nf < 8; nf++) {
            rm0 = fmaxf(rm0, fmaxf(sacc[nf][0], sacc[nf][1]));
            rm1 = fmaxf(rm1, fmaxf(sacc[nf][2], sacc[nf][3]));
        }
        rm0 = fmaxf(rm0, __shfl_xor_sync(0xffffffffu, rm0, 1));
        rm0 = fmaxf(rm0, __shfl_xor_sync(0xffffffffu, rm0, 2));
        rm1 = fmaxf(rm1, __shfl_xor_sync(0xffffffffu, rm1, 1));
        rm1 = fmaxf(rm1, __shfl_xor_sync(0xffffffffu, rm1, 2));
        float mn0 = fmaxf(m0, rm0), mn1 = fmaxf(m1, rm1);
        float corr0 = exp2f(m0 - mn0), corr1 = exp2f(m1 - mn1);
        m0 = mn0; m1 = mn1;

        float rs0 = 0.f, rs1 = 0.f;
#pragma unroll
        for (int nf = 0; nf < 8; nf++) {
            float p0 = exp2f(sacc[nf][0] - mn0);
            float p1 = exp2f(sacc[nf][1] - mn0);
            float p2 = exp2f(sacc[nf][2] - mn1);
            float p3 = exp2f(sacc[nf][3] - mn1);
            sacc[nf][0] = p0; sacc[nf][1] = p1; sacc[nf][2] = p2; sacc[nf][3] = p3;
            rs0 += p0 + p1; rs1 += p2 + p3;
        }
        l0 = l0 * corr0 + rs0;
        l1 = l1 * corr1 + rs1;
        if (__any_sync(0xffffffffu, (corr0 != 1.f) || (corr1 != 1.f))) {
#pragma unroll
            for (int df = 0; df < 16; df++) {
                o[df][0] *= corr0; o[df][1] *= corr0;
                o[df][2] *= corr1; o[df][3] *= corr1;
            }
        }

        // ---- pack P into fp16 hi/lo A-fragments ----
        uint32_t ph[4][4], pl[4][4];
#pragma unroll
        for (int kk = 0; kk < 4; kk++) {
            const float* A0 = sacc[2 * kk];
            const float* A1 = sacc[2 * kk + 1];
            split2h(A0[0], A0[1], ph[kk][0], pl[kk][0]);
            split2h(A0[2], A0[3], ph[kk][1], pl[kk][1]);
            split2h(A1[0], A1[1], ph[kk][2], pl[kk][2]);
            split2h(A1[2], A1[3], ph[kk][3], pl[kk][3]);
        }

        // ---- O += P V : (Ph+Pl) x Vh ----
#pragma unroll
        for (int kk = 0; kk < 4; kk++) {
#pragma unroll
            for (int nf2 = 0; nf2 < 8; nf2++) {
                uint32_t vh4[4];
                int vrow = kk * 16 + (lane & 15);
                int vcol = nf2 * 16 + ((lane >> 4) << 3);
                ldsm4t(vh4, sm + vb + vrow * AS + vcol);
                mma_f16(o[2 * nf2],     ph[kk], vh4[0], vh4[1]);
                mma_f16(o[2 * nf2 + 1], ph[kk], vh4[2], vh4[3]);
                mma_f16(o[2 * nf2],     pl[kk], vh4[0], vh4[1]);
                mma_f16(o[2 * nf2 + 1], pl[kk], vh4[2], vh4[3]);
            }
        }
        // no bottom barrier: next iter writes the OTHER stage; the stage we
        // just read is only overwritten after every warp passes the NEXT
        // iteration's __syncthreads.
    }

    // ---- finalize ----
    l0 += __shfl_xor_sync(0xffffffffu, l0, 1);
    l0 += __shfl_xor_sync(0xffffffffu, l0, 2);
    l1 += __shfl_xor_sync(0xffffffffu, l1, 1);
    l1 += __shfl_xor_sync(0xffffffffu, l1, 2);
    float inv0 = 1.f / l0, inv1 = 1.f / l1;

    int r0 = rowbase + (lane >> 2);
    size_t base0 = ((size_t)b * T_ + r0) * HID + h * HD + (lane & 3) * 2;
    size_t base1 = base0 + (size_t)8 * HID;
#pragma unroll
    for (int df = 0; df < 16; df++) {
        *(float2*)(O + base0 + df * 8) = make_float2(o[df][0] * inv0, o[df][1] * inv0);
        *(float2*)(O + base1 + df * 8) = make_float2(o[df][2] * inv1, o[df][3] * inv1);
    }
}

// =====================================================================
// host launcher
// =====================================================================
extern "C" void kernel_launch(void* const* d_in, const int* in_sizes, int n_in,
                              void* d_out, int out_size)
{
    const float* x    = (const float*)d_in[0];
    const float* cosb = (const float*)d_in[1];
    const float* sinb = (const float*)d_in[2];
    const float* wq   = (const float*)d_in[3];
    const float* wk   = (const float*)d_in[4];
    const float* wv   = (const float*)d_in[5];
    const float* wo   = (const float*)d_in[6];

    float* Octx;
    __half *Qh, *Ql, *Kh, *Vh;
    cudaGetSymbolAddress((void**)&Octx, g_Octx);
    cudaGetSymbolAddress((void**)&Qh, g_Qh);
    cudaGetSymbolAddress((void**)&Ql, g_Ql);
    cudaGetSymbolAddress((void**)&Kh, g_Kh);
    cudaGetSymbolAddress((void**)&Vh, g_Vh);

    cudaFuncSetAttribute(attn_kernel, cudaFuncAttributeMaxDynamicSharedMemorySize,
                         ATTN_SMEM_BYTES);
    cudaFuncSetAttribute(gemm_f16, cudaFuncAttributeMaxDynamicSharedMemorySize,
                         GEMM_SMEM_BYTES);
    cudaFuncSetAttribute(gemm_qkv_rope, cudaFuncAttributeMaxDynamicSharedMemorySize,
                         GEMM_SMEM_BYTES);

    const int M = B_ * T_;  // 4096
    float qsc = (1.0f / sqrtf((float)HD)) * 1.4426950408889634f;

    // 0: fused QKV projection + rope + split (384 tiles, one launch)
    gemm_qkv_rope<<<384, 512, GEMM_SMEM_BYTES>>>(
        x, wq, wk, wv, cosb, sinb, Qh, Ql, Kh, Vh, qsc);
    // 1: attention (double-buffered KV)
    attn_kernel<<<dim3(T_ / 64, B_ * NH), 128, ATTN_SMEM_BYTES>>>(
        Qh, Ql, Kh, Vh, Octx);
    // 2: output projection
    gemm_f16<<<dim3(HID / 256, M / 128), 512, GEMM_SMEM_BYTES>>>(
        Octx, wo, (float*)d_out, M, HID, HID);
}

// round 13
// speedup vs baseline: 1.4668x; 1.0516x over previous
#include <cuda_runtime.h>
#include <cuda_fp16.h>
#include <cstdint>
#include <cstddef>
#include <math.h>

// Problem constants
constexpr int B_  = 2;
constexpr int T_  = 2048;
constexpr int HID = 2048;
constexpr int NH  = 16;
constexpr int NKV = 4;
constexpr int HD  = 128;

// ---------------- scratch (static device arrays; no allocation) ----------------
__device__ float   g_Octx[(size_t)B_ * T_ * NH * HD];
__device__ __half  g_Qh[(size_t)B_ * NH  * T_ * HD];
__device__ __half  g_Ql[(size_t)B_ * NH  * T_ * HD];
__device__ __half  g_Kh[(size_t)B_ * NKV * T_ * HD];
__device__ __half  g_Vh[(size_t)B_ * NKV * T_ * HD];
// persistent-kernel work-stealing counters (self-resetting each launch)
__device__ int g_tile_ctr = 0;
__device__ int g_done_ctr = 0;

// ---------------- PTX helpers ----------------
__device__ __forceinline__ uint32_t smem_u32(const void* p) {
    return (uint32_t)__cvta_generic_to_shared(p);
}
__device__ __forceinline__ void ldsm4(uint32_t r[4], const void* p) {
    uint32_t a = smem_u32(p);
    asm volatile("ldmatrix.sync.aligned.m8n8.x4.shared.b16 {%0,%1,%2,%3}, [%4];"
                 : "=r"(r[0]), "=r"(r[1]), "=r"(r[2]), "=r"(r[3]) : "r"(a));
}
__device__ __forceinline__ void ldsm4t(uint32_t r[4], const void* p) {
    uint32_t a = smem_u32(p);
    asm volatile("ldmatrix.sync.aligned.m8n8.x4.trans.shared.b16 {%0,%1,%2,%3}, [%4];"
                 : "=r"(r[0]), "=r"(r[1]), "=r"(r[2]), "=r"(r[3]) : "r"(a));
}
__device__ __forceinline__ void mma_f16(float c[4], const uint32_t a[4], uint32_t b0, uint32_t b1) {
    asm volatile("mma.sync.aligned.m16n8k16.row.col.f32.f16.f16.f32 "
                 "{%0,%1,%2,%3}, {%4,%5,%6,%7}, {%8,%9}, {%0,%1,%2,%3};"
                 : "+f"(c[0]), "+f"(c[1]), "+f"(c[2]), "+f"(c[3])
                 : "r"(a[0]), "r"(a[1]), "r"(a[2]), "r"(a[3]), "r"(b0), "r"(b1));
}
__device__ __forceinline__ void cpasync16(uint32_t saddr, const void* g) {
    asm volatile("cp.async.cg.shared.global [%0], [%1], 16;" :: "r"(saddr), "l"(g));
}
__device__ __forceinline__ void cpcommit() { asm volatile("cp.async.commit_group;"); }
template <int N> __device__ __forceinline__ void cpwait() {
    asm volatile("cp.async.wait_group %0;" :: "n"(N));
}
// fp16 hi/lo split of a float pair
__device__ __forceinline__ void split2h(float a, float b, uint32_t& hv, uint32_t& lv) {
    __half2 h = __floats2half2_rn(a, b);
    float2 f = __half22float2(h);
    __half2 l = __floats2half2_rn(a - f.x, b - f.y);
    hv = *reinterpret_cast<uint32_t*>(&h);
    lv = *reinterpret_cast<uint32_t*>(&l);
}
__device__ __forceinline__ uint32_t cvt2h(float a, float b) {
    __half2 h = __floats2half2_rn(a, b);
    return *reinterpret_cast<uint32_t*>(&h);
}
__device__ __forceinline__ void split_store4h(float4 v, __half* hi, __half* lo) {
    uint32_t h0, l0, h1, l1;
    split2h(v.x, v.y, h0, l0);
    split2h(v.z, v.w, h1, l1);
    *reinterpret_cast<uint2*>(hi) = make_uint2(h0, h1);
    *reinterpret_cast<uint2*>(lo) = make_uint2(l0, l1);
}
__device__ __forceinline__ void cvt_store4h(float4 v, __half* dst) {
    *reinterpret_cast<uint2*>(dst) = make_uint2(cvt2h(v.x, v.y), cvt2h(v.z, v.w));
}

// =====================================================================
// GEMM tile constants: CTA 128x256x32, 512 thr (16 warps 4x4),
// warp tile 32x64, two smem stages, one barrier per k-tile.
// A split into fp16 hi/lo (2 planes); B single fp16 (1 plane).
// =====================================================================
constexpr int SA_ST = 40;    // sA row stride (32+8 halves)
constexpr int SB_ST = 264;   // sB row stride (256+8 halves)
constexpr int SA_SZ = 128 * SA_ST;          // 5120
constexpr int SB_SZ = 32 * SB_ST;           // 8448
constexpr int ST_SZ = 2 * SA_SZ + SB_SZ;    // halves per stage = 18688
constexpr int GEMM_SMEM_BYTES = 2 * ST_SZ * 2;   // 74752 B

constexpr int QKV_TILES = 384;              // 256 Q + 64 K + 64 V
constexpr int QKV_GRID  = 152;              // persistent CTAs (GB300 SM count)

// =====================================================================
// PERSISTENT fused QKV projection + RoPE + scale + fp16 split/convert.
// Work-stealing over 384 equal tiles via atomic counter (self-resetting).
// Q written as hi/lo split; K,V written single fp16.
// =====================================================================
__global__ __launch_bounds__(512, 1) void gemm_qkv_rope(
    const float* __restrict__ A,
    const float* __restrict__ wq, const float* __restrict__ wk, const float* __restrict__ wv,
    const float* __restrict__ cosb, const float* __restrict__ sinb,
    __half* __restrict__ Qh, __half* __restrict__ Ql,
    __half* __restrict__ Kh, __half* __restrict__ Vh,
    float qsc)
{
    extern __shared__ __half gs[];
    __shared__ int s_tile;

    const int tid  = threadIdx.x;
    const int lane = tid & 31;
    const int wid  = tid >> 5;
    const int wm   = (wid >> 2) * 32;
    const int wn   = (wid & 3) * 64;
    const int K = HID;

    for (;;) {
        if (tid == 0) s_tile = atomicAdd(&g_tile_ctr, 1);
        __syncthreads();
        const int tile = s_tile;
        if (tile >= QKV_TILES) break;

        int which, bm, bn;
        if (tile < 256)      { which = 0; bm = tile >> 3;         bn = tile & 7; }
        else if (tile < 320) { which = 1; bm = (tile - 256) >> 1; bn = (tile - 256) & 1; }
        else                 { which = 2; bm = (tile - 320) >> 1; bn = (tile - 320) & 1; }
        const float* Bm = (which == 0) ? wq : (which == 1) ? wk : wv;
        const int N = (which == 0) ? (NH * HD) : (NKV * HD);

        const float* Ab = A + (size_t)bm * 128 * K;
        const float* Bb = Bm + (size_t)bn * 256;

        float acc[2][8][4] = {};
        float4 ra[2], rb[4];

        auto gload = [&](int k0) {
#pragma unroll
            for (int i = 0; i < 2; i++) {
                int idx = i * 512 + tid;
                int r = idx >> 3, c4 = idx & 7;
                ra[i] = *(const float4*)(Ab + (size_t)r * K + k0 + c4 * 4);
            }
#pragma unroll
            for (int i = 0; i < 4; i++) {
                int idx = i * 512 + tid;
                int r = idx >> 6, c4 = idx & 63;
                rb[i] = *(const float4*)(Bb + (size_t)(k0 + r) * N + c4 * 4);
            }
        };
        auto sstore = [&](int s) {
            __half* sA0 = gs + s * ST_SZ;
            __half* sA1 = sA0 + SA_SZ;
            __half* sB0 = sA0 + 2 * SA_SZ;
#pragma unroll
            for (int i = 0; i < 2; i++) {
                int idx = i * 512 + tid;
                int r = idx >> 3, c = (idx & 7) * 4;
                split_store4h(ra[i], sA0 + r * SA_ST + c, sA1 + r * SA_ST + c);
            }
#pragma unroll
            for (int i = 0; i < 4; i++) {
                int idx = i * 512 + tid;
                int r = idx >> 6, c = (idx & 63) * 4;
                cvt_store4h(rb[i], sB0 + r * SB_ST + c);
            }
        };

        gload(0);
        sstore(0);
        __syncthreads();

        const int nk = K / 32;
        for (int kt = 0; kt < nk; kt++) {
            const int s = kt & 1;
            if (kt + 1 < nk) gload((kt + 1) * 32);

            const __half* sA0 = gs + s * ST_SZ;
            const __half* sA1 = sA0 + SA_SZ;
            const __half* sB0 = sA0 + 2 * SA_SZ;

#pragma unroll
            for (int ks = 0; ks < 2; ks++) {
                const int colA = ks * 16 + ((lane >> 4) << 3);
                uint32_t af0[2][4], af1[2][4];
#pragma unroll
                for (int mf = 0; mf < 2; mf++) {
                    int row = wm + mf * 16 + (lane & 15);
                    ldsm4(af0[mf], sA0 + row * SA_ST + colA);
                    ldsm4(af1[mf], sA1 + row * SA_ST + colA);
                }
                const int rowB = ks * 16 + (lane & 15);
#pragma unroll
                for (int nf2 = 0; nf2 < 4; nf2++) {
                    const int colB = wn + nf2 * 16 + ((lane >> 4) << 3);
                    uint32_t bh[4];
                    ldsm4t(bh, sB0 + rowB * SB_ST + colB);
#pragma unroll
                    for (int mf = 0; mf < 2; mf++)
#pragma unroll
                        for (int sub = 0; sub < 2; sub++)
                            mma_f16(acc[mf][nf2 * 2 + sub], af0[mf], bh[sub * 2], bh[sub * 2 + 1]);
#pragma unroll
                    for (int mf = 0; mf < 2; mf++)
#pragma unroll
                        for (int sub = 0; sub < 2; sub++)
                            mma_f16(acc[mf][nf2 * 2 + sub], af1[mf], bh[sub * 2], bh[sub * 2 + 1]);
                }
            }
            if (kt + 1 < nk) sstore(s ^ 1);
            __syncthreads();
        }

        // ---- fused rope + convert epilogue (smem exchange, two 64-row passes) ----
        {
            float* sf = reinterpret_cast<float*>(gs);
            const int H = (which == 0) ? NH : NKV;
            const float scale = (which == 0) ? qsc : 1.0f;
            const int do_rope = (which != 2);

#pragma unroll
            for (int mf = 0; mf < 2; mf++) {
                int rl0 = (wm >> 5) * 16 + (lane >> 2);
#pragma unroll
                for (int nf = 0; nf < 8; nf++) {
                    int col = wn + nf * 8 + (lane & 3) * 2;
                    *(float2*)(sf + rl0 * 264 + col)       = make_float2(acc[mf][nf][0], acc[mf][nf][1]);
                    *(float2*)(sf + (rl0 + 8) * 264 + col) = make_float2(acc[mf][nf][2], acc[mf][nf][3]);
                }
                __syncthreads();
#pragma unroll
                for (int k = 0; k < 16; k++) {
                    int e2 = k * 512 + tid;
                    int rl = e2 >> 7;
                    int c2 = (e2 & 127) * 2;
                    int r  = bm * 128 + (rl >> 4) * 32 + mf * 16 + (rl & 15);
                    int t  = r & (T_ - 1);
                    int b  = r >> 11;
                    int gc = bn * 256 + c2;
                    int h  = gc >> 7;
                    int d  = gc & 127;
                    float2 v = *(float2*)(sf + rl * 264 + c2);
                    float o0, o1;
                    if (do_rope) {
                        int dd = d & 63;
                        float2 cs = *(const float2*)(cosb + t * 64 + dd);
                        float2 sn = *(const float2*)(sinb + t * 64 + dd);
                        float2 w  = *(float2*)(sf + rl * 264 + (c2 ^ 64));
                        if (d < 64) { o0 = v.x * cs.x - w.x * sn.x; o1 = v.y * cs.y - w.y * sn.y; }
                        else        { o0 = v.x * cs.x + w.x * sn.x; o1 = v.y * cs.y + w.y * sn.y; }
                    } else { o0 = v.x; o1 = v.y; }
                    o0 *= scale; o1 *= scale;
                    size_t di = (((size_t)(b * H + h)) * T_ + t) * HD + d;
                    if (which == 0) {
                        uint32_t hv, lv;
                        split2h(o0, o1, hv, lv);
                        *(uint32_t*)(Qh + di) = hv;
                        *(uint32_t*)(Ql + di) = lv;
                    } else if (which == 1) {
                        *(uint32_t*)(Kh + di) = cvt2h(o0, o1);
                    } else {
                        *(uint32_t*)(Vh + di) = cvt2h(o0, o1);
                    }
                }
                __syncthreads();
            }
        }
    }

    // self-reset counters for the next (graph-replayed) launch
    if (tid == 0) {
        int d = atomicAdd(&g_done_ctr, 1);
        if (d == (int)gridDim.x - 1) {
            g_tile_ctr = 0;
            g_done_ctr = 0;
            __threadfence();
        }
    }
}

// =====================================================================
// Output-projection GEMM (fp32 in/out): A split fp16, B single fp16.
// =====================================================================
__global__ __launch_bounds__(512, 1) void gemm_f16(
    const float* __restrict__ A, const float* __restrict__ Bm, float* __restrict__ C,
    int M, int N, int K)
{
    extern __shared__ __half gs[];

    const int tid  = threadIdx.x;
    const int lane = tid & 31;
    const int wid  = tid >> 5;
    const int bm   = blockIdx.y, bn = blockIdx.x;
    const int wm   = (wid >> 2) * 32;
    const int wn   = (wid & 3) * 64;

    const float* Ab = A + (size_t)bm * 128 * K;
    const float* Bb = Bm + (size_t)bn * 256;

    float acc[2][8][4] = {};
    float4 ra[2], rb[4];

    auto gload = [&](int k0) {
#pragma unroll
        for (int i = 0; i < 2; i++) {
            int idx = i * 512 + tid;
            int r = idx >> 3, c4 = idx & 7;
            ra[i] = *(const float4*)(Ab + (size_t)r * K + k0 + c4 * 4);
        }
#pragma unroll
        for (int i = 0; i < 4; i++) {
            int idx = i * 512 + tid;
            int r = idx >> 6, c4 = idx & 63;
            rb[i] = *(const float4*)(Bb + (size_t)(k0 + r) * N + c4 * 4);
        }
    };
    auto sstore = [&](int s) {
        __half* sA0 = gs + s * ST_SZ;
        __half* sA1 = sA0 + SA_SZ;
        __half* sB0 = sA0 + 2 * SA_SZ;
#pragma unroll
        for (int i = 0; i < 2; i++) {
            int idx = i * 512 + tid;
            int r = idx >> 3, c = (idx & 7) * 4;
            split_store4h(ra[i], sA0 + r * SA_ST + c, sA1 + r * SA_ST + c);
        }
#pragma unroll
        for (int i = 0; i < 4; i++) {
            int idx = i * 512 + tid;
            int r = idx >> 6, c = (idx & 63) * 4;
            cvt_store4h(rb[i], sB0 + r * SB_ST + c);
        }
    };

    gload(0);
    sstore(0);
    __syncthreads();

    const int nk = K / 32;
    for (int kt = 0; kt < nk; kt++) {
        const int s = kt & 1;
        if (kt + 1 < nk) gload((kt + 1) * 32);

        const __half* sA0 = gs + s * ST_SZ;
        const __half* sA1 = sA0 + SA_SZ;
        const __half* sB0 = sA0 + 2 * SA_SZ;

#pragma unroll
        for (int ks = 0; ks < 2; ks++) {
            const int colA = ks * 16 + ((lane >> 4) << 3);
            uint32_t af0[2][4], af1[2][4];
#pragma unroll
            for (int mf = 0; mf < 2; mf++) {
                int row = wm + mf * 16 + (lane & 15);
                ldsm4(af0[mf], sA0 + row * SA_ST + colA);
                ldsm4(af1[mf], sA1 + row * SA_ST + colA);
            }
            const int rowB = ks * 16 + (lane & 15);
#pragma unroll
            for (int nf2 = 0; nf2 < 4; nf2++) {
                const int colB = wn + nf2 * 16 + ((lane >> 4) << 3);
                uint32_t bh[4];
                ldsm4t(bh, sB0 + rowB * SB_ST + colB);
#pragma unroll
                for (int mf = 0; mf < 2; mf++)
#pragma unroll
                    for (int sub = 0; sub < 2; sub++)
                        mma_f16(acc[mf][nf2 * 2 + sub], af0[mf], bh[sub * 2], bh[sub * 2 + 1]);
#pragma unroll
                for (int mf = 0; mf < 2; mf++)
#pragma unroll
                    for (int sub = 0; sub < 2; sub++)
                        mma_f16(acc[mf][nf2 * 2 + sub], af1[mf], bh[sub * 2], bh[sub * 2 + 1]);
            }
        }
        if (kt + 1 < nk) sstore(s ^ 1);
        __syncthreads();
    }

#pragma unroll
    for (int mf = 0; mf < 2; mf++) {
        int r0 = bm * 128 + wm + mf * 16 + (lane >> 2);
#pragma unroll
        for (int nf = 0; nf < 8; nf++) {
            int c = bn * 256 + wn + nf * 8 + (lane & 3) * 2;
            *(float2*)(C + (size_t)r0 * N + c)       = make_float2(acc[mf][nf][0], acc[mf][nf][1]);
            *(float2*)(C + (size_t)(r0 + 8) * N + c) = make_float2(acc[mf][nf][2], acc[mf][nf][3]);
        }
    }
}

// =====================================================================
// Flash attention (causal, GQA). Br=64 (4 warps x 16 rows), Bc=64.
// Q split fp16 hi/lo; K, V, and P single fp16. Double-buffered KV,
// one barrier per tile. 2 CTAs per SM.
// =====================================================================
constexpr int AS       = 136;
constexpr int Q_H_OFF  = 0;
constexpr int Q_L_OFF  = 64 * AS;
constexpr int KV_STAGE = 2 * 64 * AS;
constexpr int KV_BASE  = 2 * 64 * AS;
constexpr int ATTN_SMEM_BYTES = (2 * 64 * AS + 2 * KV_STAGE) * 2;   // 104448

__global__ __launch_bounds__(128, 2) void attn_kernel(
    const __half* __restrict__ Qh, const __half* __restrict__ Ql,
    const __half* __restrict__ Kh, const __half* __restrict__ Vh,
    float* __restrict__ O)
{
    extern __shared__ __half sm[];
    const int tid  = threadIdx.x;
    const int lane = tid & 31;
    const int wid  = tid >> 5;
    const int bh   = blockIdx.y;
    const int b    = bh >> 4, h = bh & 15;
    const int qi   = (int)gridDim.x - 1 - (int)blockIdx.x;
    const int qbase = qi * 64;
    const int kvi  = b * NKV + (h >> 2);

    const __half* qh_g = Qh + ((size_t)bh * T_ + qbase) * HD;
    const __half* ql_g = Ql + ((size_t)bh * T_ + qbase) * HD;
    const __half* k_g  = Kh + (size_t)kvi * T_ * HD;
    const __half* v_g  = Vh + (size_t)kvi * T_ * HD;

#pragma unroll
    for (int i = 0; i < 8; i++) {
        int c = i * 128 + tid;
        int split = c >> 9, cc = c & 511;
        int row = cc >> 3, ch = cc & 7;
        const __half* src = (split ? ql_g : qh_g) + row * HD + ch * 16;
        cpasync16(smem_u32(sm + (split ? Q_L_OFF : Q_H_OFF) + row * AS + ch * 16), src);
        cpasync16(smem_u32(sm + (split ? Q_L_OFF : Q_H_OFF) + row * AS + ch * 16 + 8),
                  src + 8);
    }

    auto loadKV = [&](int j, int st) {
        size_t gb = (size_t)j * 64 * HD;
        const int koff = KV_BASE + st * KV_STAGE;
        const int voff = koff + 64 * AS;
#pragma unroll
        for (int i = 0; i < 8; i++) {
            int c = i * 128 + tid;
            int which = c >> 9, cc = c & 511;
            int row = cc >> 3, ch = cc & 7;
            const __half* src = (which ? v_g : k_g) + gb + row * HD + ch * 16;
            int off = (which ? voff : koff) + row * AS + ch * 16;
            cpasync16(smem_u32(sm + off), src);
            cpasync16(smem_u32(sm + off + 8), src + 8);
        }
    };
    loadKV(0, 0);
    cpcommit();

    float m0 = -1e30f, m1 = -1e30f, l0 = 0.f, l1 = 0.f;
    float o[16][4];
#pragma unroll
    for (int i = 0; i < 16; i++)
#pragma unroll
        for (int j = 0; j < 4; j++) o[i][j] = 0.f;

    const int nj = qi + 1;
    const int rowbase = qbase + wid * 16;

    for (int j = 0; j < nj; j++) {
        const int s = j & 1;
        cpwait<0>();
        __syncthreads();
        if (j + 1 < nj) { loadKV(j + 1, s ^ 1); cpcommit(); }

        const int kb = KV_BASE + s * KV_STAGE;
        const int vb = kb + 64 * AS;

        // ---- S = Q K^T (exp2 domain): (Qh+Ql) x Kh ----
        float sacc[8][4];
#pragma unroll
        for (int i = 0; i < 8; i++)
#pragma unroll
            for (int jj = 0; jj < 4; jj++) sacc[i][jj] = 0.f;

#pragma unroll
        for (int ks = 0; ks < 8; ks++) {
            uint32_t qa[2][4];
            {
                int row = wid * 16 + (lane & 15);
                int col = ks * 16 + ((lane >> 4) << 3);
                ldsm4(qa[0], sm + Q_H_OFF + row * AS + col);
                ldsm4(qa[1], sm + Q_L_OFF + row * AS + col);
            }
#pragma unroll
            for (int nf2 = 0; nf2 < 4; nf2++) {
                uint32_t kh4[4];
                int krow = nf2 * 16 + (lane & 15);
                int kcol = ks * 16 + ((lane >> 4) << 3);
                ldsm4(kh4, sm + kb + krow * AS + kcol);
                mma_f16(sacc[2 * nf2],     qa[0], kh4[0], kh4[2]);
                mma_f16(sacc[2 * nf2 + 1], qa[0], kh4[1], kh4[3]);
                mma_f16(sacc[2 * nf2],     qa[1], kh4[0], kh4[2]);
                mma_f16(sacc[2 * nf2 + 1], qa[1], kh4[1], kh4[3]);
            }
        }

        // ---- causal mask (diagonal tile only) ----
        const int kvb = j * 64;
        if (kvb + 63 > rowbase) {
            int r0 = rowbase + (lane >> 2), r1 = r0 + 8;
#pragma unroll
            for (int nf = 0; nf < 8; nf++) {
                int c0 = kvb + nf * 8 + (lane & 3) * 2;
                if (c0 > r0)     sacc[nf][0] = -1e30f;
                if (c0 + 1 > r0) sacc[nf][1] = -1e30f;
                if (c0 > r1)     sacc[nf][2] = -1e30f;
                if (c0 + 1 > r1) sacc[nf][3] = -1e30f;
            }
        }

        // ---- online softmax (base 2) ----
        float rm0 = -1e30f, rm1 = -1e30f;
#pragma unroll
        for (int nf = 0; nf < 8; nf++) {
            rm0 = fmaxf(rm0, fmaxf(sacc[nf][0], sacc[nf][1]));
            rm1 = fmaxf(rm1, fmaxf(sacc[nf][2], sacc[nf][3]));
        }
        rm0 = fmaxf(rm0, __shfl_xor_sync(0xffffffffu, rm0, 1));
        rm0 = fmaxf(rm0, __shfl_xor_sync(0xffffffffu, rm0, 2));
        rm1 = fmaxf(rm1, __shfl_xor_sync(0xffffffffu, rm1, 1));
        rm1 = fmaxf(rm1, __shfl_xor_sync(0xffffffffu, rm1, 2));
        float mn0 = fmaxf(m0, rm0), mn1 = fmaxf(m1, rm1);
        float corr0 = exp2f(m0 - mn0), corr1 = exp2f(m1 - mn1);
        m0 = mn0; m1 = mn1;

        float rs0 = 0.f, rs1 = 0.f;
#pragma unroll
        for (int nf = 0; nf < 8; nf++) {
            float p0 = exp2f(sacc[nf][0] - mn0);
            float p1 = exp2f(sacc[nf][1] - mn0);
            float p2 = exp2f(sacc[nf][2] - mn1);
            float p3 = exp2f(sacc[nf][3] - mn1);
            sacc[nf][0] = p0; sacc[nf][1] = p1; sacc[nf][2] = p2; sacc[nf][3] = p3;
            rs0 += p0 + p1; rs1 += p2 + p3;
        }
        l0 = l0 * corr0 + rs0;
        l1 = l1 * corr1 + rs1;
        if (__any_sync(0xffffffffu, (corr0 != 1.f) || (corr1 != 1.f))) {
#pragma unroll
            for (int df = 0; df < 16; df++) {
                o[df][0] *= corr0; o[df][1] *= corr0;
                o[df][2] *= corr1; o[df][3] *= corr1;
            }
        }

        // ---- pack P into single-fp16 A-fragments ----
        uint32_t ph[4][4];
#pragma unroll
        for (int kk = 0; kk < 4; kk++) {
            const float* A0 = sacc[2 * kk];
            const float* A1 = sacc[2 * kk + 1];
            ph[kk][0] = cvt2h(A0[0], A0[1]);
            ph[kk][1] = cvt2h(A0[2], A0[3]);
            ph[kk][2] = cvt2h(A1[0], A1[1]);
            ph[kk][3] = cvt2h(A1[2], A1[3]);
        }

        // ---- O += P V : single-plane P x Vh ----
#pragma unroll
        for (int kk = 0; kk < 4; kk++) {
#pragma unroll
            for (int nf2 = 0; nf2 < 8; nf2++) {
                uint32_t vh4[4];
                int vrow = kk * 16 + (lane & 15);
                int vcol = nf2 * 16 + ((lane >> 4) << 3);
                ldsm4t(vh4, sm + vb + vrow * AS + vcol);
                mma_f16(o[2 * nf2],     ph[kk], vh4[0], vh4[1]);
                mma_f16(o[2 * nf2 + 1], ph[kk], vh4[2], vh4[3]);
            }
        }
    }

    // ---- finalize ----
    l0 += __shfl_xor_sync(0xffffffffu, l0, 1);
    l0 += __shfl_xor_sync(0xffffffffu, l0, 2);
    l1 += __shfl_xor_sync(0xffffffffu, l1, 1);
    l1 += __shfl_xor_sync(0xffffffffu, l1, 2);
    float inv0 = 1.f / l0, inv1 = 1.f / l1;

    int r0 = rowbase + (lane >> 2);
    size_t base0 = ((size_t)b * T_ + r0) * HID + h * HD + (lane & 3) * 2;
    size_t base1 = base0 + (size_t)8 * HID;
#pragma unroll
    for (int df = 0; df < 16; df++) {
        *(float2*)(O + base0 + df * 8) = make_float2(o[df][0] * inv0, o[df][1] * inv0);
        *(float2*)(O + base1 + df * 8) = make_float2(o[df][2] * inv1, o[df][3] * inv1);
    }
}

// =====================================================================
// host launcher
// =====================================================================
extern "C" void kernel_launch(void* const* d_in, const int* in_sizes, int n_in,
                              void* d_out, int out_size)
{
    const float* x    = (const float*)d_in[0];
    const float* cosb = (const float*)d_in[1];
    const float* sinb = (const float*)d_in[2];
    const float* wq   = (const float*)d_in[3];
    const float* wk   = (const float*)d_in[4];
    const float* wv   = (const float*)d_in[5];
    const float* wo   = (const float*)d_in[6];

    float* Octx;
    __half *Qh, *Ql, *Kh, *Vh;
    cudaGetSymbolAddress((void**)&Octx, g_Octx);
    cudaGetSymbolAddress((void**)&Qh, g_Qh);
    cudaGetSymbolAddress((void**)&Ql, g_Ql);
    cudaGetSymbolAddress((void**)&Kh, g_Kh);
    cudaGetSymbolAddress((void**)&Vh, g_Vh);

    cudaFuncSetAttribute(attn_kernel, cudaFuncAttributeMaxDynamicSharedMemorySize,
                         ATTN_SMEM_BYTES);
    cudaFuncSetAttribute(gemm_f16, cudaFuncAttributeMaxDynamicSharedMemorySize,
                         GEMM_SMEM_BYTES);
    cudaFuncSetAttribute(gemm_qkv_rope, cudaFuncAttributeMaxDynamicSharedMemorySize,
                         GEMM_SMEM_BYTES);

    const int M = B_ * T_;  // 4096
    float qsc = (1.0f / sqrtf((float)HD)) * 1.4426950408889634f;

    // 0: persistent fused QKV projection + rope + split (work-stealing)
    gemm_qkv_rope<<<QKV_GRID, 512, GEMM_SMEM_BYTES>>>(
        x, wq, wk, wv, cosb, sinb, Qh, Ql, Kh, Vh, qsc);
    // 1: attention (double-buffered KV, single-fp16 P)
    attn_kernel<<<dim3(T_ / 64, B_ * NH), 128, ATTN_SMEM_BYTES>>>(
        Qh, Ql, Kh, Vh, Octx);
    // 2: output projection
    gemm_f16<<<dim3(HID / 256, M / 128), 512, GEMM_SMEM_BYTES>>>(
        Octx, wo, (float*)d_out, M, HID, HID);
}

// round 14
// speedup vs baseline: 1.6681x; 1.1373x over previous
#include <cuda_runtime.h>
#include <cuda_fp16.h>
#include <cstdint>
#include <cstddef>
#include <math.h>

// Problem constants
constexpr int B_  = 2;
constexpr int T_  = 2048;
constexpr int HID = 2048;
constexpr int NH  = 16;
constexpr int NKV = 4;
constexpr int HD  = 128;

// ---------------- scratch (static device arrays; no allocation) ----------------
__device__ __half  g_Octx[(size_t)B_ * T_ * NH * HD];
__device__ __half  g_Qh[(size_t)B_ * NH  * T_ * HD];
__device__ __half  g_Ql[(size_t)B_ * NH  * T_ * HD];
__device__ __half  g_Kh[(size_t)B_ * NKV * T_ * HD];
__device__ __half  g_Vh[(size_t)B_ * NKV * T_ * HD];
// persistent-kernel work-stealing counters (self-resetting each launch)
__device__ int g_tile_ctr = 0;
__device__ int g_done_ctr = 0;

// ---------------- PTX helpers ----------------
__device__ __forceinline__ uint32_t smem_u32(const void* p) {
    return (uint32_t)__cvta_generic_to_shared(p);
}
__device__ __forceinline__ void ldsm4(uint32_t r[4], const void* p) {
    uint32_t a = smem_u32(p);
    asm volatile("ldmatrix.sync.aligned.m8n8.x4.shared.b16 {%0,%1,%2,%3}, [%4];"
                 : "=r"(r[0]), "=r"(r[1]), "=r"(r[2]), "=r"(r[3]) : "r"(a));
}
__device__ __forceinline__ void ldsm4t(uint32_t r[4], const void* p) {
    uint32_t a = smem_u32(p);
    asm volatile("ldmatrix.sync.aligned.m8n8.x4.trans.shared.b16 {%0,%1,%2,%3}, [%4];"
                 : "=r"(r[0]), "=r"(r[1]), "=r"(r[2]), "=r"(r[3]) : "r"(a));
}
__device__ __forceinline__ void mma_f16(float c[4], const uint32_t a[4], uint32_t b0, uint32_t b1) {
    asm volatile("mma.sync.aligned.m16n8k16.row.col.f32.f16.f16.f32 "
                 "{%0,%1,%2,%3}, {%4,%5,%6,%7}, {%8,%9}, {%0,%1,%2,%3};"
                 : "+f"(c[0]), "+f"(c[1]), "+f"(c[2]), "+f"(c[3])
                 : "r"(a[0]), "r"(a[1]), "r"(a[2]), "r"(a[3]), "r"(b0), "r"(b1));
}
__device__ __forceinline__ void cpasync16(uint32_t saddr, const void* g) {
    asm volatile("cp.async.cg.shared.global [%0], [%1], 16;" :: "r"(saddr), "l"(g));
}
__device__ __forceinline__ void cpcommit() { asm volatile("cp.async.commit_group;"); }
template <int N> __device__ __forceinline__ void cpwait() {
    asm volatile("cp.async.wait_group %0;" :: "n"(N));
}
// fp16 hi/lo split of a float pair
__device__ __forceinline__ void split2h(float a, float b, uint32_t& hv, uint32_t& lv) {
    __half2 h = __floats2half2_rn(a, b);
    float2 f = __half22float2(h);
    __half2 l = __floats2half2_rn(a - f.x, b - f.y);
    hv = *reinterpret_cast<uint32_t*>(&h);
    lv = *reinterpret_cast<uint32_t*>(&l);
}
__device__ __forceinline__ uint32_t cvt2h(float a, float b) {
    __half2 h = __floats2half2_rn(a, b);
    return *reinterpret_cast<uint32_t*>(&h);
}
__device__ __forceinline__ void split_store4h(float4 v, __half* hi, __half* lo) {
    uint32_t h0, l0, h1, l1;
    split2h(v.x, v.y, h0, l0);
    split2h(v.z, v.w, h1, l1);
    *reinterpret_cast<uint2*>(hi) = make_uint2(h0, h1);
    *reinterpret_cast<uint2*>(lo) = make_uint2(l0, l1);
}
__device__ __forceinline__ void cvt_store4h(float4 v, __half* dst) {
    *reinterpret_cast<uint2*>(dst) = make_uint2(cvt2h(v.x, v.y), cvt2h(v.z, v.w));
}

// =====================================================================
// GEMM tile constants (QKV kernel): CTA 128x256x32, 512 thr (16 warps),
// warp tile 32x64. A split fp16 hi/lo (2 planes); B single fp16.
// =====================================================================
constexpr int SA_ST = 40;    // sA row stride (32+8 halves)
constexpr int SB_ST = 264;   // sB row stride (256+8 halves)
constexpr int SA_SZ = 128 * SA_ST;          // 5120
constexpr int SB_SZ = 32 * SB_ST;           // 8448
constexpr int ST_SZ = 2 * SA_SZ + SB_SZ;    // halves per stage = 18688
constexpr int GEMM_SMEM_BYTES = 2 * ST_SZ * 2;   // 74752 B

constexpr int QKV_TILES = 384;              // 256 Q + 64 K + 64 V
constexpr int QKV_GRID  = 152;

// ctx GEMM (single-plane A): stage = A(5120) + B(8448) halves
constexpr int CT_SZ = SA_SZ + SB_SZ;              // 13568
constexpr int CTX_SMEM_BYTES = 2 * CT_SZ * 2;     // 54272 B

// =====================================================================
// PERSISTENT fused QKV projection + RoPE + scale + fp16 split/convert.
// =====================================================================
__global__ __launch_bounds__(512, 1) void gemm_qkv_rope(
    const float* __restrict__ A,
    const float* __restrict__ wq, const float* __restrict__ wk, const float* __restrict__ wv,
    const float* __restrict__ cosb, const float* __restrict__ sinb,
    __half* __restrict__ Qh, __half* __restrict__ Ql,
    __half* __restrict__ Kh, __half* __restrict__ Vh,
    float qsc)
{
    extern __shared__ __half gs[];
    __shared__ int s_tile;

    const int tid  = threadIdx.x;
    const int lane = tid & 31;
    const int wid  = tid >> 5;
    const int wm   = (wid >> 2) * 32;
    const int wn   = (wid & 3) * 64;
    const int K = HID;

    for (;;) {
        if (tid == 0) s_tile = atomicAdd(&g_tile_ctr, 1);
        __syncthreads();
        const int tile = s_tile;
        if (tile >= QKV_TILES) break;

        int which, bm, bn;
        if (tile < 256)      { which = 0; bm = tile >> 3;         bn = tile & 7; }
        else if (tile < 320) { which = 1; bm = (tile - 256) >> 1; bn = (tile - 256) & 1; }
        else                 { which = 2; bm = (tile - 320) >> 1; bn = (tile - 320) & 1; }
        const float* Bm = (which == 0) ? wq : (which == 1) ? wk : wv;
        const int N = (which == 0) ? (NH * HD) : (NKV * HD);

        const float* Ab = A + (size_t)bm * 128 * K;
        const float* Bb = Bm + (size_t)bn * 256;

        float acc[2][8][4] = {};
        float4 ra[2], rb[4];

        auto gload = [&](int k0) {
#pragma unroll
            for (int i = 0; i < 2; i++) {
                int idx = i * 512 + tid;
                int r = idx >> 3, c4 = idx & 7;
                ra[i] = *(const float4*)(Ab + (size_t)r * K + k0 + c4 * 4);
            }
#pragma unroll
            for (int i = 0; i < 4; i++) {
                int idx = i * 512 + tid;
                int r = idx >> 6, c4 = idx & 63;
                rb[i] = *(const float4*)(Bb + (size_t)(k0 + r) * N + c4 * 4);
            }
        };
        auto sstore = [&](int s) {
            __half* sA0 = gs + s * ST_SZ;
            __half* sA1 = sA0 + SA_SZ;
            __half* sB0 = sA0 + 2 * SA_SZ;
#pragma unroll
            for (int i = 0; i < 2; i++) {
                int idx = i * 512 + tid;
                int r = idx >> 3, c = (idx & 7) * 4;
                split_store4h(ra[i], sA0 + r * SA_ST + c, sA1 + r * SA_ST + c);
            }
#pragma unroll
            for (int i = 0; i < 4; i++) {
                int idx = i * 512 + tid;
                int r = idx >> 6, c = (idx & 63) * 4;
                cvt_store4h(rb[i], sB0 + r * SB_ST + c);
            }
        };

        gload(0);
        sstore(0);
        __syncthreads();

        const int nk = K / 32;
        for (int kt = 0; kt < nk; kt++) {
            const int s = kt & 1;
            if (kt + 1 < nk) gload((kt + 1) * 32);

            const __half* sA0 = gs + s * ST_SZ;
            const __half* sA1 = sA0 + SA_SZ;
            const __half* sB0 = sA0 + 2 * SA_SZ;

#pragma unroll
            for (int ks = 0; ks < 2; ks++) {
                const int colA = ks * 16 + ((lane >> 4) << 3);
                uint32_t af0[2][4], af1[2][4];
#pragma unroll
                for (int mf = 0; mf < 2; mf++) {
                    int row = wm + mf * 16 + (lane & 15);
                    ldsm4(af0[mf], sA0 + row * SA_ST + colA);
                    ldsm4(af1[mf], sA1 + row * SA_ST + colA);
                }
                const int rowB = ks * 16 + (lane & 15);
#pragma unroll
                for (int nf2 = 0; nf2 < 4; nf2++) {
                    const int colB = wn + nf2 * 16 + ((lane >> 4) << 3);
                    uint32_t bh[4];
                    ldsm4t(bh, sB0 + rowB * SB_ST + colB);
#pragma unroll
                    for (int mf = 0; mf < 2; mf++)
#pragma unroll
                        for (int sub = 0; sub < 2; sub++)
                            mma_f16(acc[mf][nf2 * 2 + sub], af0[mf], bh[sub * 2], bh[sub * 2 + 1]);
#pragma unroll
                    for (int mf = 0; mf < 2; mf++)
#pragma unroll
                        for (int sub = 0; sub < 2; sub++)
                            mma_f16(acc[mf][nf2 * 2 + sub], af1[mf], bh[sub * 2], bh[sub * 2 + 1]);
                }
            }
            if (kt + 1 < nk) sstore(s ^ 1);
            __syncthreads();
        }

        // ---- fused rope + convert epilogue ----
        {
            float* sf = reinterpret_cast<float*>(gs);
            const int H = (which == 0) ? NH : NKV;
            const float scale = (which == 0) ? qsc : 1.0f;
            const int do_rope = (which != 2);

#pragma unroll
            for (int mf = 0; mf < 2; mf++) {
                int rl0 = (wm >> 5) * 16 + (lane >> 2);
#pragma unroll
                for (int nf = 0; nf < 8; nf++) {
                    int col = wn + nf * 8 + (lane & 3) * 2;
                    *(float2*)(sf + rl0 * 264 + col)       = make_float2(acc[mf][nf][0], acc[mf][nf][1]);
                    *(float2*)(sf + (rl0 + 8) * 264 + col) = make_float2(acc[mf][nf][2], acc[mf][nf][3]);
                }
                __syncthreads();
#pragma unroll
                for (int k = 0; k < 16; k++) {
                    int e2 = k * 512 + tid;
                    int rl = e2 >> 7;
                    int c2 = (e2 & 127) * 2;
                    int r  = bm * 128 + (rl >> 4) * 32 + mf * 16 + (rl & 15);
                    int t  = r & (T_ - 1);
                    int b  = r >> 11;
                    int gc = bn * 256 + c2;
                    int h  = gc >> 7;
                    int d  = gc & 127;
                    float2 v = *(float2*)(sf + rl * 264 + c2);
                    float o0, o1;
                    if (do_rope) {
                        int dd = d & 63;
                        float2 cs = *(const float2*)(cosb + t * 64 + dd);
                        float2 sn = *(const float2*)(sinb + t * 64 + dd);
                        float2 w  = *(float2*)(sf + rl * 264 + (c2 ^ 64));
                        if (d < 64) { o0 = v.x * cs.x - w.x * sn.x; o1 = v.y * cs.y - w.y * sn.y; }
                        else        { o0 = v.x * cs.x + w.x * sn.x; o1 = v.y * cs.y + w.y * sn.y; }
                    } else { o0 = v.x; o1 = v.y; }
                    o0 *= scale; o1 *= scale;
                    size_t di = (((size_t)(b * H + h)) * T_ + t) * HD + d;
                    if (which == 0) {
                        uint32_t hv, lv;
                        split2h(o0, o1, hv, lv);
                        *(uint32_t*)(Qh + di) = hv;
                        *(uint32_t*)(Ql + di) = lv;
                    } else if (which == 1) {
                        *(uint32_t*)(Kh + di) = cvt2h(o0, o1);
                    } else {
                        *(uint32_t*)(Vh + di) = cvt2h(o0, o1);
                    }
                }
                __syncthreads();
            }
        }
    }

    if (tid == 0) {
        int d = atomicAdd(&g_done_ctr, 1);
        if (d == (int)gridDim.x - 1) {
            g_tile_ctr = 0;
            g_done_ctr = 0;
            __threadfence();
        }
    }
}

// =====================================================================
// Output-projection GEMM: A is fp16 context (direct cp.async, single
// plane), B fp32 weights converted inline to fp16, fp32 out.
// CTA 128x256x32, 512 thr, warp tile 32x64.
// =====================================================================
__global__ __launch_bounds__(512, 1) void gemm_ctx(
    const __half* __restrict__ A, const float* __restrict__ Bm, float* __restrict__ C,
    int M, int N, int K)
{
    extern __shared__ __half gs[];

    const int tid  = threadIdx.x;
    const int lane = tid & 31;
    const int wid  = tid >> 5;
    const int bm   = blockIdx.y, bn = blockIdx.x;
    const int wm   = (wid >> 2) * 32;
    const int wn   = (wid & 3) * 64;

    const __half* Ab = A + (size_t)bm * 128 * K;
    const float*  Bb = Bm + (size_t)bn * 256;

    float acc[2][8][4] = {};
    float4 rb[4];

    auto gloadA = [&](int k0, int s) {
        __half* sA0 = gs + s * CT_SZ;
        int r = tid >> 2, ch = (tid & 3) * 8;       // 512 thr: 128 rows x 4 chunks
        cpasync16(smem_u32(sA0 + r * SA_ST + ch), Ab + (size_t)r * K + k0 + ch);
    };
    auto gloadB = [&](int k0) {
#pragma unroll
        for (int i = 0; i < 4; i++) {
            int idx = i * 512 + tid;
            int r = idx >> 6, c4 = idx & 63;
            rb[i] = *(const float4*)(Bb + (size_t)(k0 + r) * N + c4 * 4);
        }
    };
    auto sstoreB = [&](int s) {
        __half* sB0 = gs + s * CT_SZ + SA_SZ;
#pragma unroll
        for (int i = 0; i < 4; i++) {
            int idx = i * 512 + tid;
            int r = idx >> 6, c = (idx & 63) * 4;
            cvt_store4h(rb[i], sB0 + r * SB_ST + c);
        }
    };

    gloadA(0, 0);
    cpcommit();
    gloadB(0);
    sstoreB(0);
    cpwait<0>();
    __syncthreads();

    const int nk = K / 32;
    for (int kt = 0; kt < nk; kt++) {
        const int s = kt & 1;
        if (kt + 1 < nk) {
            gloadA((kt + 1) * 32, s ^ 1);
            cpcommit();
            gloadB((kt + 1) * 32);
        }

        const __half* sA0 = gs + s * CT_SZ;
        const __half* sB0 = sA0 + SA_SZ;

#pragma unroll
        for (int ks = 0; ks < 2; ks++) {
            const int colA = ks * 16 + ((lane >> 4) << 3);
            uint32_t af0[2][4];
#pragma unroll
            for (int mf = 0; mf < 2; mf++) {
                int row = wm + mf * 16 + (lane & 15);
                ldsm4(af0[mf], sA0 + row * SA_ST + colA);
            }
            const int rowB = ks * 16 + (lane & 15);
#pragma unroll
            for (int nf2 = 0; nf2 < 4; nf2++) {
                const int colB = wn + nf2 * 16 + ((lane >> 4) << 3);
                uint32_t bh[4];
                ldsm4t(bh, sB0 + rowB * SB_ST + colB);
#pragma unroll
                for (int mf = 0; mf < 2; mf++)
#pragma unroll
                    for (int sub = 0; sub < 2; sub++)
                        mma_f16(acc[mf][nf2 * 2 + sub], af0[mf], bh[sub * 2], bh[sub * 2 + 1]);
            }
        }
        if (kt + 1 < nk) sstoreB(s ^ 1);
        cpwait<0>();
        __syncthreads();
    }

#pragma unroll
    for (int mf = 0; mf < 2; mf++) {
        int r0 = bm * 128 + wm + mf * 16 + (lane >> 2);
#pragma unroll
        for (int nf = 0; nf < 8; nf++) {
            int c = bn * 256 + wn + nf * 8 + (lane & 3) * 2;
            *(float2*)(C + (size_t)r0 * N + c)       = make_float2(acc[mf][nf][0], acc[mf][nf][1]);
            *(float2*)(C + (size_t)(r0 + 8) * N + c) = make_float2(acc[mf][nf][2], acc[mf][nf][3]);
        }
    }
}

// =====================================================================
// Flash attention (causal, GQA). Br=64 (4 warps x 16 rows), Bc=64.
// Q split fp16 hi/lo; K, V, P single fp16. Output: single fp16 context.
// Double-buffered KV, one barrier per tile. 2 CTAs per SM.
// =====================================================================
constexpr int AS       = 136;
constexpr int Q_H_OFF  = 0;
constexpr int Q_L_OFF  = 64 * AS;
constexpr int KV_STAGE = 2 * 64 * AS;
constexpr int KV_BASE  = 2 * 64 * AS;
constexpr int ATTN_SMEM_BYTES = (2 * 64 * AS + 2 * KV_STAGE) * 2;   // 104448

__global__ __launch_bounds__(128, 2) void attn_kernel(
    const __half* __restrict__ Qh, const __half* __restrict__ Ql,
    const __half* __restrict__ Kh, const __half* __restrict__ Vh,
    __half* __restrict__ O)
{
    extern __shared__ __half sm[];
    const int tid  = threadIdx.x;
    const int lane = tid & 31;
    const int wid  = tid >> 5;
    const int bh   = blockIdx.y;
    const int b    = bh >> 4, h = bh & 15;
    const int qi   = (int)gridDim.x - 1 - (int)blockIdx.x;
    const int qbase = qi * 64;
    const int kvi  = b * NKV + (h >> 2);

    const __half* qh_g = Qh + ((size_t)bh * T_ + qbase) * HD;
    const __half* ql_g = Ql + ((size_t)bh * T_ + qbase) * HD;
    const __half* k_g  = Kh + (size_t)kvi * T_ * HD;
    const __half* v_g  = Vh + (size_t)kvi * T_ * HD;

#pragma unroll
    for (int i = 0; i < 8; i++) {
        int c = i * 128 + tid;
        int split = c >> 9, cc = c & 511;
        int row = cc >> 3, ch = cc & 7;
        const __half* src = (split ? ql_g : qh_g) + row * HD + ch * 16;
        cpasync16(smem_u32(sm + (split ? Q_L_OFF : Q_H_OFF) + row * AS + ch * 16), src);
        cpasync16(smem_u32(sm + (split ? Q_L_OFF : Q_H_OFF) + row * AS + ch * 16 + 8),
                  src + 8);
    }

    auto loadKV = [&](int j, int st) {
        size_t gb = (size_t)j * 64 * HD;
        const int koff = KV_BASE + st * KV_STAGE;
        const int voff = koff + 64 * AS;
#pragma unroll
        for (int i = 0; i < 8; i++) {
            int c = i * 128 + tid;
            int which = c >> 9, cc = c & 511;
            int row = cc >> 3, ch = cc & 7;
            const __half* src = (which ? v_g : k_g) + gb + row * HD + ch * 16;
            int off = (which ? voff : koff) + row * AS + ch * 16;
            cpasync16(smem_u32(sm + off), src);
            cpasync16(smem_u32(sm + off + 8), src + 8);
        }
    };
    loadKV(0, 0);
    cpcommit();

    float m0 = -1e30f, m1 = -1e30f, l0 = 0.f, l1 = 0.f;
    float o[16][4];
#pragma unroll
    for (int i = 0; i < 16; i++)
#pragma unroll
        for (int j = 0; j < 4; j++) o[i][j] = 0.f;

    const int nj = qi + 1;
    const int rowbase = qbase + wid * 16;

    for (int j = 0; j < nj; j++) {
        const int s = j & 1;
        cpwait<0>();
        __syncthreads();
        if (j + 1 < nj) { loadKV(j + 1, s ^ 1); cpcommit(); }

        const int kb = KV_BASE + s * KV_STAGE;
        const int vb = kb + 64 * AS;

        float sacc[8][4];
#pragma unroll
        for (int i = 0; i < 8; i++)
#pragma unroll
            for (int jj = 0; jj < 4; jj++) sacc[i][jj] = 0.f;

#pragma unroll
        for (int ks = 0; ks < 8; ks++) {
            uint32_t qa[2][4];
            {
                int row = wid * 16 + (lane & 15);
                int col = ks * 16 + ((lane >> 4) << 3);
                ldsm4(qa[0], sm + Q_H_OFF + row * AS + col);
                ldsm4(qa[1], sm + Q_L_OFF + row * AS + col);
            }
#pragma unroll
            for (int nf2 = 0; nf2 < 4; nf2++) {
                uint32_t kh4[4];
                int krow = nf2 * 16 + (lane & 15);
                int kcol = ks * 16 + ((lane >> 4) << 3);
                ldsm4(kh4, sm + kb + krow * AS + kcol);
                mma_f16(sacc[2 * nf2],     qa[0], kh4[0], kh4[2]);
                mma_f16(sacc[2 * nf2 + 1], qa[0], kh4[1], kh4[3]);
                mma_f16(sacc[2 * nf2],     qa[1], kh4[0], kh4[2]);
                mma_f16(sacc[2 * nf2 + 1], qa[1], kh4[1], kh4[3]);
            }
        }

        const int kvb = j * 64;
        if (kvb + 63 > rowbase) {
            int r0 = rowbase + (lane >> 2), r1 = r0 + 8;
#pragma unroll
            for (int nf = 0; nf < 8; nf++) {
                int c0 = kvb + nf * 8 + (lane & 3) * 2;
                if (c0 > r0)     sacc[nf][0] = -1e30f;
                if (c0 + 1 > r0) sacc[nf][1] = -1e30f;
                if (c0 > r1)     sacc[nf][2] = -1e30f;
                if (c0 + 1 > r1) sacc[nf][3] = -1e30f;
            }
        }

        float rm0 = -1e30f, rm1 = -1e30f;
#pragma unroll
        for (int nf = 0; nf < 8; nf++) {
            rm0 = fmaxf(rm0, fmaxf(sacc[nf][0], sacc[nf][1]));
            rm1 = fmaxf(rm1, fmaxf(sacc[nf][2], sacc[nf][3]));
        }
        rm0 = fmaxf(rm0, __shfl_xor_sync(0xffffffffu, rm0, 1));
        rm0 = fmaxf(rm0, __shfl_xor_sync(0xffffffffu, rm0, 2));
        rm1 = fmaxf(rm1, __shfl_xor_sync(0xffffffffu, rm1, 1));
        rm1 = fmaxf(rm1, __shfl_xor_sync(0xffffffffu, rm1, 2));
        float mn0 = fmaxf(m0, rm0), mn1 = fmaxf(m1, rm1);
        float corr0 = exp2f(m0 - mn0), corr1 = exp2f(m1 - mn1);
        m0 = mn0; m1 = mn1;

        float rs0 = 0.f, rs1 = 0.f;
#pragma unroll
        for (int nf = 0; nf < 8; nf++) {
            float p0 = exp2f(sacc[nf][0] - mn0);
            float p1 = exp2f(sacc[nf][1] - mn0);
            float p2 = exp2f(sacc[nf][2] - mn1);
            float p3 = exp2f(sacc[nf][3] - mn1);
            sacc[nf][0] = p0; sacc[nf][1] = p1; sacc[nf][2] = p2; sacc[nf][3] = p3;
            rs0 += p0 + p1; rs1 += p2 + p3;
        }
        l0 = l0 * corr0 + rs0;
        l1 = l1 * corr1 + rs1;
        if (__any_sync(0xffffffffu, (corr0 != 1.f) || (corr1 != 1.f))) {
#pragma unroll
            for (int df = 0; df < 16; df++) {
                o[df][0] *= corr0; o[df][1] *= corr0;
                o[df][2] *= corr1; o[df][3] *= corr1;
            }
        }

        uint32_t ph[4][4];
#pragma unroll
        for (int kk = 0; kk < 4; kk++) {
            const float* A0 = sacc[2 * kk];
            const float* A1 = sacc[2 * kk + 1];
            ph[kk][0] = cvt2h(A0[0], A0[1]);
            ph[kk][1] = cvt2h(A0[2], A0[3]);
            ph[kk][2] = cvt2h(A1[0], A1[1]);
            ph[kk][3] = cvt2h(A1[2], A1[3]);
        }

#pragma unroll
        for (int kk = 0; kk < 4; kk++) {
#pragma unroll
            for (int nf2 = 0; nf2 < 8; nf2++) {
                uint32_t vh4[4];
                int vrow = kk * 16 + (lane & 15);
                int vcol = nf2 * 16 + ((lane >> 4) << 3);
                ldsm4t(vh4, sm + vb + vrow * AS + vcol);
                mma_f16(o[2 * nf2],     ph[kk], vh4[0], vh4[1]);
                mma_f16(o[2 * nf2 + 1], ph[kk], vh4[2], vh4[3]);
            }
        }
    }

    // ---- finalize: write single-fp16 context ----
    l0 += __shfl_xor_sync(0xffffffffu, l0, 1);
    l0 += __shfl_xor_sync(0xffffffffu, l0, 2);
    l1 += __shfl_xor_sync(0xffffffffu, l1, 1);
    l1 += __shfl_xor_sync(0xffffffffu, l1, 2);
    float inv0 = 1.f / l0, inv1 = 1.f / l1;

    int r0 = rowbase + (lane >> 2);
    size_t base0 = ((size_t)b * T_ + r0) * HID + h * HD + (lane & 3) * 2;
    size_t base1 = base0 + (size_t)8 * HID;
#pragma unroll
    for (int df = 0; df < 16; df++) {
        *(uint32_t*)(O + base0 + df * 8) = cvt2h(o[df][0] * inv0, o[df][1] * inv0);
        *(uint32_t*)(O + base1 + df * 8) = cvt2h(o[df][2] * inv1, o[df][3] * inv1);
    }
}

// =====================================================================
// host launcher
// =====================================================================
extern "C" void kernel_launch(void* const* d_in, const int* in_sizes, int n_in,
                              void* d_out, int out_size)
{
    const float* x    = (const float*)d_in[0];
    const float* cosb = (const float*)d_in[1];
    const float* sinb = (const float*)d_in[2];
    const float* wq   = (const float*)d_in[3];
    const float* wk   = (const float*)d_in[4];
    const float* wv   = (const float*)d_in[5];
    const float* wo   = (const float*)d_in[6];

    __half *Octx, *Qh, *Ql, *Kh, *Vh;
    cudaGetSymbolAddress((void**)&Octx, g_Octx);
    cudaGetSymbolAddress((void**)&Qh, g_Qh);
    cudaGetSymbolAddress((void**)&Ql, g_Ql);
    cudaGetSymbolAddress((void**)&Kh, g_Kh);
    cudaGetSymbolAddress((void**)&Vh, g_Vh);

    cudaFuncSetAttribute(attn_kernel, cudaFuncAttributeMaxDynamicSharedMemorySize,
                         ATTN_SMEM_BYTES);
    cudaFuncSetAttribute(gemm_ctx, cudaFuncAttributeMaxDynamicSharedMemorySize,
                         CTX_SMEM_BYTES);
    cudaFuncSetAttribute(gemm_qkv_rope, cudaFuncAttributeMaxDynamicSharedMemorySize,
                         GEMM_SMEM_BYTES);

    const int M = B_ * T_;  // 4096
    float qsc = (1.0f / sqrtf((float)HD)) * 1.4426950408889634f;

    // 0: persistent fused QKV projection + rope + split (work-stealing)
    gemm_qkv_rope<<<QKV_GRID, 512, GEMM_SMEM_BYTES>>>(
        x, wq, wk, wv, cosb, sinb, Qh, Ql, Kh, Vh, qsc);
    // 1: attention (fp16 context out)
    attn_kernel<<<dim3(T_ / 64, B_ * NH), 128, ATTN_SMEM_BYTES>>>(
        Qh, Ql, Kh, Vh, Octx);
    // 2: output projection (fp16 A direct, single plane)
    gemm_ctx<<<dim3(HID / 256, M / 128), 512, CTX_SMEM_BYTES>>>(
        Octx, wo, (float*)d_out, M, HID, HID);
}

// round 15
// speedup vs baseline: 1.9899x; 1.1929x over previous
#include <cuda_runtime.h>
#include <cuda_fp16.h>
#include <cstdint>
#include <cstddef>
#include <math.h>

// Problem constants
constexpr int B_  = 2;
constexpr int T_  = 2048;
constexpr int HID = 2048;
constexpr int NH  = 16;
constexpr int NKV = 4;
constexpr int HD  = 128;

// ---------------- scratch (static device arrays; no allocation) ----------------
__device__ __half  g_Octx[(size_t)B_ * T_ * NH * HD];
__device__ __half  g_Qh[(size_t)B_ * NH  * T_ * HD];
__device__ __half  g_Ql[(size_t)B_ * NH  * T_ * HD];
__device__ __half  g_Kh[(size_t)B_ * NKV * T_ * HD];
__device__ __half  g_Vh[(size_t)B_ * NKV * T_ * HD];
// persistent-kernel work-stealing counters (self-resetting each launch)
__device__ int g_tile_ctr = 0;
__device__ int g_done_ctr = 0;

// ---------------- PTX helpers ----------------
__device__ __forceinline__ uint32_t smem_u32(const void* p) {
    return (uint32_t)__cvta_generic_to_shared(p);
}
__device__ __forceinline__ void ldsm4(uint32_t r[4], const void* p) {
    uint32_t a = smem_u32(p);
    asm volatile("ldmatrix.sync.aligned.m8n8.x4.shared.b16 {%0,%1,%2,%3}, [%4];"
                 : "=r"(r[0]), "=r"(r[1]), "=r"(r[2]), "=r"(r[3]) : "r"(a));
}
__device__ __forceinline__ void ldsm4t(uint32_t r[4], const void* p) {
    uint32_t a = smem_u32(p);
    asm volatile("ldmatrix.sync.aligned.m8n8.x4.trans.shared.b16 {%0,%1,%2,%3}, [%4];"
                 : "=r"(r[0]), "=r"(r[1]), "=r"(r[2]), "=r"(r[3]) : "r"(a));
}
__device__ __forceinline__ void mma_f16(float c[4], const uint32_t a[4], uint32_t b0, uint32_t b1) {
    asm volatile("mma.sync.aligned.m16n8k16.row.col.f32.f16.f16.f32 "
                 "{%0,%1,%2,%3}, {%4,%5,%6,%7}, {%8,%9}, {%0,%1,%2,%3};"
                 : "+f"(c[0]), "+f"(c[1]), "+f"(c[2]), "+f"(c[3])
                 : "r"(a[0]), "r"(a[1]), "r"(a[2]), "r"(a[3]), "r"(b0), "r"(b1));
}
__device__ __forceinline__ void cpasync16(uint32_t saddr, const void* g) {
    asm volatile("cp.async.cg.shared.global [%0], [%1], 16;" :: "r"(saddr), "l"(g));
}
__device__ __forceinline__ void cpcommit() { asm volatile("cp.async.commit_group;"); }
template <int N> __device__ __forceinline__ void cpwait() {
    asm volatile("cp.async.wait_group %0;" :: "n"(N));
}
// fp16 hi/lo split of a float pair
__device__ __forceinline__ void split2h(float a, float b, uint32_t& hv, uint32_t& lv) {
    __half2 h = __floats2half2_rn(a, b);
    float2 f = __half22float2(h);
    __half2 l = __floats2half2_rn(a - f.x, b - f.y);
    hv = *reinterpret_cast<uint32_t*>(&h);
    lv = *reinterpret_cast<uint32_t*>(&l);
}
__device__ __forceinline__ uint32_t cvt2h(float a, float b) {
    __half2 h = __floats2half2_rn(a, b);
    return *reinterpret_cast<uint32_t*>(&h);
}
__device__ __forceinline__ void cvt_store4h(float4 v, __half* dst) {
    *reinterpret_cast<uint2*>(dst) = make_uint2(cvt2h(v.x, v.y), cvt2h(v.z, v.w));
}

// =====================================================================
// GEMM tile constants: CTA 128x256x32, 512 thr (16 warps 4x4),
// warp tile 32x64, two smem stages, one barrier per k-tile.
// SINGLE-plane fp16 A and B.
// =====================================================================
constexpr int SA_ST = 40;    // sA row stride (32+8 halves)
constexpr int SB_ST = 264;   // sB row stride (256+8 halves)
constexpr int SA_SZ = 128 * SA_ST;          // 5120
constexpr int SB_SZ = 32 * SB_ST;           // 8448
constexpr int ST_SZ = SA_SZ + SB_SZ;        // halves per stage = 13568
// qkv kernel smem high-water mark is the fp32 rope-exchange buffer (64x264 f32)
constexpr int QKV_SMEM_BYTES = 74752;
constexpr int CTX_SMEM_BYTES = 2 * ST_SZ * 2;     // 54272 B

constexpr int QKV_TILES = 384;              // 256 Q + 64 K + 64 V
constexpr int QKV_GRID  = 152;

// =====================================================================
// PERSISTENT fused QKV projection + RoPE + scale + fp16 convert.
// Single-fp16 x (A) and weights (B); Q output split hi/lo for attention.
// =====================================================================
__global__ __launch_bounds__(512, 1) void gemm_qkv_rope(
    const float* __restrict__ A,
    const float* __restrict__ wq, const float* __restrict__ wk, const float* __restrict__ wv,
    const float* __restrict__ cosb, const float* __restrict__ sinb,
    __half* __restrict__ Qh, __half* __restrict__ Ql,
    __half* __restrict__ Kh, __half* __restrict__ Vh,
    float qsc)
{
    extern __shared__ __half gs[];
    __shared__ int s_tile;

    const int tid  = threadIdx.x;
    const int lane = tid & 31;
    const int wid  = tid >> 5;
    const int wm   = (wid >> 2) * 32;
    const int wn   = (wid & 3) * 64;
    const int K = HID;

    for (;;) {
        if (tid == 0) s_tile = atomicAdd(&g_tile_ctr, 1);
        __syncthreads();
        const int tile = s_tile;
        if (tile >= QKV_TILES) break;

        int which, bm, bn;
        if (tile < 256)      { which = 0; bm = tile >> 3;         bn = tile & 7; }
        else if (tile < 320) { which = 1; bm = (tile - 256) >> 1; bn = (tile - 256) & 1; }
        else                 { which = 2; bm = (tile - 320) >> 1; bn = (tile - 320) & 1; }
        const float* Bm = (which == 0) ? wq : (which == 1) ? wk : wv;
        const int N = (which == 0) ? (NH * HD) : (NKV * HD);

        const float* Ab = A + (size_t)bm * 128 * K;
        const float* Bb = Bm + (size_t)bn * 256;

        float acc[2][8][4] = {};
        float4 ra[2], rb[4];

        auto gload = [&](int k0) {
#pragma unroll
            for (int i = 0; i < 2; i++) {
                int idx = i * 512 + tid;
                int r = idx >> 3, c4 = idx & 7;
                ra[i] = *(const float4*)(Ab + (size_t)r * K + k0 + c4 * 4);
            }
#pragma unroll
            for (int i = 0; i < 4; i++) {
                int idx = i * 512 + tid;
                int r = idx >> 6, c4 = idx & 63;
                rb[i] = *(const float4*)(Bb + (size_t)(k0 + r) * N + c4 * 4);
            }
        };
        auto sstore = [&](int s) {
            __half* sA0 = gs + s * ST_SZ;
            __half* sB0 = sA0 + SA_SZ;
#pragma unroll
            for (int i = 0; i < 2; i++) {
                int idx = i * 512 + tid;
                int r = idx >> 3, c = (idx & 7) * 4;
                cvt_store4h(ra[i], sA0 + r * SA_ST + c);
            }
#pragma unroll
            for (int i = 0; i < 4; i++) {
                int idx = i * 512 + tid;
                int r = idx >> 6, c = (idx & 63) * 4;
                cvt_store4h(rb[i], sB0 + r * SB_ST + c);
            }
        };

        gload(0);
        sstore(0);
        __syncthreads();

        const int nk = K / 32;
        for (int kt = 0; kt < nk; kt++) {
            const int s = kt & 1;
            if (kt + 1 < nk) gload((kt + 1) * 32);

            const __half* sA0 = gs + s * ST_SZ;
            const __half* sB0 = sA0 + SA_SZ;

#pragma unroll
            for (int ks = 0; ks < 2; ks++) {
                const int colA = ks * 16 + ((lane >> 4) << 3);
                uint32_t af0[2][4];
#pragma unroll
                for (int mf = 0; mf < 2; mf++) {
                    int row = wm + mf * 16 + (lane & 15);
                    ldsm4(af0[mf], sA0 + row * SA_ST + colA);
                }
                const int rowB = ks * 16 + (lane & 15);
#pragma unroll
                for (int nf2 = 0; nf2 < 4; nf2++) {
                    const int colB = wn + nf2 * 16 + ((lane >> 4) << 3);
                    uint32_t bh[4];
                    ldsm4t(bh, sB0 + rowB * SB_ST + colB);
#pragma unroll
                    for (int mf = 0; mf < 2; mf++)
#pragma unroll
                        for (int sub = 0; sub < 2; sub++)
                            mma_f16(acc[mf][nf2 * 2 + sub], af0[mf], bh[sub * 2], bh[sub * 2 + 1]);
                }
            }
            if (kt + 1 < nk) sstore(s ^ 1);
            __syncthreads();
        }

        // ---- fused rope + convert epilogue (smem exchange, two 64-row passes) ----
        {
            float* sf = reinterpret_cast<float*>(gs);
            const int H = (which == 0) ? NH : NKV;
            const float scale = (which == 0) ? qsc : 1.0f;
            const int do_rope = (which != 2);

#pragma unroll
            for (int mf = 0; mf < 2; mf++) {
                int rl0 = (wm >> 5) * 16 + (lane >> 2);
#pragma unroll
                for (int nf = 0; nf < 8; nf++) {
                    int col = wn + nf * 8 + (lane & 3) * 2;
                    *(float2*)(sf + rl0 * 264 + col)       = make_float2(acc[mf][nf][0], acc[mf][nf][1]);
                    *(float2*)(sf + (rl0 + 8) * 264 + col) = make_float2(acc[mf][nf][2], acc[mf][nf][3]);
                }
                __syncthreads();
#pragma unroll
                for (int k = 0; k < 16; k++) {
                    int e2 = k * 512 + tid;
                    int rl = e2 >> 7;
                    int c2 = (e2 & 127) * 2;
                    int r  = bm * 128 + (rl >> 4) * 32 + mf * 16 + (rl & 15);
                    int t  = r & (T_ - 1);
                    int b  = r >> 11;
                    int gc = bn * 256 + c2;
                    int h  = gc >> 7;
                    int d  = gc & 127;
                    float2 v = *(float2*)(sf + rl * 264 + c2);
                    float o0, o1;
                    if (do_rope) {
                        int dd = d & 63;
                        float2 cs = *(const float2*)(cosb + t * 64 + dd);
                        float2 sn = *(const float2*)(sinb + t * 64 + dd);
                        float2 w  = *(float2*)(sf + rl * 264 + (c2 ^ 64));
                        if (d < 64) { o0 = v.x * cs.x - w.x * sn.x; o1 = v.y * cs.y - w.y * sn.y; }
                        else        { o0 = v.x * cs.x + w.x * sn.x; o1 = v.y * cs.y + w.y * sn.y; }
                    } else { o0 = v.x; o1 = v.y; }
                    o0 *= scale; o1 *= scale;
                    size_t di = (((size_t)(b * H + h)) * T_ + t) * HD + d;
                    if (which == 0) {
                        uint32_t hv, lv;
                        split2h(o0, o1, hv, lv);
                        *(uint32_t*)(Qh + di) = hv;
                        *(uint32_t*)(Ql + di) = lv;
                    } else if (which == 1) {
                        *(uint32_t*)(Kh + di) = cvt2h(o0, o1);
                    } else {
                        *(uint32_t*)(Vh + di) = cvt2h(o0, o1);
                    }
                }
                __syncthreads();
            }
        }
    }

    if (tid == 0) {
        int d = atomicAdd(&g_done_ctr, 1);
        if (d == (int)gridDim.x - 1) {
            g_tile_ctr = 0;
            g_done_ctr = 0;
            __threadfence();
        }
    }
}

// =====================================================================
// Output-projection GEMM: A is fp16 context (direct cp.async, single
// plane), B fp32 weights converted inline to fp16, fp32 out.
// =====================================================================
__global__ __launch_bounds__(512, 1) void gemm_ctx(
    const __half* __restrict__ A, const float* __restrict__ Bm, float* __restrict__ C,
    int M, int N, int K)
{
    extern __shared__ __half gs[];

    const int tid  = threadIdx.x;
    const int lane = tid & 31;
    const int wid  = tid >> 5;
    const int bm   = blockIdx.y, bn = blockIdx.x;
    const int wm   = (wid >> 2) * 32;
    const int wn   = (wid & 3) * 64;

    const __half* Ab = A + (size_t)bm * 128 * K;
    const float*  Bb = Bm + (size_t)bn * 256;

    float acc[2][8][4] = {};
    float4 rb[4];

    auto gloadA = [&](int k0, int s) {
        __half* sA0 = gs + s * ST_SZ;
        int r = tid >> 2, ch = (tid & 3) * 8;
        cpasync16(smem_u32(sA0 + r * SA_ST + ch), Ab + (size_t)r * K + k0 + ch);
    };
    auto gloadB = [&](int k0) {
#pragma unroll
        for (int i = 0; i < 4; i++) {
            int idx = i * 512 + tid;
            int r = idx >> 6, c4 = idx & 63;
            rb[i] = *(const float4*)(Bb + (size_t)(k0 + r) * N + c4 * 4);
        }
    };
    auto sstoreB = [&](int s) {
        __half* sB0 = gs + s * ST_SZ + SA_SZ;
#pragma unroll
        for (int i = 0; i < 4; i++) {
            int idx = i * 512 + tid;
            int r = idx >> 6, c = (idx & 63) * 4;
            cvt_store4h(rb[i], sB0 + r * SB_ST + c);
        }
    };

    gloadA(0, 0);
    cpcommit();
    gloadB(0);
    sstoreB(0);
    cpwait<0>();
    __syncthreads();

    const int nk = K / 32;
    for (int kt = 0; kt < nk; kt++) {
        const int s = kt & 1;
        if (kt + 1 < nk) {
            gloadA((kt + 1) * 32, s ^ 1);
            cpcommit();
            gloadB((kt + 1) * 32);
        }

        const __half* sA0 = gs + s * ST_SZ;
        const __half* sB0 = sA0 + SA_SZ;

#pragma unroll
        for (int ks = 0; ks < 2; ks++) {
            const int colA = ks * 16 + ((lane >> 4) << 3);
            uint32_t af0[2][4];
#pragma unroll
            for (int mf = 0; mf < 2; mf++) {
                int row = wm + mf * 16 + (lane & 15);
                ldsm4(af0[mf], sA0 + row * SA_ST + colA);
            }
            const int rowB = ks * 16 + (lane & 15);
#pragma unroll
            for (int nf2 = 0; nf2 < 4; nf2++) {
                const int colB = wn + nf2 * 16 + ((lane >> 4) << 3);
                uint32_t bh[4];
                ldsm4t(bh, sB0 + rowB * SB_ST + colB);
#pragma unroll
                for (int mf = 0; mf < 2; mf++)
#pragma unroll
                    for (int sub = 0; sub < 2; sub++)
                        mma_f16(acc[mf][nf2 * 2 + sub], af0[mf], bh[sub * 2], bh[sub * 2 + 1]);
            }
        }
        if (kt + 1 < nk) sstoreB(s ^ 1);
        cpwait<0>();
        __syncthreads();
    }

#pragma unroll
    for (int mf = 0; mf < 2; mf++) {
        int r0 = bm * 128 + wm + mf * 16 + (lane >> 2);
#pragma unroll
        for (int nf = 0; nf < 8; nf++) {
            int c = bn * 256 + wn + nf * 8 + (lane & 3) * 2;
            *(float2*)(C + (size_t)r0 * N + c)       = make_float2(acc[mf][nf][0], acc[mf][nf][1]);
            *(float2*)(C + (size_t)(r0 + 8) * N + c) = make_float2(acc[mf][nf][2], acc[mf][nf][3]);
        }
    }
}

// =====================================================================
// Flash attention (causal, GQA). Br=64 (4 warps x 16 rows), Bc=64.
// Q split fp16 hi/lo; K, V, P single fp16. Output: single fp16 context.
// Double-buffered KV, one barrier per tile. 2 CTAs per SM.
// =====================================================================
constexpr int AS       = 136;
constexpr int Q_H_OFF  = 0;
constexpr int Q_L_OFF  = 64 * AS;
constexpr int KV_STAGE = 2 * 64 * AS;
constexpr int KV_BASE  = 2 * 64 * AS;
constexpr int ATTN_SMEM_BYTES = (2 * 64 * AS + 2 * KV_STAGE) * 2;   // 104448

__global__ __launch_bounds__(128, 2) void attn_kernel(
    const __half* __restrict__ Qh, const __half* __restrict__ Ql,
    const __half* __restrict__ Kh, const __half* __restrict__ Vh,
    __half* __restrict__ O)
{
    extern __shared__ __half sm[];
    const int tid  = threadIdx.x;
    const int lane = tid & 31;
    const int wid  = tid >> 5;
    const int bh   = blockIdx.y;
    const int b    = bh >> 4, h = bh & 15;
    const int qi   = (int)gridDim.x - 1 - (int)blockIdx.x;
    const int qbase = qi * 64;
    const int kvi  = b * NKV + (h >> 2);

    const __half* qh_g = Qh + ((size_t)bh * T_ + qbase) * HD;
    const __half* ql_g = Ql + ((size_t)bh * T_ + qbase) * HD;
    const __half* k_g  = Kh + (size_t)kvi * T_ * HD;
    const __half* v_g  = Vh + (size_t)kvi * T_ * HD;

#pragma unroll
    for (int i = 0; i < 8; i++) {
        int c = i * 128 + tid;
        int split = c >> 9, cc = c & 511;
        int row = cc >> 3, ch = cc & 7;
        const __half* src = (split ? ql_g : qh_g) + row * HD + ch * 16;
        cpasync16(smem_u32(sm + (split ? Q_L_OFF : Q_H_OFF) + row * AS + ch * 16), src);
        cpasync16(smem_u32(sm + (split ? Q_L_OFF : Q_H_OFF) + row * AS + ch * 16 + 8),
                  src + 8);
    }

    auto loadKV = [&](int j, int st) {
        size_t gb = (size_t)j * 64 * HD;
        const int koff = KV_BASE + st * KV_STAGE;
        const int voff = koff + 64 * AS;
#pragma unroll
        for (int i = 0; i < 8; i++) {
            int c = i * 128 + tid;
            int which = c >> 9, cc = c & 511;
            int row = cc >> 3, ch = cc & 7;
            const __half* src = (which ? v_g : k_g) + gb + row * HD + ch * 16;
            int off = (which ? voff : koff) + row * AS + ch * 16;
            cpasync16(smem_u32(sm + off), src);
            cpasync16(smem_u32(sm + off + 8), src + 8);
        }
    };
    loadKV(0, 0);
    cpcommit();

    float m0 = -1e30f, m1 = -1e30f, l0 = 0.f, l1 = 0.f;
    float o[16][4];
#pragma unroll
    for (int i = 0; i < 16; i++)
#pragma unroll
        for (int j = 0; j < 4; j++) o[i][j] = 0.f;

    const int nj = qi + 1;
    const int rowbase = qbase + wid * 16;

    for (int j = 0; j < nj; j++) {
        const int s = j & 1;
        cpwait<0>();
        __syncthreads();
        if (j + 1 < nj) { loadKV(j + 1, s ^ 1); cpcommit(); }

        const int kb = KV_BASE + s * KV_STAGE;
        const int vb = kb + 64 * AS;

        float sacc[8][4];
#pragma unroll
        for (int i = 0; i < 8; i++)
#pragma unroll
            for (int jj = 0; jj < 4; jj++) sacc[i][jj] = 0.f;

#pragma unroll
        for (int ks = 0; ks < 8; ks++) {
            uint32_t qa[2][4];
            {
                int row = wid * 16 + (lane & 15);
                int col = ks * 16 + ((lane >> 4) << 3);
                ldsm4(qa[0], sm + Q_H_OFF + row * AS + col);
                ldsm4(qa[1], sm + Q_L_OFF + row * AS + col);
            }
#pragma unroll
            for (int nf2 = 0; nf2 < 4; nf2++) {
                uint32_t kh4[4];
                int krow = nf2 * 16 + (lane & 15);
                int kcol = ks * 16 + ((lane >> 4) << 3);
                ldsm4(kh4, sm + kb + krow * AS + kcol);
                mma_f16(sacc[2 * nf2],     qa[0], kh4[0], kh4[2]);
                mma_f16(sacc[2 * nf2 + 1], qa[0], kh4[1], kh4[3]);
                mma_f16(sacc[2 * nf2],     qa[1], kh4[0], kh4[2]);
                mma_f16(sacc[2 * nf2 + 1], qa[1], kh4[1], kh4[3]);
            }
        }

        const int kvb = j * 64;
        if (kvb + 63 > rowbase) {
            int r0 = rowbase + (lane >> 2), r1 = r0 + 8;
#pragma unroll
            for (int nf = 0; nf < 8; nf++) {
                int c0 = kvb + nf * 8 + (lane & 3) * 2;
                if (c0 > r0)     sacc[nf][0] = -1e30f;
                if (c0 + 1 > r0) sacc[nf][1] = -1e30f;
                if (c0 > r1)     sacc[nf][2] = -1e30f;
                if (c0 + 1 > r1) sacc[nf][3] = -1e30f;
            }
        }

        float rm0 = -1e30f, rm1 = -1e30f;
#pragma unroll
        for (int nf = 0; nf < 8; nf++) {
            rm0 = fmaxf(rm0, fmaxf(sacc[nf][0], sacc[nf][1]));
            rm1 = fmaxf(rm1, fmaxf(sacc[nf][2], sacc[nf][3]));
        }
        rm0 = fmaxf(rm0, __shfl_xor_sync(0xffffffffu, rm0, 1));
        rm0 = fmaxf(rm0, __shfl_xor_sync(0xffffffffu, rm0, 2));
        rm1 = fmaxf(rm1, __shfl_xor_sync(0xffffffffu, rm1, 1));
        rm1 = fmaxf(rm1, __shfl_xor_sync(0xffffffffu, rm1, 2));
        float mn0 = fmaxf(m0, rm0), mn1 = fmaxf(m1, rm1);
        float corr0 = exp2f(m0 - mn0), corr1 = exp2f(m1 - mn1);
        m0 = mn0; m1 = mn1;

        float rs0 = 0.f, rs1 = 0.f;
#pragma unroll
        for (int nf = 0; nf < 8; nf++) {
            float p0 = exp2f(sacc[nf][0] - mn0);
            float p1 = exp2f(sacc[nf][1] - mn0);
            float p2 = exp2f(sacc[nf][2] - mn1);
            float p3 = exp2f(sacc[nf][3] - mn1);
            sacc[nf][0] = p0; sacc[nf][1] = p1; sacc[nf][2] = p2; sacc[nf][3] = p3;
            rs0 += p0 + p1; rs1 += p2 + p3;
        }
        l0 = l0 * corr0 + rs0;
        l1 = l1 * corr1 + rs1;
        if (__any_sync(0xffffffffu, (corr0 != 1.f) || (corr1 != 1.f))) {
#pragma unroll
            for (int df = 0; df < 16; df++) {
                o[df][0] *= corr0; o[df][1] *= corr0;
                o[df][2] *= corr1; o[df][3] *= corr1;
            }
        }

        uint32_t ph[4][4];
#pragma unroll
        for (int kk = 0; kk < 4; kk++) {
            const float* A0 = sacc[2 * kk];
            const float* A1 = sacc[2 * kk + 1];
            ph[kk][0] = cvt2h(A0[0], A0[1]);
            ph[kk][1] = cvt2h(A0[2], A0[3]);
            ph[kk][2] = cvt2h(A1[0], A1[1]);
            ph[kk][3] = cvt2h(A1[2], A1[3]);
        }

#pragma unroll
        for (int kk = 0; kk < 4; kk++) {
#pragma unroll
            for (int nf2 = 0; nf2 < 8; nf2++) {
                uint32_t vh4[4];
                int vrow = kk * 16 + (lane & 15);
                int vcol = nf2 * 16 + ((lane >> 4) << 3);
                ldsm4t(vh4, sm + vb + vrow * AS + vcol);
                mma_f16(o[2 * nf2],     ph[kk], vh4[0], vh4[1]);
                mma_f16(o[2 * nf2 + 1], ph[kk], vh4[2], vh4[3]);
            }
        }
    }

    // ---- finalize: write single-fp16 context ----
    l0 += __shfl_xor_sync(0xffffffffu, l0, 1);
    l0 += __shfl_xor_sync(0xffffffffu, l0, 2);
    l1 += __shfl_xor_sync(0xffffffffu, l1, 1);
    l1 += __shfl_xor_sync(0xffffffffu, l1, 2);
    float inv0 = 1.f / l0, inv1 = 1.f / l1;

    int r0 = rowbase + (lane >> 2);
    size_t base0 = ((size_t)b * T_ + r0) * HID + h * HD + (lane & 3) * 2;
    size_t base1 = base0 + (size_t)8 * HID;
#pragma unroll
    for (int df = 0; df < 16; df++) {
        *(uint32_t*)(O + base0 + df * 8) = cvt2h(o[df][0] * inv0, o[df][1] * inv0);
        *(uint32_t*)(O + base1 + df * 8) = cvt2h(o[df][2] * inv1, o[df][3] * inv1);
    }
}

// =====================================================================
// host launcher
// =====================================================================
extern "C" void kernel_launch(void* const* d_in, const int* in_sizes, int n_in,
                              void* d_out, int out_size)
{
    const float* x    = (const float*)d_in[0];
    const float* cosb = (const float*)d_in[1];
    const float* sinb = (const float*)d_in[2];
    const float* wq   = (const float*)d_in[3];
    const float* wk   = (const float*)d_in[4];
    const float* wv   = (const float*)d_in[5];
    const float* wo   = (const float*)d_in[6];

    __half *Octx, *Qh, *Ql, *Kh, *Vh;
    cudaGetSymbolAddress((void**)&Octx, g_Octx);
    cudaGetSymbolAddress((void**)&Qh, g_Qh);
    cudaGetSymbolAddress((void**)&Ql, g_Ql);
    cudaGetSymbolAddress((void**)&Kh, g_Kh);
    cudaGetSymbolAddress((void**)&Vh, g_Vh);

    cudaFuncSetAttribute(attn_kernel, cudaFuncAttributeMaxDynamicSharedMemorySize,
                         ATTN_SMEM_BYTES);
    cudaFuncSetAttribute(gemm_ctx, cudaFuncAttributeMaxDynamicSharedMemorySize,
                         CTX_SMEM_BYTES);
    cudaFuncSetAttribute(gemm_qkv_rope, cudaFuncAttributeMaxDynamicSharedMemorySize,
                         QKV_SMEM_BYTES);

    const int M = B_ * T_;  // 4096
    float qsc = (1.0f / sqrtf((float)HD)) * 1.4426950408889634f;

    // 0: persistent fused QKV projection + rope (single-fp16 operands)
    gemm_qkv_rope<<<QKV_GRID, 512, QKV_SMEM_BYTES>>>(
        x, wq, wk, wv, cosb, sinb, Qh, Ql, Kh, Vh, qsc);
    // 1: attention (fp16 context out)
    attn_kernel<<<dim3(T_ / 64, B_ * NH), 128, ATTN_SMEM_BYTES>>>(
        Qh, Ql, Kh, Vh, Octx);
    // 2: output projection (fp16 A direct, single plane)
    gemm_ctx<<<dim3(HID / 256, M / 128), 512, CTX_SMEM_BYTES>>>(
        Octx, wo, (float*)d_out, M, HID, HID);
}

// round 16
// speedup vs baseline: 2.3539x; 1.1829x over previous
#include <cuda_runtime.h>
#include <cuda_fp16.h>
#include <cstdint>
#include <cstddef>
#include <math.h>

// Problem constants
constexpr int B_  = 2;
constexpr int T_  = 2048;
constexpr int HID = 2048;
constexpr int NH  = 16;
constexpr int NKV = 4;
constexpr int HD  = 128;

// ---------------- scratch (static device arrays; no allocation) ----------------
__device__ __half  g_Octx[(size_t)B_ * T_ * NH * HD];
__device__ __half  g_Qh[(size_t)B_ * NH  * T_ * HD];
__device__ __half  g_Kh[(size_t)B_ * NKV * T_ * HD];
__device__ __half  g_Vh[(size_t)B_ * NKV * T_ * HD];
// fp16 copies of inputs (one-time convert per launch)
__device__ __half  g_xh [(size_t)B_ * T_ * HID];
__device__ __half  g_wqh[(size_t)HID * NH * HD];
__device__ __half  g_wkh[(size_t)HID * NKV * HD];
__device__ __half  g_wvh[(size_t)HID * NKV * HD];
__device__ __half  g_woh[(size_t)NH * HD * HID];
// persistent-kernel work-stealing counters (self-resetting each launch)
__device__ int g_tile_ctr = 0;
__device__ int g_done_ctr = 0;

// ---------------- PTX helpers ----------------
__device__ __forceinline__ uint32_t smem_u32(const void* p) {
    return (uint32_t)__cvta_generic_to_shared(p);
}
__device__ __forceinline__ void ldsm4(uint32_t r[4], const void* p) {
    uint32_t a = smem_u32(p);
    asm volatile("ldmatrix.sync.aligned.m8n8.x4.shared.b16 {%0,%1,%2,%3}, [%4];"
                 : "=r"(r[0]), "=r"(r[1]), "=r"(r[2]), "=r"(r[3]) : "r"(a));
}
__device__ __forceinline__ void ldsm4t(uint32_t r[4], const void* p) {
    uint32_t a = smem_u32(p);
    asm volatile("ldmatrix.sync.aligned.m8n8.x4.trans.shared.b16 {%0,%1,%2,%3}, [%4];"
                 : "=r"(r[0]), "=r"(r[1]), "=r"(r[2]), "=r"(r[3]) : "r"(a));
}
__device__ __forceinline__ void mma_f16(float c[4], const uint32_t a[4], uint32_t b0, uint32_t b1) {
    asm volatile("mma.sync.aligned.m16n8k16.row.col.f32.f16.f16.f32 "
                 "{%0,%1,%2,%3}, {%4,%5,%6,%7}, {%8,%9}, {%0,%1,%2,%3};"
                 : "+f"(c[0]), "+f"(c[1]), "+f"(c[2]), "+f"(c[3])
                 : "r"(a[0]), "r"(a[1]), "r"(a[2]), "r"(a[3]), "r"(b0), "r"(b1));
}
__device__ __forceinline__ void cpasync16(uint32_t saddr, const void* g) {
    asm volatile("cp.async.cg.shared.global [%0], [%1], 16;" :: "r"(saddr), "l"(g));
}
__device__ __forceinline__ void cpcommit() { asm volatile("cp.async.commit_group;"); }
template <int N> __device__ __forceinline__ void cpwait() {
    asm volatile("cp.async.wait_group %0;" :: "n"(N));
}
__device__ __forceinline__ uint32_t cvt2h(float a, float b) {
    __half2 h = __floats2half2_rn(a, b);
    return *reinterpret_cast<uint32_t*>(&h);
}
__device__ __forceinline__ void cvt_store4h(float4 v, __half* dst) {
    *reinterpret_cast<uint2*>(dst) = make_uint2(cvt2h(v.x, v.y), cvt2h(v.z, v.w));
}

// =====================================================================
// prep: one-time fp32 -> fp16 conversion of x and all weights
// =====================================================================
constexpr int NX4  = (B_ * T_ * HID) / 4;      // 2097152
constexpr int NW4  = (HID * NH * HD) / 4;      // 1048576 (wq, wo)
constexpr int NKW4 = (HID * NKV * HD) / 4;     // 262144  (wk, wv)
constexpr int CVT_TOTAL = NX4 + 2 * NW4 + 2 * NKW4;   // 4718592

__global__ void cvt_inputs(const float4* __restrict__ x,
                           const float4* __restrict__ wq, const float4* __restrict__ wk,
                           const float4* __restrict__ wv, const float4* __restrict__ wo,
                           __half* __restrict__ xh,
                           __half* __restrict__ wqh, __half* __restrict__ wkh,
                           __half* __restrict__ wvh, __half* __restrict__ woh)
{
    int i = blockIdx.x * 256 + threadIdx.x;
    const float4* s; __half* d; int o;
    if (i < NX4)                          { s = x;  d = xh;  o = i; }
    else if (i < NX4 + NW4)               { s = wq; d = wqh; o = i - NX4; }
    else if (i < NX4 + NW4 + NKW4)        { s = wk; d = wkh; o = i - NX4 - NW4; }
    else if (i < NX4 + NW4 + 2 * NKW4)    { s = wv; d = wvh; o = i - NX4 - NW4 - NKW4; }
    else                                  { s = wo; d = woh; o = i - NX4 - NW4 - 2 * NKW4; }
    cvt_store4h(s[o], d + (size_t)o * 4);
}

// =====================================================================
// GEMM tile constants: CTA 128x256x32, 512 thr (16 warps 4x4),
// warp tile 32x64. Pure fp16 cp.async pipeline, one barrier/k-tile.
// =====================================================================
constexpr int SA_ST = 40;    // sA row stride (32+8 halves)
constexpr int SB_ST = 264;   // sB row stride (256+8 halves)
constexpr int SA_SZ = 128 * SA_ST;          // 5120
constexpr int SB_SZ = 32 * SB_ST;           // 8448
constexpr int ST_SZ = SA_SZ + SB_SZ;        // 13568 halves/stage
// qkv smem high-water: fp32 rope-exchange buffer 64x264 f32 = 67584 B
constexpr int QKV_SMEM_BYTES = 69632;
constexpr int CTX_SMEM_BYTES = 2 * ST_SZ * 2;     // 54272 B

constexpr int QKV_TILES = 384;              // 256 Q + 64 K + 64 V
constexpr int QKV_GRID  = 152;

// =====================================================================
// PERSISTENT fused QKV projection + RoPE + scale. All-fp16 operands
// via cp.async; Q/K/V outputs single fp16.
// =====================================================================
__global__ __launch_bounds__(512, 1) void gemm_qkv_rope(
    const __half* __restrict__ A,
    const __half* __restrict__ wq, const __half* __restrict__ wk, const __half* __restrict__ wv,
    const float* __restrict__ cosb, const float* __restrict__ sinb,
    __half* __restrict__ Qh, __half* __restrict__ Kh, __half* __restrict__ Vh,
    float qsc)
{
    extern __shared__ __half gs[];
    __shared__ int s_tile;

    const int tid  = threadIdx.x;
    const int lane = tid & 31;
    const int wid  = tid >> 5;
    const int wm   = (wid >> 2) * 32;
    const int wn   = (wid & 3) * 64;
    const int K = HID;

    for (;;) {
        if (tid == 0) s_tile = atomicAdd(&g_tile_ctr, 1);
        __syncthreads();
        const int tile = s_tile;
        if (tile >= QKV_TILES) break;

        int which, bm, bn;
        if (tile < 256)      { which = 0; bm = tile >> 3;         bn = tile & 7; }
        else if (tile < 320) { which = 1; bm = (tile - 256) >> 1; bn = (tile - 256) & 1; }
        else                 { which = 2; bm = (tile - 320) >> 1; bn = (tile - 320) & 1; }
        const __half* Bm = (which == 0) ? wq : (which == 1) ? wk : wv;
        const int N = (which == 0) ? (NH * HD) : (NKV * HD);

        const __half* Ab = A + (size_t)bm * 128 * K;
        const __half* Bb = Bm + (size_t)bn * 256;

        float acc[2][8][4] = {};

        auto loadAB = [&](int k0, int s) {
            __half* sA0 = gs + s * ST_SZ;
            __half* sB0 = sA0 + SA_SZ;
            {   // A: 128 rows x 32 halves = 512 x 16B chunks (1/thread)
                int r = tid >> 2, ch = (tid & 3) * 8;
                cpasync16(smem_u32(sA0 + r * SA_ST + ch), Ab + (size_t)r * K + k0 + ch);
            }
#pragma unroll
            for (int i = 0; i < 2; i++) {   // B: 32 rows x 256 halves = 1024 chunks
                int idx = i * 512 + tid;
                int r = idx >> 5, ch = (idx & 31) * 8;
                cpasync16(smem_u32(sB0 + r * SB_ST + ch), Bb + (size_t)(k0 + r) * N + ch);
            }
            cpcommit();
        };

        loadAB(0, 0);

        const int nk = K / 32;
        for (int kt = 0; kt < nk; kt++) {
            const int s = kt & 1;
            cpwait<0>();
            __syncthreads();
            if (kt + 1 < nk) loadAB((kt + 1) * 32, s ^ 1);

            const __half* sA0 = gs + s * ST_SZ;
            const __half* sB0 = sA0 + SA_SZ;

#pragma unroll
            for (int ks = 0; ks < 2; ks++) {
                const int colA = ks * 16 + ((lane >> 4) << 3);
                uint32_t af0[2][4];
#pragma unroll
                for (int mf = 0; mf < 2; mf++) {
                    int row = wm + mf * 16 + (lane & 15);
                    ldsm4(af0[mf], sA0 + row * SA_ST + colA);
                }
                const int rowB = ks * 16 + (lane & 15);
#pragma unroll
                for (int nf2 = 0; nf2 < 4; nf2++) {
                    const int colB = wn + nf2 * 16 + ((lane >> 4) << 3);
                    uint32_t bh[4];
                    ldsm4t(bh, sB0 + rowB * SB_ST + colB);
#pragma unroll
                    for (int mf = 0; mf < 2; mf++)
#pragma unroll
                        for (int sub = 0; sub < 2; sub++)
                            mma_f16(acc[mf][nf2 * 2 + sub], af0[mf], bh[sub * 2], bh[sub * 2 + 1]);
                }
            }
        }
        __syncthreads();   // all warps done reading stages before epilogue reuses gs

        // ---- fused rope + convert epilogue (smem exchange, two 64-row passes) ----
        {
            float* sf = reinterpret_cast<float*>(gs);
            const int H = (which == 0) ? NH : NKV;
            const float scale = (which == 0) ? qsc : 1.0f;
            const int do_rope = (which != 2);
            __half* dst = (which == 0) ? Qh : (which == 1) ? Kh : Vh;

#pragma unroll
            for (int mf = 0; mf < 2; mf++) {
                int rl0 = (wm >> 5) * 16 + (lane >> 2);
#pragma unroll
                for (int nf = 0; nf < 8; nf++) {
                    int col = wn + nf * 8 + (lane & 3) * 2;
                    *(float2*)(sf + rl0 * 264 + col)       = make_float2(acc[mf][nf][0], acc[mf][nf][1]);
                    *(float2*)(sf + (rl0 + 8) * 264 + col) = make_float2(acc[mf][nf][2], acc[mf][nf][3]);
                }
                __syncthreads();
#pragma unroll
                for (int k = 0; k < 16; k++) {
                    int e2 = k * 512 + tid;
                    int rl = e2 >> 7;
                    int c2 = (e2 & 127) * 2;
                    int r  = bm * 128 + (rl >> 4) * 32 + mf * 16 + (rl & 15);
                    int t  = r & (T_ - 1);
                    int b  = r >> 11;
                    int gc = bn * 256 + c2;
                    int h  = gc >> 7;
                    int d  = gc & 127;
                    float2 v = *(float2*)(sf + rl * 264 + c2);
                    float o0, o1;
                    if (do_rope) {
                        int dd = d & 63;
                        float2 cs = *(const float2*)(cosb + t * 64 + dd);
                        float2 sn = *(const float2*)(sinb + t * 64 + dd);
                        float2 w  = *(float2*)(sf + rl * 264 + (c2 ^ 64));
                        if (d < 64) { o0 = v.x * cs.x - w.x * sn.x; o1 = v.y * cs.y - w.y * sn.y; }
                        else        { o0 = v.x * cs.x + w.x * sn.x; o1 = v.y * cs.y + w.y * sn.y; }
                    } else { o0 = v.x; o1 = v.y; }
                    o0 *= scale; o1 *= scale;
                    size_t di = (((size_t)(b * H + h)) * T_ + t) * HD + d;
                    *(uint32_t*)(dst + di) = cvt2h(o0, o1);
                }
                __syncthreads();
            }
        }
    }

    if (tid == 0) {
        int d = atomicAdd(&g_done_ctr, 1);
        if (d == (int)gridDim.x - 1) {
            g_tile_ctr = 0;
            g_done_ctr = 0;
            __threadfence();
        }
    }
}

// =====================================================================
// Output-projection GEMM: fp16 context A, pre-converted fp16 wo B,
// pure cp.async pipeline, fp32 out.
// =====================================================================
__global__ __launch_bounds__(512, 1) void gemm_ctx(
    const __half* __restrict__ A, const __half* __restrict__ Bm, float* __restrict__ C,
    int M, int N, int K)
{
    extern __shared__ __half gs[];

    const int tid  = threadIdx.x;
    const int lane = tid & 31;
    const int wid  = tid >> 5;
    const int bm   = blockIdx.y, bn = blockIdx.x;
    const int wm   = (wid >> 2) * 32;
    const int wn   = (wid & 3) * 64;

    const __half* Ab = A + (size_t)bm * 128 * K;
    const __half* Bb = Bm + (size_t)bn * 256;

    float acc[2][8][4] = {};

    auto loadAB = [&](int k0, int s) {
        __half* sA0 = gs + s * ST_SZ;
        __half* sB0 = sA0 + SA_SZ;
        {
            int r = tid >> 2, ch = (tid & 3) * 8;
            cpasync16(smem_u32(sA0 + r * SA_ST + ch), Ab + (size_t)r * K + k0 + ch);
        }
#pragma unroll
        for (int i = 0; i < 2; i++) {
            int idx = i * 512 + tid;
            int r = idx >> 5, ch = (idx & 31) * 8;
            cpasync16(smem_u32(sB0 + r * SB_ST + ch), Bb + (size_t)(k0 + r) * N + ch);
        }
        cpcommit();
    };

    loadAB(0, 0);

    const int nk = K / 32;
    for (int kt = 0; kt < nk; kt++) {
        const int s = kt & 1;
        cpwait<0>();
        __syncthreads();
        if (kt + 1 < nk) loadAB((kt + 1) * 32, s ^ 1);

        const __half* sA0 = gs + s * ST_SZ;
        const __half* sB0 = sA0 + SA_SZ;

#pragma unroll
        for (int ks = 0; ks < 2; ks++) {
            const int colA = ks * 16 + ((lane >> 4) << 3);
            uint32_t af0[2][4];
#pragma unroll
            for (int mf = 0; mf < 2; mf++) {
                int row = wm + mf * 16 + (lane & 15);
                ldsm4(af0[mf], sA0 + row * SA_ST + colA);
            }
            const int rowB = ks * 16 + (lane & 15);
#pragma unroll
            for (int nf2 = 0; nf2 < 4; nf2++) {
                const int colB = wn + nf2 * 16 + ((lane >> 4) << 3);
                uint32_t bh[4];
                ldsm4t(bh, sB0 + rowB * SB_ST + colB);
#pragma unroll
                for (int mf = 0; mf < 2; mf++)
#pragma unroll
                    for (int sub = 0; sub < 2; sub++)
                        mma_f16(acc[mf][nf2 * 2 + sub], af0[mf], bh[sub * 2], bh[sub * 2 + 1]);
            }
        }
    }

#pragma unroll
    for (int mf = 0; mf < 2; mf++) {
        int r0 = bm * 128 + wm + mf * 16 + (lane >> 2);
#pragma unroll
        for (int nf = 0; nf < 8; nf++) {
            int c = bn * 256 + wn + nf * 8 + (lane & 3) * 2;
            *(float2*)(C + (size_t)r0 * N + c)       = make_float2(acc[mf][nf][0], acc[mf][nf][1]);
            *(float2*)(C + (size_t)(r0 + 8) * N + c) = make_float2(acc[mf][nf][2], acc[mf][nf][3]);
        }
    }
}

// =====================================================================
// Flash attention (causal, GQA). Br=64 (4 warps x 16 rows), Bc=64.
// Q, K, V, P all single fp16. Double-buffered KV, one barrier per tile.
// 2 CTAs per SM (smem 87040 x 2 <= 228KB).
// =====================================================================
constexpr int AS       = 136;
constexpr int Q_OFF    = 0;
constexpr int KV_BASE  = 64 * AS;
constexpr int KV_STAGE = 2 * 64 * AS;
constexpr int ATTN_SMEM_BYTES = (64 * AS + 2 * KV_STAGE) * 2;   // 87040

__global__ __launch_bounds__(128, 2) void attn_kernel(
    const __half* __restrict__ Qh,
    const __half* __restrict__ Kh, const __half* __restrict__ Vh,
    __half* __restrict__ O)
{
    extern __shared__ __half sm[];
    const int tid  = threadIdx.x;
    const int lane = tid & 31;
    const int wid  = tid >> 5;
    const int bh   = blockIdx.y;
    const int b    = bh >> 4, h = bh & 15;
    const int qi   = (int)gridDim.x - 1 - (int)blockIdx.x;
    const int qbase = qi * 64;
    const int kvi  = b * NKV + (h >> 2);

    const __half* q_g = Qh + ((size_t)bh * T_ + qbase) * HD;
    const __half* k_g = Kh + (size_t)kvi * T_ * HD;
    const __half* v_g = Vh + (size_t)kvi * T_ * HD;

    // Q tile: 64 rows x 128 halves = 1024 x 16B chunks
#pragma unroll
    for (int i = 0; i < 8; i++) {
        int c = i * 128 + tid;
        int row = c >> 4, ch = c & 15;
        cpasync16(smem_u32(sm + Q_OFF + row * AS + ch * 8), q_g + row * HD + ch * 8);
    }

    auto loadKV = [&](int j, int st) {
        size_t gb = (size_t)j * 64 * HD;
        const int koff = KV_BASE + st * KV_STAGE;
        const int voff = koff + 64 * AS;
#pragma unroll
        for (int i = 0; i < 8; i++) {
            int c = i * 128 + tid;
            int which = c >> 9, cc = c & 511;
            int row = cc >> 3, ch = cc & 7;
            const __half* src = (which ? v_g : k_g) + gb + row * HD + ch * 16;
            int off = (which ? voff : koff) + row * AS + ch * 16;
            cpasync16(smem_u32(sm + off), src);
            cpasync16(smem_u32(sm + off + 8), src + 8);
        }
    };
    loadKV(0, 0);
    cpcommit();

    float m0 = -1e30f, m1 = -1e30f, l0 = 0.f, l1 = 0.f;
    float o[16][4];
#pragma unroll
    for (int i = 0; i < 16; i++)
#pragma unroll
        for (int j = 0; j < 4; j++) o[i][j] = 0.f;

    const int nj = qi + 1;
    const int rowbase = qbase + wid * 16;

    for (int j = 0; j < nj; j++) {
        const int s = j & 1;
        cpwait<0>();
        __syncthreads();
        if (j + 1 < nj) { loadKV(j + 1, s ^ 1); cpcommit(); }

        const int kb = KV_BASE + s * KV_STAGE;
        const int vb = kb + 64 * AS;

        // ---- S = Q K^T (exp2 domain), single-plane Q ----
        float sacc[8][4];
#pragma unroll
        for (int i = 0; i < 8; i++)
#pragma unroll
            for (int jj = 0; jj < 4; jj++) sacc[i][jj] = 0.f;

#pragma unroll
        for (int ks = 0; ks < 8; ks++) {
            uint32_t qa[4];
            {
                int row = wid * 16 + (lane & 15);
                int col = ks * 16 + ((lane >> 4) << 3);
                ldsm4(qa, sm + Q_OFF + row * AS + col);
            }
#pragma unroll
            for (int nf2 = 0; nf2 < 4; nf2++) {
                uint32_t kh4[4];
                int krow = nf2 * 16 + (lane & 15);
                int kcol = ks * 16 + ((lane >> 4) << 3);
                ldsm4(kh4, sm + kb + krow * AS + kcol);
                mma_f16(sacc[2 * nf2],     qa, kh4[0], kh4[2]);
                mma_f16(sacc[2 * nf2 + 1], qa, kh4[1], kh4[3]);
            }
        }

        // ---- causal mask (diagonal tile only) ----
        const int kvb = j * 64;
        if (kvb + 63 > rowbase) {
            int r0 = rowbase + (lane >> 2), r1 = r0 + 8;
#pragma unroll
            for (int nf = 0; nf < 8; nf++) {
                int c0 = kvb + nf * 8 + (lane & 3) * 2;
                if (c0 > r0)     sacc[nf][0] = -1e30f;
                if (c0 + 1 > r0) sacc[nf][1] = -1e30f;
                if (c0 > r1)     sacc[nf][2] = -1e30f;
                if (c0 + 1 > r1) sacc[nf][3] = -1e30f;
            }
        }

        // ---- online softmax (base 2) ----
        float rm0 = -1e30f, rm1 = -1e30f;
#pragma unroll
        for (int nf = 0; nf < 8; nf++) {
            rm0 = fmaxf(rm0, fmaxf(sacc[nf][0], sacc[nf][1]));
            rm1 = fmaxf(rm1, fmaxf(sacc[nf][2], sacc[nf][3]));
        }
        rm0 = fmaxf(rm0, __shfl_xor_sync(0xffffffffu, rm0, 1));
        rm0 = fmaxf(rm0, __shfl_xor_sync(0xffffffffu, rm0, 2));
        rm1 = fmaxf(rm1, __shfl_xor_sync(0xffffffffu, rm1, 1));
        rm1 = fmaxf(rm1, __shfl_xor_sync(0xffffffffu, rm1, 2));
        float mn0 = fmaxf(m0, rm0), mn1 = fmaxf(m1, rm1);
        float corr0 = exp2f(m0 - mn0), corr1 = exp2f(m1 - mn1);
        m0 = mn0; m1 = mn1;

        float rs0 = 0.f, rs1 = 0.f;
#pragma unroll
        for (int nf = 0; nf < 8; nf++) {
            float p0 = exp2f(sacc[nf][0] - mn0);
            float p1 = exp2f(sacc[nf][1] - mn0);
            float p2 = exp2f(sacc[nf][2] - mn1);
            float p3 = exp2f(sacc[nf][3] - mn1);
            sacc[nf][0] = p0; sacc[nf][1] = p1; sacc[nf][2] = p2; sacc[nf][3] = p3;
            rs0 += p0 + p1; rs1 += p2 + p3;
        }
        l0 = l0 * corr0 + rs0;
        l1 = l1 * corr1 + rs1;
        if (__any_sync(0xffffffffu, (corr0 != 1.f) || (corr1 != 1.f))) {
#pragma unroll
            for (int df = 0; df < 16; df++) {
                o[df][0] *= corr0; o[df][1] *= corr0;
                o[df][2] *= corr1; o[df][3] *= corr1;
            }
        }

        // ---- pack P into single-fp16 A-fragments ----
        uint32_t ph[4][4];
#pragma unroll
        for (int kk = 0; kk < 4; kk++) {
            const float* A0 = sacc[2 * kk];
            const float* A1 = sacc[2 * kk + 1];
            ph[kk][0] = cvt2h(A0[0], A0[1]);
            ph[kk][1] = cvt2h(A0[2], A0[3]);
            ph[kk][2] = cvt2h(A1[0], A1[1]);
            ph[kk][3] = cvt2h(A1[2], A1[3]);
        }

        // ---- O += P V ----
#pragma unroll
        for (int kk = 0; kk < 4; kk++) {
#pragma unroll
            for (int nf2 = 0; nf2 < 8; nf2++) {
                uint32_t vh4[4];
                int vrow = kk * 16 + (lane & 15);
                int vcol = nf2 * 16 + ((lane >> 4) << 3);
                ldsm4t(vh4, sm + vb + vrow * AS + vcol);
                mma_f16(o[2 * nf2],     ph[kk], vh4[0], vh4[1]);
                mma_f16(o[2 * nf2 + 1], ph[kk], vh4[2], vh4[3]);
            }
        }
    }

    // ---- finalize: write single-fp16 context ----
    l0 += __shfl_xor_sync(0xffffffffu, l0, 1);
    l0 += __shfl_xor_sync(0xffffffffu, l0, 2);
    l1 += __shfl_xor_sync(0xffffffffu, l1, 1);
    l1 += __shfl_xor_sync(0xffffffffu, l1, 2);
    float inv0 = 1.f / l0, inv1 = 1.f / l1;

    int r0 = rowbase + (lane >> 2);
    size_t base0 = ((size_t)b * T_ + r0) * HID + h * HD + (lane & 3) * 2;
    size_t base1 = base0 + (size_t)8 * HID;
#pragma unroll
    for (int df = 0; df < 16; df++) {
        *(uint32_t*)(O + base0 + df * 8) = cvt2h(o[df][0] * inv0, o[df][1] * inv0);
        *(uint32_t*)(O + base1 + df * 8) = cvt2h(o[df][2] * inv1, o[df][3] * inv1);
    }
}

// =====================================================================
// host launcher
// =====================================================================
extern "C" void kernel_launch(void* const* d_in, const int* in_sizes, int n_in,
                              void* d_out, int out_size)
{
    const float* x    = (const float*)d_in[0];
    const float* cosb = (const float*)d_in[1];
    const float* sinb = (const float*)d_in[2];
    const float* wq   = (const float*)d_in[3];
    const float* wk   = (const float*)d_in[4];
    const float* wv   = (const float*)d_in[5];
    const float* wo   = (const float*)d_in[6];

    __half *Octx, *Qh, *Kh, *Vh, *xh, *wqh, *wkh, *wvh, *woh;
    cudaGetSymbolAddress((void**)&Octx, g_Octx);
    cudaGetSymbolAddress((void**)&Qh, g_Qh);
    cudaGetSymbolAddress((void**)&Kh, g_Kh);
    cudaGetSymbolAddress((void**)&Vh, g_Vh);
    cudaGetSymbolAddress((void**)&xh, g_xh);
    cudaGetSymbolAddress((void**)&wqh, g_wqh);
    cudaGetSymbolAddress((void**)&wkh, g_wkh);
    cudaGetSymbolAddress((void**)&wvh, g_wvh);
    cudaGetSymbolAddress((void**)&woh, g_woh);

    cudaFuncSetAttribute(attn_kernel, cudaFuncAttributeMaxDynamicSharedMemorySize,
                         ATTN_SMEM_BYTES);
    cudaFuncSetAttribute(gemm_ctx, cudaFuncAttributeMaxDynamicSharedMemorySize,
                         CTX_SMEM_BYTES);
    cudaFuncSetAttribute(gemm_qkv_rope, cudaFuncAttributeMaxDynamicSharedMemorySize,
                         QKV_SMEM_BYTES);

    const int M = B_ * T_;  // 4096
    float qsc = (1.0f / sqrtf((float)HD)) * 1.4426950408889634f;

    // 0: one-time fp32 -> fp16 conversion of x and all weights
    cvt_inputs<<<CVT_TOTAL / 256, 256>>>(
        (const float4*)x, (const float4*)wq, (const float4*)wk,
        (const float4*)wv, (const float4*)wo, xh, wqh, wkh, wvh, woh);
    // 1: persistent fused QKV projection + rope (pure fp16 cp.async)
    gemm_qkv_rope<<<QKV_GRID, 512, QKV_SMEM_BYTES>>>(
        xh, wqh, wkh, wvh, cosb, sinb, Qh, Kh, Vh, qsc);
    // 2: attention (single-fp16 Q/K/V/P, fp16 context out)
    attn_kernel<<<dim3(T_ / 64, B_ * NH), 128, ATTN_SMEM_BYTES>>>(
        Qh, Kh, Vh, Octx);
    // 3: output projection (all-fp16 cp.async, fp32 out)
    gemm_ctx<<<dim3(HID / 256, M / 128), 512, CTX_SMEM_BYTES>>>(
        Octx, woh, (float*)d_out, M, HID, HID);
}

// round 17
// speedup vs baseline: 2.4627x; 1.0462x over previous
#include <cuda_runtime.h>
#include <cuda_fp16.h>
#include <cstdint>
#include <cstddef>
#include <math.h>

// Problem constants
constexpr int B_  = 2;
constexpr int T_  = 2048;
constexpr int HID = 2048;
constexpr int NH  = 16;
constexpr int NKV = 4;
constexpr int HD  = 128;

// ---------------- scratch (static device arrays; no allocation) ----------------
__device__ __half  g_Octx[(size_t)B_ * T_ * NH * HD];
__device__ __half  g_Qh[(size_t)B_ * NH  * T_ * HD];
__device__ __half  g_Kh[(size_t)B_ * NKV * T_ * HD];
__device__ __half  g_Vh[(size_t)B_ * NKV * T_ * HD];
// fp16 copies of inputs (one-time convert per launch)
__device__ __half  g_xh [(size_t)B_ * T_ * HID];
__device__ __half  g_wqh[(size_t)HID * NH * HD];
__device__ __half  g_wkh[(size_t)HID * NKV * HD];
__device__ __half  g_wvh[(size_t)HID * NKV * HD];
__device__ __half  g_woh[(size_t)NH * HD * HID];
// persistent-kernel work-stealing counters (self-resetting each launch)
__device__ int g_tile_ctr = 0;
__device__ int g_done_ctr = 0;

// ---------------- PTX helpers ----------------
__device__ __forceinline__ uint32_t smem_u32(const void* p) {
    return (uint32_t)__cvta_generic_to_shared(p);
}
__device__ __forceinline__ void ldsm4(uint32_t r[4], const void* p) {
    uint32_t a = smem_u32(p);
    asm volatile("ldmatrix.sync.aligned.m8n8.x4.shared.b16 {%0,%1,%2,%3}, [%4];"
                 : "=r"(r[0]), "=r"(r[1]), "=r"(r[2]), "=r"(r[3]) : "r"(a));
}
__device__ __forceinline__ void ldsm4t(uint32_t r[4], const void* p) {
    uint32_t a = smem_u32(p);
    asm volatile("ldmatrix.sync.aligned.m8n8.x4.trans.shared.b16 {%0,%1,%2,%3}, [%4];"
                 : "=r"(r[0]), "=r"(r[1]), "=r"(r[2]), "=r"(r[3]) : "r"(a));
}
__device__ __forceinline__ void mma_f16(float c[4], const uint32_t a[4], uint32_t b0, uint32_t b1) {
    asm volatile("mma.sync.aligned.m16n8k16.row.col.f32.f16.f16.f32 "
                 "{%0,%1,%2,%3}, {%4,%5,%6,%7}, {%8,%9}, {%0,%1,%2,%3};"
                 : "+f"(c[0]), "+f"(c[1]), "+f"(c[2]), "+f"(c[3])
                 : "r"(a[0]), "r"(a[1]), "r"(a[2]), "r"(a[3]), "r"(b0), "r"(b1));
}
__device__ __forceinline__ void cpasync16(uint32_t saddr, const void* g) {
    asm volatile("cp.async.cg.shared.global [%0], [%1], 16;" :: "r"(saddr), "l"(g));
}
__device__ __forceinline__ void cpcommit() { asm volatile("cp.async.commit_group;"); }
template <int N> __device__ __forceinline__ void cpwait() {
    asm volatile("cp.async.wait_group %0;" :: "n"(N));
}
__device__ __forceinline__ uint32_t cvt2h(float a, float b) {
    __half2 h = __floats2half2_rn(a, b);
    return *reinterpret_cast<uint32_t*>(&h);
}
__device__ __forceinline__ void cvt_store4h(float4 v, __half* dst) {
    *reinterpret_cast<uint2*>(dst) = make_uint2(cvt2h(v.x, v.y), cvt2h(v.z, v.w));
}

// =====================================================================
// prep: one-time fp32 -> fp16 conversion of x and all weights
// =====================================================================
constexpr int NX4  = (B_ * T_ * HID) / 4;      // 2097152
constexpr int NW4  = (HID * NH * HD) / 4;      // 1048576 (wq, wo)
constexpr int NKW4 = (HID * NKV * HD) / 4;     // 262144  (wk, wv)
constexpr int CVT_TOTAL = NX4 + 2 * NW4 + 2 * NKW4;   // 4718592

__global__ void cvt_inputs(const float4* __restrict__ x,
                           const float4* __restrict__ wq, const float4* __restrict__ wk,
                           const float4* __restrict__ wv, const float4* __restrict__ wo,
                           __half* __restrict__ xh,
                           __half* __restrict__ wqh, __half* __restrict__ wkh,
                           __half* __restrict__ wvh, __half* __restrict__ woh)
{
    int i = blockIdx.x * 256 + threadIdx.x;
    const float4* s; __half* d; int o;
    if (i < NX4)                          { s = x;  d = xh;  o = i; }
    else if (i < NX4 + NW4)               { s = wq; d = wqh; o = i - NX4; }
    else if (i < NX4 + NW4 + NKW4)        { s = wk; d = wkh; o = i - NX4 - NW4; }
    else if (i < NX4 + NW4 + 2 * NKW4)    { s = wv; d = wvh; o = i - NX4 - NW4 - NKW4; }
    else                                  { s = wo; d = woh; o = i - NX4 - NW4 - 2 * NKW4; }
    cvt_store4h(s[o], d + (size_t)o * 4);
}

// =====================================================================
// GEMM tile constants: CTA 128x256 with K-chunk 64, 512 thr (16 warps),
// warp tile 32x64. Pure fp16 cp.async pipeline, one barrier/k-chunk.
// KC=64 doubles compute per pipeline step (covers load latency) and
// halves barrier count vs KC=32.
// =====================================================================
constexpr int SA_ST = 72;    // sA row stride (64+8 halves)
constexpr int SB_ST = 264;   // sB row stride (256+8 halves)
constexpr int SA_SZ = 128 * SA_ST;          // 9216
constexpr int SB_SZ = 64 * SB_ST;           // 16896
constexpr int ST_SZ = SA_SZ + SB_SZ;        // 26112 halves/stage
constexpr int GEMM_SMEM_BYTES = 2 * ST_SZ * 2;    // 104448 B (covers 67.6KB rope buf)

constexpr int QKV_TILES = 384;              // 256 Q + 64 K + 64 V
constexpr int QKV_GRID  = 152;

// =====================================================================
// PERSISTENT fused QKV projection + RoPE + scale. All-fp16 operands
// via cp.async; Q/K/V outputs single fp16.
// =====================================================================
__global__ __launch_bounds__(512, 1) void gemm_qkv_rope(
    const __half* __restrict__ A,
    const __half* __restrict__ wq, const __half* __restrict__ wk, const __half* __restrict__ wv,
    const float* __restrict__ cosb, const float* __restrict__ sinb,
    __half* __restrict__ Qh, __half* __restrict__ Kh, __half* __restrict__ Vh,
    float qsc)
{
    extern __shared__ __half gs[];
    __shared__ int s_tile;

    const int tid  = threadIdx.x;
    const int lane = tid & 31;
    const int wid  = tid >> 5;
    const int wm   = (wid >> 2) * 32;
    const int wn   = (wid & 3) * 64;
    const int K = HID;

    for (;;) {
        if (tid == 0) s_tile = atomicAdd(&g_tile_ctr, 1);
        __syncthreads();
        const int tile = s_tile;
        if (tile >= QKV_TILES) break;

        int which, bm, bn;
        if (tile < 256)      { which = 0; bm = tile >> 3;         bn = tile & 7; }
        else if (tile < 320) { which = 1; bm = (tile - 256) >> 1; bn = (tile - 256) & 1; }
        else                 { which = 2; bm = (tile - 320) >> 1; bn = (tile - 320) & 1; }
        const __half* Bm = (which == 0) ? wq : (which == 1) ? wk : wv;
        const int N = (which == 0) ? (NH * HD) : (NKV * HD);

        const __half* Ab = A + (size_t)bm * 128 * K;
        const __half* Bb = Bm + (size_t)bn * 256;

        float acc[2][8][4] = {};

        auto loadAB = [&](int k0, int s) {
            __half* sA0 = gs + s * ST_SZ;
            __half* sB0 = sA0 + SA_SZ;
#pragma unroll
            for (int i = 0; i < 2; i++) {   // A: 128 rows x 64 halves = 1024 chunks
                int idx = i * 512 + tid;
                int r = idx >> 3, ch = (idx & 7) * 8;
                cpasync16(smem_u32(sA0 + r * SA_ST + ch), Ab + (size_t)r * K + k0 + ch);
            }
#pragma unroll
            for (int i = 0; i < 4; i++) {   // B: 64 rows x 256 halves = 2048 chunks
                int idx = i * 512 + tid;
                int r = idx >> 5, ch = (idx & 31) * 8;
                cpasync16(smem_u32(sB0 + r * SB_ST + ch), Bb + (size_t)(k0 + r) * N + ch);
            }
            cpcommit();
        };

        loadAB(0, 0);

        const int nk = K / 64;   // 32
        for (int kt = 0; kt < nk; kt++) {
            const int s = kt & 1;
            cpwait<0>();
            __syncthreads();
            if (kt + 1 < nk) loadAB((kt + 1) * 64, s ^ 1);

            const __half* sA0 = gs + s * ST_SZ;
            const __half* sB0 = sA0 + SA_SZ;

#pragma unroll
            for (int ks = 0; ks < 4; ks++) {
                const int colA = ks * 16 + ((lane >> 4) << 3);
                uint32_t af0[2][4];
#pragma unroll
                for (int mf = 0; mf < 2; mf++) {
                    int row = wm + mf * 16 + (lane & 15);
                    ldsm4(af0[mf], sA0 + row * SA_ST + colA);
                }
                const int rowB = ks * 16 + (lane & 15);
#pragma unroll
                for (int nf2 = 0; nf2 < 4; nf2++) {
                    const int colB = wn + nf2 * 16 + ((lane >> 4) << 3);
                    uint32_t bh[4];
                    ldsm4t(bh, sB0 + rowB * SB_ST + colB);
#pragma unroll
                    for (int mf = 0; mf < 2; mf++)
#pragma unroll
                        for (int sub = 0; sub < 2; sub++)
                            mma_f16(acc[mf][nf2 * 2 + sub], af0[mf], bh[sub * 2], bh[sub * 2 + 1]);
                }
            }
        }
        __syncthreads();   // all warps done reading stages before epilogue reuses gs

        // ---- fused rope + convert epilogue (smem exchange, two 64-row passes) ----
        {
            float* sf = reinterpret_cast<float*>(gs);
            const int H = (which == 0) ? NH : NKV;
            const float scale = (which == 0) ? qsc : 1.0f;
            const int do_rope = (which != 2);
            __half* dst = (which == 0) ? Qh : (which == 1) ? Kh : Vh;

#pragma unroll
            for (int mf = 0; mf < 2; mf++) {
                int rl0 = (wm >> 5) * 16 + (lane >> 2);
#pragma unroll
                for (int nf = 0; nf < 8; nf++) {
                    int col = wn + nf * 8 + (lane & 3) * 2;
                    *(float2*)(sf + rl0 * 264 + col)       = make_float2(acc[mf][nf][0], acc[mf][nf][1]);
                    *(float2*)(sf + (rl0 + 8) * 264 + col) = make_float2(acc[mf][nf][2], acc[mf][nf][3]);
                }
                __syncthreads();
#pragma unroll
                for (int k = 0; k < 16; k++) {
                    int e2 = k * 512 + tid;
                    int rl = e2 >> 7;
                    int c2 = (e2 & 127) * 2;
                    int r  = bm * 128 + (rl >> 4) * 32 + mf * 16 + (rl & 15);
                    int t  = r & (T_ - 1);
                    int b  = r >> 11;
                    int gc = bn * 256 + c2;
                    int h  = gc >> 7;
                    int d  = gc & 127;
                    float2 v = *(float2*)(sf + rl * 264 + c2);
                    float o0, o1;
                    if (do_rope) {
                        int dd = d & 63;
                        float2 cs = *(const float2*)(cosb + t * 64 + dd);
                        float2 sn = *(const float2*)(sinb + t * 64 + dd);
                        float2 w  = *(float2*)(sf + rl * 264 + (c2 ^ 64));
                        if (d < 64) { o0 = v.x * cs.x - w.x * sn.x; o1 = v.y * cs.y - w.y * sn.y; }
                        else        { o0 = v.x * cs.x + w.x * sn.x; o1 = v.y * cs.y + w.y * sn.y; }
                    } else { o0 = v.x; o1 = v.y; }
                    o0 *= scale; o1 *= scale;
                    size_t di = (((size_t)(b * H + h)) * T_ + t) * HD + d;
                    *(uint32_t*)(dst + di) = cvt2h(o0, o1);
                }
                __syncthreads();
            }
        }
    }

    if (tid == 0) {
        int d = atomicAdd(&g_done_ctr, 1);
        if (d == (int)gridDim.x - 1) {
            g_tile_ctr = 0;
            g_done_ctr = 0;
            __threadfence();
        }
    }
}

// =====================================================================
// Output-projection GEMM: fp16 context A, pre-converted fp16 wo B,
// pure cp.async pipeline (KC=64), fp32 out.
// =====================================================================
__global__ __launch_bounds__(512, 1) void gemm_ctx(
    const __half* __restrict__ A, const __half* __restrict__ Bm, float* __restrict__ C,
    int M, int N, int K)
{
    extern __shared__ __half gs[];

    const int tid  = threadIdx.x;
    const int lane = tid & 31;
    const int wid  = tid >> 5;
    const int bm   = blockIdx.y, bn = blockIdx.x;
    const int wm   = (wid >> 2) * 32;
    const int wn   = (wid & 3) * 64;

    const __half* Ab = A + (size_t)bm * 128 * K;
    const __half* Bb = Bm + (size_t)bn * 256;

    float acc[2][8][4] = {};

    auto loadAB = [&](int k0, int s) {
        __half* sA0 = gs + s * ST_SZ;
        __half* sB0 = sA0 + SA_SZ;
#pragma unroll
        for (int i = 0; i < 2; i++) {
            int idx = i * 512 + tid;
            int r = idx >> 3, ch = (idx & 7) * 8;
            cpasync16(smem_u32(sA0 + r * SA_ST + ch), Ab + (size_t)r * K + k0 + ch);
        }
#pragma unroll
        for (int i = 0; i < 4; i++) {
            int idx = i * 512 + tid;
            int r = idx >> 5, ch = (idx & 31) * 8;
            cpasync16(smem_u32(sB0 + r * SB_ST + ch), Bb + (size_t)(k0 + r) * N + ch);
        }
        cpcommit();
    };

    loadAB(0, 0);

    const int nk = K / 64;
    for (int kt = 0; kt < nk; kt++) {
        const int s = kt & 1;
        cpwait<0>();
        __syncthreads();
        if (kt + 1 < nk) loadAB((kt + 1) * 64, s ^ 1);

        const __half* sA0 = gs + s * ST_SZ;
        const __half* sB0 = sA0 + SA_SZ;

#pragma unroll
        for (int ks = 0; ks < 4; ks++) {
            const int colA = ks * 16 + ((lane >> 4) << 3);
            uint32_t af0[2][4];
#pragma unroll
            for (int mf = 0; mf < 2; mf++) {
                int row = wm + mf * 16 + (lane & 15);
                ldsm4(af0[mf], sA0 + row * SA_ST + colA);
            }
            const int rowB = ks * 16 + (lane & 15);
#pragma unroll
            for (int nf2 = 0; nf2 < 4; nf2++) {
                const int colB = wn + nf2 * 16 + ((lane >> 4) << 3);
                uint32_t bh[4];
                ldsm4t(bh, sB0 + rowB * SB_ST + colB);
#pragma unroll
                for (int mf = 0; mf < 2; mf++)
#pragma unroll
                    for (int sub = 0; sub < 2; sub++)
                        mma_f16(acc[mf][nf2 * 2 + sub], af0[mf], bh[sub * 2], bh[sub * 2 + 1]);
            }
        }
    }

#pragma unroll
    for (int mf = 0; mf < 2; mf++) {
        int r0 = bm * 128 + wm + mf * 16 + (lane >> 2);
#pragma unroll
        for (int nf = 0; nf < 8; nf++) {
            int c = bn * 256 + wn + nf * 8 + (lane & 3) * 2;
            *(float2*)(C + (size_t)r0 * N + c)       = make_float2(acc[mf][nf][0], acc[mf][nf][1]);
            *(float2*)(C + (size_t)(r0 + 8) * N + c) = make_float2(acc[mf][nf][2], acc[mf][nf][3]);
        }
    }
}

// =====================================================================
// Flash attention (causal, GQA). Br=64 (4 warps x 16 rows), Bc=64.
// Q, K, V, P all single fp16. Double-buffered KV, one barrier per tile.
// 2 CTAs per SM (smem 87040 x 2 <= 228KB).
// =====================================================================
constexpr int AS       = 136;
constexpr int Q_OFF    = 0;
constexpr int KV_BASE  = 64 * AS;
constexpr int KV_STAGE = 2 * 64 * AS;
constexpr int ATTN_SMEM_BYTES = (64 * AS + 2 * KV_STAGE) * 2;   // 87040

__global__ __launch_bounds__(128, 2) void attn_kernel(
    const __half* __restrict__ Qh,
    const __half* __restrict__ Kh, const __half* __restrict__ Vh,
    __half* __restrict__ O)
{
    extern __shared__ __half sm[];
    const int tid  = threadIdx.x;
    const int lane = tid & 31;
    const int wid  = tid >> 5;
    const int bh   = blockIdx.y;
    const int b    = bh >> 4, h = bh & 15;
    const int qi   = (int)gridDim.x - 1 - (int)blockIdx.x;
    const int qbase = qi * 64;
    const int kvi  = b * NKV + (h >> 2);

    const __half* q_g = Qh + ((size_t)bh * T_ + qbase) * HD;
    const __half* k_g = Kh + (size_t)kvi * T_ * HD;
    const __half* v_g = Vh + (size_t)kvi * T_ * HD;

#pragma unroll
    for (int i = 0; i < 8; i++) {
        int c = i * 128 + tid;
        int row = c >> 4, ch = c & 15;
        cpasync16(smem_u32(sm + Q_OFF + row * AS + ch * 8), q_g + row * HD + ch * 8);
    }

    auto loadKV = [&](int j, int st) {
        size_t gb = (size_t)j * 64 * HD;
        const int koff = KV_BASE + st * KV_STAGE;
        const int voff = koff + 64 * AS;
#pragma unroll
        for (int i = 0; i < 8; i++) {
            int c = i * 128 + tid;
            int which = c >> 9, cc = c & 511;
            int row = cc >> 3, ch = cc & 7;
            const __half* src = (which ? v_g : k_g) + gb + row * HD + ch * 16;
            int off = (which ? voff : koff) + row * AS + ch * 16;
            cpasync16(smem_u32(sm + off), src);
            cpasync16(smem_u32(sm + off + 8), src + 8);
        }
    };
    loadKV(0, 0);
    cpcommit();

    float m0 = -1e30f, m1 = -1e30f, l0 = 0.f, l1 = 0.f;
    float o[16][4];
#pragma unroll
    for (int i = 0; i < 16; i++)
#pragma unroll
        for (int j = 0; j < 4; j++) o[i][j] = 0.f;

    const int nj = qi + 1;
    const int rowbase = qbase + wid * 16;

    for (int j = 0; j < nj; j++) {
        const int s = j & 1;
        cpwait<0>();
        __syncthreads();
        if (j + 1 < nj) { loadKV(j + 1, s ^ 1); cpcommit(); }

        const int kb = KV_BASE + s * KV_STAGE;
        const int vb = kb + 64 * AS;

        float sacc[8][4];
#pragma unroll
        for (int i = 0; i < 8; i++)
#pragma unroll
            for (int jj = 0; jj < 4; jj++) sacc[i][jj] = 0.f;

#pragma unroll
        for (int ks = 0; ks < 8; ks++) {
            uint32_t qa[4];
            {
                int row = wid * 16 + (lane & 15);
                int col = ks * 16 + ((lane >> 4) << 3);
                ldsm4(qa, sm + Q_OFF + row * AS + col);
            }
#pragma unroll
            for (int nf2 = 0; nf2 < 4; nf2++) {
                uint32_t kh4[4];
                int krow = nf2 * 16 + (lane & 15);
                int kcol = ks * 16 + ((lane >> 4) << 3);
                ldsm4(kh4, sm + kb + krow * AS + kcol);
                mma_f16(sacc[2 * nf2],     qa, kh4[0], kh4[2]);
                mma_f16(sacc[2 * nf2 + 1], qa, kh4[1], kh4[3]);
            }
        }

        const int kvb = j * 64;
        if (kvb + 63 > rowbase) {
            int r0 = rowbase + (lane >> 2), r1 = r0 + 8;
#pragma unroll
            for (int nf = 0; nf < 8; nf++) {
                int c0 = kvb + nf * 8 + (lane & 3) * 2;
                if (c0 > r0)     sacc[nf][0] = -1e30f;
                if (c0 + 1 > r0) sacc[nf][1] = -1e30f;
                if (c0 > r1)     sacc[nf][2] = -1e30f;
                if (c0 + 1 > r1) sacc[nf][3] = -1e30f;
            }
        }

        float rm0 = -1e30f, rm1 = -1e30f;
#pragma unroll
        for (int nf = 0; nf < 8; nf++) {
            rm0 = fmaxf(rm0, fmaxf(sacc[nf][0], sacc[nf][1]));
            rm1 = fmaxf(rm1, fmaxf(sacc[nf][2], sacc[nf][3]));
        }
        rm0 = fmaxf(rm0, __shfl_xor_sync(0xffffffffu, rm0, 1));
        rm0 = fmaxf(rm0, __shfl_xor_sync(0xffffffffu, rm0, 2));
        rm1 = fmaxf(rm1, __shfl_xor_sync(0xffffffffu, rm1, 1));
        rm1 = fmaxf(rm1, __shfl_xor_sync(0xffffffffu, rm1, 2));
        float mn0 = fmaxf(m0, rm0), mn1 = fmaxf(m1, rm1);
        float corr0 = exp2f(m0 - mn0), corr1 = exp2f(m1 - mn1);
        m0 = mn0; m1 = mn1;

        float rs0 = 0.f, rs1 = 0.f;
#pragma unroll
        for (int nf = 0; nf < 8; nf++) {
            float p0 = exp2f(sacc[nf][0] - mn0);
            float p1 = exp2f(sacc[nf][1] - mn0);
            float p2 = exp2f(sacc[nf][2] - mn1);
            float p3 = exp2f(sacc[nf][3] - mn1);
            sacc[nf][0] = p0; sacc[nf][1] = p1; sacc[nf][2] = p2; sacc[nf][3] = p3;
            rs0 += p0 + p1; rs1 += p2 + p3;
        }
        l0 = l0 * corr0 + rs0;
        l1 = l1 * corr1 + rs1;
        if (__any_sync(0xffffffffu, (corr0 != 1.f) || (corr1 != 1.f))) {
#pragma unroll
            for (int df = 0; df < 16; df++) {
                o[df][0] *= corr0; o[df][1] *= corr0;
                o[df][2] *= corr1; o[df][3] *= corr1;
            }
        }

        uint32_t ph[4][4];
#pragma unroll
        for (int kk = 0; kk < 4; kk++) {
            const float* A0 = sacc[2 * kk];
            const float* A1 = sacc[2 * kk + 1];
            ph[kk][0] = cvt2h(A0[0], A0[1]);
            ph[kk][1] = cvt2h(A0[2], A0[3]);
            ph[kk][2] = cvt2h(A1[0], A1[1]);
            ph[kk][3] = cvt2h(A1[2], A1[3]);
        }

#pragma unroll
        for (int kk = 0; kk < 4; kk++) {
#pragma unroll
            for (int nf2 = 0; nf2 < 8; nf2++) {
                uint32_t vh4[4];
                int vrow = kk * 16 + (lane & 15);
                int vcol = nf2 * 16 + ((lane >> 4) << 3);
                ldsm4t(vh4, sm + vb + vrow * AS + vcol);
                mma_f16(o[2 * nf2],     ph[kk], vh4[0], vh4[1]);
                mma_f16(o[2 * nf2 + 1], ph[kk], vh4[2], vh4[3]);
            }
        }
    }

    // ---- finalize: write single-fp16 context ----
    l0 += __shfl_xor_sync(0xffffffffu, l0, 1);
    l0 += __shfl_xor_sync(0xffffffffu, l0, 2);
    l1 += __shfl_xor_sync(0xffffffffu, l1, 1);
    l1 += __shfl_xor_sync(0xffffffffu, l1, 2);
    float inv0 = 1.f / l0, inv1 = 1.f / l1;

    int r0 = rowbase + (lane >> 2);
    size_t base0 = ((size_t)b * T_ + r0) * HID + h * HD + (lane & 3) * 2;
    size_t base1 = base0 + (size_t)8 * HID;
#pragma unroll
    for (int df = 0; df < 16; df++) {
        *(uint32_t*)(O + base0 + df * 8) = cvt2h(o[df][0] * inv0, o[df][1] * inv0);
        *(uint32_t*)(O + base1 + df * 8) = cvt2h(o[df][2] * inv1, o[df][3] * inv1);
    }
}

// =====================================================================
// host launcher
// =====================================================================
extern "C" void kernel_launch(void* const* d_in, const int* in_sizes, int n_in,
                              void* d_out, int out_size)
{
    const float* x    = (const float*)d_in[0];
    const float* cosb = (const float*)d_in[1];
    const float* sinb = (const float*)d_in[2];
    const float* wq   = (const float*)d_in[3];
    const float* wk   = (const float*)d_in[4];
    const float* wv   = (const float*)d_in[5];
    const float* wo   = (const float*)d_in[6];

    __half *Octx, *Qh, *Kh, *Vh, *xh, *wqh, *wkh, *wvh, *woh;
    cudaGetSymbolAddress((void**)&Octx, g_Octx);
    cudaGetSymbolAddress((void**)&Qh, g_Qh);
    cudaGetSymbolAddress((void**)&Kh, g_Kh);
    cudaGetSymbolAddress((void**)&Vh, g_Vh);
    cudaGetSymbolAddress((void**)&xh, g_xh);
    cudaGetSymbolAddress((void**)&wqh, g_wqh);
    cudaGetSymbolAddress((void**)&wkh, g_wkh);
    cudaGetSymbolAddress((void**)&wvh, g_wvh);
    cudaGetSymbolAddress((void**)&woh, g_woh);

    cudaFuncSetAttribute(attn_kernel, cudaFuncAttributeMaxDynamicSharedMemorySize,
                         ATTN_SMEM_BYTES);
    cudaFuncSetAttribute(gemm_ctx, cudaFuncAttributeMaxDynamicSharedMemorySize,
                         GEMM_SMEM_BYTES);
    cudaFuncSetAttribute(gemm_qkv_rope, cudaFuncAttributeMaxDynamicSharedMemorySize,
                         GEMM_SMEM_BYTES);

    const int M = B_ * T_;  // 4096
    float qsc = (1.0f / sqrtf((float)HD)) * 1.4426950408889634f;

    // 0: one-time fp32 -> fp16 conversion of x and all weights
    cvt_inputs<<<CVT_TOTAL / 256, 256>>>(
        (const float4*)x, (const float4*)wq, (const float4*)wk,
        (const float4*)wv, (const float4*)wo, xh, wqh, wkh, wvh, woh);
    // 1: persistent fused QKV projection + rope (pure fp16 cp.async, KC=64)
    gemm_qkv_rope<<<QKV_GRID, 512, GEMM_SMEM_BYTES>>>(
        xh, wqh, wkh, wvh, cosb, sinb, Qh, Kh, Vh, qsc);
    // 2: attention (single-fp16 Q/K/V/P, fp16 context out)
    attn_kernel<<<dim3(T_ / 64, B_ * NH), 128, ATTN_SMEM_BYTES>>>(
        Qh, Kh, Vh, Octx);
    // 3: output projection (all-fp16 cp.async, KC=64, fp32 out)
    gemm_ctx<<<dim3(HID / 256, M / 128), 512, GEMM_SMEM_BYTES>>>(
        Octx, woh, (float*)d_out, M, HID, HID);
}